// round 7
// baseline (speedup 1.0000x reference)
#include <cuda_runtime.h>
#include <cuda_bf16.h>
#include <cstdint>

#define NB   8
#define NS   2048
#define NDIN 1024
#define ND   128

// fp32 Q, K, V scratch (for fixup + tail gather): 24 MB
__device__ float g_QKV[3][(size_t)NB * NS * ND];
// bf16 hi/lo pre-swizzled 64-row tiles: [QH,QL,KH,KL,VH,VL][b][tile][16KB] = 24 MB
__device__ uint4 g_bf[6][NB][32][1024];
// compacted global-token K/V tail tiles: [KH,KL,VH,VL][b][16KB]
__device__ uint4 g_tail[4][NB][1024];

struct GMask { unsigned int w[NS / 32]; };   // 2048-bit global-token mask
struct GIdx  { int idx[32]; };               // the 32 global token indices

// ===========================================================================
// Warp-MMA helpers (mma.sync / ldmatrix — baseline PTX, no sm_103a gating)
// ===========================================================================
__device__ __forceinline__ uint32_t smem_to_u32(const void* smem_ptr) {
    uint32_t addr;
    asm("{ .reg .u64 tmp; cvta.to.shared.u64 tmp, %1; cvt.u32.u64 %0, tmp; }"
        : "=r"(addr) : "l"(smem_ptr));
    return addr;
}

__device__ __forceinline__ uint32_t packbf(float lo, float hi) {
    uint32_t r;
    asm("cvt.rn.bf16x2.f32 %0, %1, %2;" : "=r"(r) : "f"(hi), "f"(lo));
    return r;
}

__device__ __forceinline__ void split2(float x, float& hf, float& lf) {
    __nv_bfloat16 h = __float2bfloat16_rn(x);
    hf = __bfloat162float(h);
    lf = x - hf;
}

#define LDSM_X4(r, addr) \
    asm volatile("ldmatrix.sync.aligned.m8n8.x4.shared.b16 {%0,%1,%2,%3}, [%4];" \
        : "=r"((r)[0]), "=r"((r)[1]), "=r"((r)[2]), "=r"((r)[3]) : "r"(addr))

#define LDSM_X4_T(r, addr) \
    asm volatile("ldmatrix.sync.aligned.m8n8.x4.trans.shared.b16 {%0,%1,%2,%3}, [%4];" \
        : "=r"((r)[0]), "=r"((r)[1]), "=r"((r)[2]), "=r"((r)[3]) : "r"(addr))

#define MMA16816(d, a, b0, b1) \
    asm("mma.sync.aligned.m16n8k16.row.col.f32.bf16.bf16.f32 " \
        "{%0,%1,%2,%3}, {%4,%5,%6,%7}, {%8,%9}, {%0,%1,%2,%3};" \
        : "+f"((d)[0]), "+f"((d)[1]), "+f"((d)[2]), "+f"((d)[3]) \
        : "r"((a)[0]), "r"((a)[1]), "r"((a)[2]), "r"((a)[3]), "r"(b0), "r"(b1))

// Swizzled address, 256-byte row stride (128 bf16 per row)
__device__ __forceinline__ uint32_t swaddr(uint32_t base, int row, int chunk) {
    return base + row * 256 + ((chunk ^ (row & 7)) << 4);
}
// Swizzled address, 128-byte row stride (proj tiles: 64 bf16 per row)
__device__ __forceinline__ uint32_t swaddr2(uint32_t base, int row, int chunk) {
    return base + row * 128 + ((chunk ^ (row & 7)) << 4);
}

__device__ __forceinline__ bool gbit(const GMask& gm, int i) {
    return (gm.w[i >> 5] >> (i & 31)) & 1u;
}

__device__ __forceinline__ void split_pack8(float4 v0, float4 v1, uint4& H, uint4& L) {
    float xs[8] = {v0.x, v0.y, v0.z, v0.w, v1.x, v1.y, v1.z, v1.w};
    float hf[8], lf[8];
    #pragma unroll
    for (int e = 0; e < 8; e++) split2(xs[e], hf[e], lf[e]);
    H.x = packbf(hf[0], hf[1]); H.y = packbf(hf[2], hf[3]);
    H.z = packbf(hf[4], hf[5]); H.w = packbf(hf[6], hf[7]);
    L.x = packbf(lf[0], lf[1]); L.y = packbf(lf[2], lf[3]);
    L.z = packbf(lf[4], lf[5]); L.w = packbf(lf[6], lf[7]);
}

__device__ __forceinline__ void store_chunk(char* smemc, uint32_t offH, uint32_t offL,
                                            float4 v0, float4 v1) {
    uint4 H, L;
    split_pack8(v0, v1, H, L);
    *(uint4*)(smemc + offH) = H;
    *(uint4*)(smemc + offL) = L;
}

// ===========================================================================
// Projection GEMM via mma.sync bf16 hi/lo split.
// Also emits pre-split, pre-swizzled bf16 hi/lo 64-row tiles to g_bf.
// ===========================================================================
#define PROJ_SMEM 65536

__global__ __launch_bounds__(256)
void proj_mma_kernel(const float* __restrict__ xq, const float* __restrict__ xk, const float* __restrict__ xv,
                     const float* __restrict__ Wq, const float* __restrict__ bq,
                     const float* __restrict__ Wk, const float* __restrict__ bk,
                     const float* __restrict__ Wv, const float* __restrict__ bv)
{
    extern __shared__ char psm[];
    const uint32_t sb  = smem_to_u32(psm);
    const uint32_t sXH = sb;
    const uint32_t sXL = sb + 16384;
    const uint32_t sWH = sb + 32768;
    const uint32_t sWL = sb + 49152;

    const int proj = blockIdx.y;
    const float* X    = (proj == 0) ? xq : (proj == 1) ? xk : xv;
    const float* W    = (proj == 0) ? Wq : (proj == 1) ? Wk : Wv;
    const float* bias = (proj == 0) ? bq : (proj == 1) ? bk : bv;
    float* out = g_QKV[proj];

    const int tid  = threadIdx.x;
    const int w    = tid >> 5;
    const int lane = tid & 31;
    const int g    = lane >> 2;
    const int tg   = lane & 3;
    const int g4   = lane >> 3;
    const int lr   = lane & 7;
    const int m0   = w * 16;
    const int mb   = blockIdx.x * 128;

    float acc[16][4];
    #pragma unroll
    for (int j = 0; j < 16; j++)
        #pragma unroll
        for (int e = 0; e < 4; e++) acc[j][e] = 0.0f;

    for (int kc = 0; kc < NDIN / 64; kc++) {
        const int k0 = kc * 64;
        if (kc) __syncthreads();

        #pragma unroll
        for (int i = 0; i < 4; i++) {
            int u = tid + i * 256;
            int row = u >> 3, ch = u & 7;
            uint32_t off = (uint32_t)(row * 128 + ((ch ^ (row & 7)) << 4));
            const float4* xsrc = (const float4*)(X + (size_t)(mb + row) * NDIN + k0 + ch * 8);
            store_chunk(psm, (sXH - sb) + off, (sXL - sb) + off, xsrc[0], xsrc[1]);
            const float4* wsrc = (const float4*)(W + (size_t)row * NDIN + k0 + ch * 8);
            store_chunk(psm, (sWH - sb) + off, (sWL - sb) + off, wsrc[0], wsrc[1]);
        }
        __syncthreads();

        #pragma unroll
        for (int ks = 0; ks < 4; ks++) {
            uint32_t ah[4], al[4];
            const int arow = m0 + ((g4 & 1) << 3) + lr;
            const int ach  = 2 * ks + (g4 >> 1);
            LDSM_X4(ah, swaddr2(sXH, arow, ach));
            LDSM_X4(al, swaddr2(sXL, arow, ach));
            #pragma unroll
            for (int jp = 0; jp < 8; jp++) {
                uint32_t bh[4], bl[4];
                const int brow = 8 * (2 * jp + (g4 >> 1)) + lr;
                const int bch  = 2 * ks + (g4 & 1);
                LDSM_X4(bh, swaddr2(sWH, brow, bch));
                LDSM_X4(bl, swaddr2(sWL, brow, bch));
                MMA16816(acc[2 * jp],     ah, bh[0], bh[1]);
                MMA16816(acc[2 * jp + 1], ah, bh[2], bh[3]);
                MMA16816(acc[2 * jp],     al, bh[0], bh[1]);
                MMA16816(acc[2 * jp + 1], al, bh[2], bh[3]);
                MMA16816(acc[2 * jp],     ah, bl[0], bl[1]);
                MMA16816(acc[2 * jp + 1], ah, bl[2], bl[3]);
            }
        }
    }

    // ---- epilogue: + bias -> fp32 g_QKV AND bf16 hi/lo swizzled tiles ----
    const int r0   = mb + m0 + g;
    const int r1   = r0 + 8;
    const int bb_  = mb / NS;
    const int s0   = r0 % NS;
    const int tile = s0 >> 6;
    const int rin0 = s0 & 63;
    const int rin1 = rin0 + 8;

    float* o0 = out + (size_t)r0 * ND;
    float* o1 = out + (size_t)r1 * ND;
    unsigned char* pH = (unsigned char*)g_bf[2 * proj][bb_][tile];
    unsigned char* pL = (unsigned char*)g_bf[2 * proj + 1][bb_][tile];

    #pragma unroll
    for (int j = 0; j < 16; j++) {
        const int c = 8 * j + 2 * tg;
        const float b0 = bias[c], b1 = bias[c + 1];
        const float x00 = acc[j][0] + b0, x01 = acc[j][1] + b1;
        const float x10 = acc[j][2] + b0, x11 = acc[j][3] + b1;
        *(float2*)(o0 + c) = make_float2(x00, x01);
        *(float2*)(o1 + c) = make_float2(x10, x11);

        float h, l, h2, l2;
        split2(x00, h, l); split2(x01, h2, l2);
        uint32_t off0 = (uint32_t)(rin0 * 256 + ((j ^ (rin0 & 7)) << 4) + tg * 4);
        *(uint32_t*)(pH + off0) = packbf(h, h2);
        *(uint32_t*)(pL + off0) = packbf(l, l2);

        split2(x10, h, l); split2(x11, h2, l2);
        uint32_t off1 = (uint32_t)(rin1 * 256 + ((j ^ (rin1 & 7)) << 4) + tg * 4);
        *(uint32_t*)(pH + off1) = packbf(h, h2);
        *(uint32_t*)(pL + off1) = packbf(l, l2);
    }
}

// ===========================================================================
// Gather the 32 global tokens' K/V rows into compact swizzled tail tiles.
// grid (NB), 256 threads.
// ===========================================================================
__global__ void gather_tail_kernel(GIdx gi)
{
    const int b = blockIdx.x, tid = threadIdx.x;
    for (int task = tid; task < 2048; task += 256) {
        const int arr = task >> 10;          // 0:K, 1:V
        const int rem = task & 1023;
        const int row = rem >> 4, ch = rem & 15;
        float4 v0 = make_float4(0, 0, 0, 0), v1 = v0;
        if (row < 32) {
            const float* src = g_QKV[arr + 1] + ((size_t)b * NS + gi.idx[row]) * ND + ch * 8;
            v0 = ((const float4*)src)[0];
            v1 = ((const float4*)src)[1];
        }
        uint4 H, L;
        split_pack8(v0, v1, H, L);
        const uint32_t off = (uint32_t)(row * 256 + ((ch ^ (row & 7)) << 4));
        *(uint4*)((unsigned char*)g_tail[2 * arr][b]     + off) = H;
        *(uint4*)((unsigned char*)g_tail[2 * arr + 1][b] + off) = L;
    }
}

// ===========================================================================
// Flash attention: paired q-blocks (bx, 31-bx), causal tile skipping,
// compact global tail. Global ROWS are wrong here; fixup kernel overwrites.
// SMEM: QH 32K | QL 32K | KH 16K | KL 16K | VH 16K | VL 16K = 128 KB.
// ===========================================================================
#define ATTN_SMEM 131072

__global__ __launch_bounds__(256)
void attn_mma_kernel(float* __restrict__ out, GMask gm, GIdx gi)
{
    extern __shared__ char smem[];
    __shared__ int tl[64];
    const uint32_t sb  = smem_to_u32(smem);
    const uint32_t sQH = sb;
    const uint32_t sQL = sb + 32768;
    const uint32_t sKH = sb + 65536;
    const uint32_t sKL = sb + 81920;
    const uint32_t sVH = sb + 98304;
    const uint32_t sVL = sb + 114688;

    const int tid  = threadIdx.x;
    const int w    = tid >> 5;
    const int lane = tid & 31;
    const int g    = lane >> 2;
    const int tg   = lane & 3;
    const int g4   = lane >> 3;
    const int lr   = lane & 7;
    const int b    = blockIdx.y;
    const int bx   = blockIdx.x;          // 0..15
    const int qb_h = 31 - bx;
    const int qb_l = bx;
    const bool heavy = (w < 4);
    const int qb   = heavy ? qb_h : qb_l;
    const int m0s  = w * 16;              // smem row base (heavy 0..63, light 64..127)

    if (tid < 64) tl[tid] = (tid < 32) ? gi.idx[tid] : (int)0x80000000;

    // ---- Q copy: heavy tile -> smem rows 0-63, light tile -> rows 64-127 ----
    #pragma unroll
    for (int seg = 0; seg < 4; seg++) {
        const uint4* src = (seg == 0) ? g_bf[0][b][qb_h] : (seg == 1) ? g_bf[0][b][qb_l]
                         : (seg == 2) ? g_bf[1][b][qb_h] : g_bf[1][b][qb_l];
        const uint32_t doff = (uint32_t)seg * 16384;
        for (int k = tid; k < 1024; k += 256)
            *(uint4*)(smem + doff + k * 16) = src[k];
    }

    const int s0tok = qb * 64 + (w & 3) * 16 + g;   // absolute token index of row 0
    const int s1tok = s0tok + 8;
    const float inv_scale = 0.08838834764831844f;   // 1/sqrt(128)

    float l0 = 0.0f, l1 = 0.0f;
    float O[16][4];
    #pragma unroll
    for (int j = 0; j < 16; j++)
        #pragma unroll
        for (int e = 0; e < 4; e++) O[j][e] = 0.0f;

    const int tmax = 31 - bx;
    for (int t = 0; t <= tmax; t++) {
        __syncthreads();
        #pragma unroll
        for (int seg = 0; seg < 4; seg++) {
            const uint4* src = g_bf[2 + seg][b][t];
            const uint32_t doff = 65536u + (uint32_t)seg * 16384;
            for (int k = tid; k < 1024; k += 256)
                *(uint4*)(smem + doff + k * 16) = src[k];
        }
        __syncthreads();

        if (heavy || t <= bx) {
            float S[8][4];
            #pragma unroll
            for (int j = 0; j < 8; j++)
                #pragma unroll
                for (int e = 0; e < 4; e++) S[j][e] = 0.0f;

            #pragma unroll
            for (int ks = 0; ks < 8; ks++) {
                uint32_t ah[4], al[4];
                const int arow = m0s + ((g4 & 1) << 3) + lr;
                const int ach  = 2 * ks + (g4 >> 1);
                LDSM_X4(ah, swaddr(sQH, arow, ach));
                LDSM_X4(al, swaddr(sQL, arow, ach));
                #pragma unroll
                for (int jp = 0; jp < 4; jp++) {
                    uint32_t bh[4], bl[4];
                    const int brow = 8 * (2 * jp + (g4 >> 1)) + lr;
                    const int bch  = 2 * ks + (g4 & 1);
                    LDSM_X4(bh, swaddr(sKH, brow, bch));
                    LDSM_X4(bl, swaddr(sKL, brow, bch));
                    MMA16816(S[2 * jp],     ah, bh[0], bh[1]);
                    MMA16816(S[2 * jp + 1], ah, bh[2], bh[3]);
                    MMA16816(S[2 * jp],     al, bh[0], bh[1]);
                    MMA16816(S[2 * jp + 1], al, bh[2], bh[3]);
                    MMA16816(S[2 * jp],     ah, bl[0], bl[1]);
                    MMA16816(S[2 * jp + 1], ah, bl[2], bl[3]);
                }
            }

            float rs0 = 0.0f, rs1 = 0.0f;
            #pragma unroll
            for (int j = 0; j < 8; j++) {
                const int cb = 64 * t + 8 * j + 2 * tg;
                const bool cg0 = gbit(gm, cb);
                const bool cg1 = gbit(gm, cb + 1);
                S[j][0] = (cg0 | (cb     <= s0tok)) ? __expf(S[j][0] * inv_scale) : 0.0f;
                S[j][1] = (cg1 | (cb + 1 <= s0tok)) ? __expf(S[j][1] * inv_scale) : 0.0f;
                S[j][2] = (cg0 | (cb     <= s1tok)) ? __expf(S[j][2] * inv_scale) : 0.0f;
                S[j][3] = (cg1 | (cb + 1 <= s1tok)) ? __expf(S[j][3] * inv_scale) : 0.0f;
                rs0 += S[j][0] + S[j][1];
                rs1 += S[j][2] + S[j][3];
            }
            rs0 += __shfl_xor_sync(0xffffffffu, rs0, 1);
            rs0 += __shfl_xor_sync(0xffffffffu, rs0, 2);
            rs1 += __shfl_xor_sync(0xffffffffu, rs1, 1);
            rs1 += __shfl_xor_sync(0xffffffffu, rs1, 2);
            l0 += rs0;
            l1 += rs1;

            #pragma unroll
            for (int ks = 0; ks < 4; ks++) {
                const float* c0 = S[2 * ks];
                const float* c1 = S[2 * ks + 1];
                uint32_t pah[4], pal[4];
                {
                    float h, l, h2, l2;
                    split2(c0[0], h, l); split2(c0[1], h2, l2);
                    pah[0] = packbf(h, h2); pal[0] = packbf(l, l2);
                    split2(c0[2], h, l); split2(c0[3], h2, l2);
                    pah[1] = packbf(h, h2); pal[1] = packbf(l, l2);
                    split2(c1[0], h, l); split2(c1[1], h2, l2);
                    pah[2] = packbf(h, h2); pal[2] = packbf(l, l2);
                    split2(c1[2], h, l); split2(c1[3], h2, l2);
                    pah[3] = packbf(h, h2); pal[3] = packbf(l, l2);
                }
                #pragma unroll
                for (int jp = 0; jp < 8; jp++) {
                    uint32_t bh[4], bl[4];
                    const int brow = 16 * ks + ((g4 & 1) << 3) + lr;
                    const int bch  = 2 * jp + (g4 >> 1);
                    LDSM_X4_T(bh, swaddr(sVH, brow, bch));
                    LDSM_X4_T(bl, swaddr(sVL, brow, bch));
                    MMA16816(O[2 * jp],     pah, bh[0], bh[1]);
                    MMA16816(O[2 * jp + 1], pah, bh[2], bh[3]);
                    MMA16816(O[2 * jp],     pal, bh[0], bh[1]);
                    MMA16816(O[2 * jp + 1], pal, bh[2], bh[3]);
                    MMA16816(O[2 * jp],     pah, bl[0], bl[1]);
                    MMA16816(O[2 * jp + 1], pah, bl[2], bl[3]);
                }
            }
        }
    }

    // ---- global tail: compacted 32 global tokens (padded to 64) ----
    __syncthreads();
    #pragma unroll
    for (int seg = 0; seg < 4; seg++) {
        const uint4* src = g_tail[seg][b];
        const uint32_t doff = 65536u + (uint32_t)seg * 16384;
        for (int k = tid; k < 1024; k += 256)
            *(uint4*)(smem + doff + k * 16) = src[k];
    }
    __syncthreads();

    {
        float S[8][4];
        #pragma unroll
        for (int j = 0; j < 8; j++)
            #pragma unroll
            for (int e = 0; e < 4; e++) S[j][e] = 0.0f;

        #pragma unroll
        for (int ks = 0; ks < 8; ks++) {
            uint32_t ah[4], al[4];
            const int arow = m0s + ((g4 & 1) << 3) + lr;
            const int ach  = 2 * ks + (g4 >> 1);
            LDSM_X4(ah, swaddr(sQH, arow, ach));
            LDSM_X4(al, swaddr(sQL, arow, ach));
            #pragma unroll
            for (int jp = 0; jp < 4; jp++) {
                uint32_t bh[4], bl[4];
                const int brow = 8 * (2 * jp + (g4 >> 1)) + lr;
                const int bch  = 2 * ks + (g4 & 1);
                LDSM_X4(bh, swaddr(sKH, brow, bch));
                LDSM_X4(bl, swaddr(sKL, brow, bch));
                MMA16816(S[2 * jp],     ah, bh[0], bh[1]);
                MMA16816(S[2 * jp + 1], ah, bh[2], bh[3]);
                MMA16816(S[2 * jp],     al, bh[0], bh[1]);
                MMA16816(S[2 * jp + 1], al, bh[2], bh[3]);
                MMA16816(S[2 * jp],     ah, bl[0], bl[1]);
                MMA16816(S[2 * jp + 1], ah, bl[2], bl[3]);
            }
        }

        const int bnd = (qb + 1) * 64;   // keys below bnd already covered causally
        float rs0 = 0.0f, rs1 = 0.0f;
        #pragma unroll
        for (int j = 0; j < 8; j++) {
            const int c0i = 8 * j + 2 * tg;
            const bool ok0 = (tl[c0i]     >= bnd);
            const bool ok1 = (tl[c0i + 1] >= bnd);
            S[j][0] = ok0 ? __expf(S[j][0] * inv_scale) : 0.0f;
            S[j][1] = ok1 ? __expf(S[j][1] * inv_scale) : 0.0f;
            S[j][2] = ok0 ? __expf(S[j][2] * inv_scale) : 0.0f;
            S[j][3] = ok1 ? __expf(S[j][3] * inv_scale) : 0.0f;
            rs0 += S[j][0] + S[j][1];
            rs1 += S[j][2] + S[j][3];
        }
        rs0 += __shfl_xor_sync(0xffffffffu, rs0, 1);
        rs0 += __shfl_xor_sync(0xffffffffu, rs0, 2);
        rs1 += __shfl_xor_sync(0xffffffffu, rs1, 1);
        rs1 += __shfl_xor_sync(0xffffffffu, rs1, 2);
        l0 += rs0;
        l1 += rs1;

        #pragma unroll
        for (int ks = 0; ks < 4; ks++) {
            const float* c0 = S[2 * ks];
            const float* c1 = S[2 * ks + 1];
            uint32_t pah[4], pal[4];
            {
                float h, l, h2, l2;
                split2(c0[0], h, l); split2(c0[1], h2, l2);
                pah[0] = packbf(h, h2); pal[0] = packbf(l, l2);
                split2(c0[2], h, l); split2(c0[3], h2, l2);
                pah[1] = packbf(h, h2); pal[1] = packbf(l, l2);
                split2(c1[0], h, l); split2(c1[1], h2, l2);
                pah[2] = packbf(h, h2); pal[2] = packbf(l, l2);
                split2(c1[2], h, l); split2(c1[3], h2, l2);
                pah[3] = packbf(h, h2); pal[3] = packbf(l, l2);
            }
            #pragma unroll
            for (int jp = 0; jp < 8; jp++) {
                uint32_t bh[4], bl[4];
                const int brow = 16 * ks + ((g4 & 1) << 3) + lr;
                const int bch  = 2 * jp + (g4 >> 1);
                LDSM_X4_T(bh, swaddr(sVH, brow, bch));
                LDSM_X4_T(bl, swaddr(sVL, brow, bch));
                MMA16816(O[2 * jp],     pah, bh[0], bh[1]);
                MMA16816(O[2 * jp + 1], pah, bh[2], bh[3]);
                MMA16816(O[2 * jp],     pal, bh[0], bh[1]);
                MMA16816(O[2 * jp + 1], pal, bh[2], bh[3]);
                MMA16816(O[2 * jp],     pah, bl[0], bl[1]);
                MMA16816(O[2 * jp + 1], pah, bl[2], bl[3]);
            }
        }
    }

    // ---- epilogue ----
    const float inv0 = 1.0f / l0;
    const float inv1 = 1.0f / l1;
    float* o0 = out + ((size_t)b * NS + s0tok) * ND;
    float* o1 = out + ((size_t)b * NS + s1tok) * ND;
    #pragma unroll
    for (int j = 0; j < 16; j++) {
        const int c = 8 * j + 2 * tg;
        *(float2*)(o0 + c) = make_float2(O[j][0] * inv0, O[j][1] * inv0);
        *(float2*)(o1 + c) = make_float2(O[j][2] * inv1, O[j][3] * inv1);
    }
}

// ===========================================================================
// Fixup: dense fp32 attention for the 32 global rows per batch (mask row = 0).
// grid (32, NB), 256 threads.
// ===========================================================================
__global__ __launch_bounds__(256)
void fixup_kernel(float* __restrict__ out, GIdx gi)
{
    __shared__ float Qs[128];
    __shared__ float p[NS];
    __shared__ float red[256];

    const int b = blockIdx.y, i = gi.idx[blockIdx.x], tid = threadIdx.x;
    const float* Qp = g_QKV[0] + ((size_t)b * NS + i) * ND;
    const float* Kp = g_QKV[1] + (size_t)b * NS * ND;
    const float* Vp = g_QKV[2] + (size_t)b * NS * ND;
    const float inv_scale = 0.08838834764831844f;

    if (tid < 128) Qs[tid] = Qp[tid];
    __syncthreads();

    float lpart = 0.0f;
    #pragma unroll
    for (int jj = 0; jj < 8; jj++) {
        const int j = tid + jj * 256;
        const float4* kr = (const float4*)(Kp + (size_t)j * ND);
        float s = 0.0f;
        #pragma unroll
        for (int d4 = 0; d4 < 32; d4++) {
            float4 kv = kr[d4];
            s += Qs[4 * d4] * kv.x + Qs[4 * d4 + 1] * kv.y
               + Qs[4 * d4 + 2] * kv.z + Qs[4 * d4 + 3] * kv.w;
        }
        const float pv = __expf(s * inv_scale);
        p[j] = pv;
        lpart += pv;
    }
    red[tid] = lpart;
    __syncthreads();
    for (int o = 128; o > 0; o >>= 1) {
        if (tid < o) red[tid] += red[tid + o];
        __syncthreads();
    }
    const float lsum = red[0];
    __syncthreads();

    const int d = tid & 127, half = tid >> 7;
    float acc = 0.0f;
    const int j0 = half * 1024;
    #pragma unroll 8
    for (int j = j0; j < j0 + 1024; j++)
        acc += p[j] * Vp[(size_t)j * ND + d];
    red[tid] = acc;
    __syncthreads();
    if (tid < 128)
        out[((size_t)b * NS + i) * ND + tid] = (red[tid] + red[tid + 128]) / lsum;
}

// ---------------------------------------------------------------------------
// Host: exact port of np.random.default_rng(0).choice(2048, 32, replace=False)
// ---------------------------------------------------------------------------
static void compute_global_mask(GMask* gm, GIdx* gidx)
{
    const uint32_t INIT_A = 0x43b0d7e5u, MULT_A = 0x931e8875u;
    const uint32_t INIT_B = 0x8b51f9ddu, MULT_B = 0x58f38dedu;
    const uint32_t MIX_L  = 0xca01f9ddu, MIX_R  = 0x4973f715u;

    uint32_t hc = INIT_A;
    auto hashf = [&](uint32_t v) -> uint32_t {
        v ^= hc; hc *= MULT_A; v *= hc; v ^= v >> 16; return v;
    };
    auto mixf = [&](uint32_t x, uint32_t y) -> uint32_t {
        uint32_t r = MIX_L * x - MIX_R * y;
        r ^= r >> 16; return r;
    };

    uint32_t pool[4];
    for (int i = 0; i < 4; i++) pool[i] = hashf(0u);
    for (int s = 0; s < 4; s++)
        for (int d = 0; d < 4; d++)
            if (s != d)
                pool[d] = mixf(pool[d], hashf(pool[s]));

    uint32_t gw[8]; uint32_t hb = INIT_B;
    for (int i = 0; i < 8; i++) {
        uint32_t dv = pool[i & 3];
        dv ^= hb; hb *= MULT_B; dv *= hb; dv ^= dv >> 16;
        gw[i] = dv;
    }
    uint64_t v64[4];
    for (int k = 0; k < 4; k++)
        v64[k] = (uint64_t)gw[2 * k] | ((uint64_t)gw[2 * k + 1] << 32);

    typedef __uint128_t u128;
    const u128 MULT = ((u128)0x2360ed051fc65da4ULL << 64) | 0x4385df649fccf645ULL;
    u128 inc = ((((u128)v64[2] << 64) | v64[3]) << 1) | 1;
    u128 st  = 0;
    st = st * MULT + inc;
    st += ((u128)v64[0] << 64) | v64[1];
    st = st * MULT + inc;

    int have = 0; uint32_t cache = 0;
    auto n64 = [&]() -> uint64_t {
        st = st * MULT + inc;
        uint64_t hi = (uint64_t)(st >> 64), lo = (uint64_t)st;
        unsigned rot = (unsigned)(hi >> 58);
        uint64_t x = hi ^ lo;
        return rot ? ((x >> rot) | (x << (64 - rot))) : x;
    };
    auto n32 = [&]() -> uint32_t {
        if (have) { have = 0; return cache; }
        uint64_t u = n64();
        have = 1; cache = (uint32_t)(u >> 32);
        return (uint32_t)u;
    };

    bool chosen[NS] = {false};
    for (uint32_t j = NS - 32; j < NS; j++) {
        uint32_t rng_excl = j + 1;
        uint64_t m = (uint64_t)n32() * rng_excl;
        uint32_t leftover = (uint32_t)m;
        if (leftover < rng_excl) {
            uint32_t threshold = (0xFFFFFFFFu - j) % rng_excl;
            while (leftover < threshold) {
                m = (uint64_t)n32() * rng_excl;
                leftover = (uint32_t)m;
            }
        }
        uint32_t val = (uint32_t)(m >> 32);
        if (chosen[val]) val = j;
        chosen[val] = true;
    }

    for (int w = 0; w < NS / 32; w++) gm->w[w] = 0u;
    int n = 0;
    for (int i = 0; i < NS; i++)
        if (chosen[i]) {
            gm->w[i >> 5] |= (1u << (i & 31));
            gidx->idx[n++] = i;
        }
}

extern "C" void kernel_launch(void* const* d_in, const int* in_sizes, int n_in,
                              void* d_out, int out_size)
{
    (void)in_sizes; (void)n_in; (void)out_size;
    GMask gm; GIdx gi;
    compute_global_mask(&gm, &gi);

    cudaFuncSetAttribute(proj_mma_kernel, cudaFuncAttributeMaxDynamicSharedMemorySize, PROJ_SMEM);
    proj_mma_kernel<<<dim3(NB * NS / 128, 3), 256, PROJ_SMEM>>>(
        (const float*)d_in[0], (const float*)d_in[1], (const float*)d_in[2],
        (const float*)d_in[3], (const float*)d_in[4],
        (const float*)d_in[5], (const float*)d_in[6],
        (const float*)d_in[7], (const float*)d_in[8]);

    gather_tail_kernel<<<NB, 256>>>(gi);

    cudaFuncSetAttribute(attn_mma_kernel, cudaFuncAttributeMaxDynamicSharedMemorySize, ATTN_SMEM);
    attn_mma_kernel<<<dim3(16, NB), 256, ATTN_SMEM>>>((float*)d_out, gm, gi);

    fixup_kernel<<<dim3(32, NB), 256>>>((float*)d_out, gi);
}

// round 8
// speedup vs baseline: 1.3248x; 1.3248x over previous
#include <cuda_runtime.h>
#include <cuda_bf16.h>
#include <cstdint>

#define NB   8
#define NS   2048
#define NDIN 1024
#define ND   128

// fp32 Q, K, V scratch: 24 MB
__device__ float g_QKV[3][(size_t)NB * NS * ND];
// bf16 hi/lo pre-swizzled 64-row tiles: [QH,QL,KH,KL,VH,VL][b][tile][16KB] = 24 MB
__device__ uint4 g_bf[6][NB][32][1024];

struct GMask { unsigned int w[NS / 32]; };   // 2048-bit global-token mask

// ===========================================================================
// Warp-MMA helpers (mma.sync / ldmatrix — baseline PTX, no sm_103a gating)
// ===========================================================================
__device__ __forceinline__ uint32_t smem_to_u32(const void* smem_ptr) {
    uint32_t addr;
    asm("{ .reg .u64 tmp; cvta.to.shared.u64 tmp, %1; cvt.u32.u64 %0, tmp; }"
        : "=r"(addr) : "l"(smem_ptr));
    return addr;
}

__device__ __forceinline__ uint32_t packbf(float lo, float hi) {
    uint32_t r;
    asm("cvt.rn.bf16x2.f32 %0, %1, %2;" : "=r"(r) : "f"(hi), "f"(lo));
    return r;
}

__device__ __forceinline__ void split2(float x, float& hf, float& lf) {
    __nv_bfloat16 h = __float2bfloat16_rn(x);
    hf = __bfloat162float(h);
    lf = x - hf;
}

#define LDSM_X4(r, addr) \
    asm volatile("ldmatrix.sync.aligned.m8n8.x4.shared.b16 {%0,%1,%2,%3}, [%4];" \
        : "=r"((r)[0]), "=r"((r)[1]), "=r"((r)[2]), "=r"((r)[3]) : "r"(addr))

#define LDSM_X4_T(r, addr) \
    asm volatile("ldmatrix.sync.aligned.m8n8.x4.trans.shared.b16 {%0,%1,%2,%3}, [%4];" \
        : "=r"((r)[0]), "=r"((r)[1]), "=r"((r)[2]), "=r"((r)[3]) : "r"(addr))

#define MMA16816(d, a, b0, b1) \
    asm("mma.sync.aligned.m16n8k16.row.col.f32.bf16.bf16.f32 " \
        "{%0,%1,%2,%3}, {%4,%5,%6,%7}, {%8,%9}, {%0,%1,%2,%3};" \
        : "+f"((d)[0]), "+f"((d)[1]), "+f"((d)[2]), "+f"((d)[3]) \
        : "r"((a)[0]), "r"((a)[1]), "r"((a)[2]), "r"((a)[3]), "r"(b0), "r"(b1))

// Swizzled address, 256-byte row stride (128 bf16 per row)
__device__ __forceinline__ uint32_t swaddr(uint32_t base, int row, int chunk) {
    return base + row * 256 + ((chunk ^ (row & 7)) << 4);
}
// Swizzled address, 128-byte row stride (proj tiles: 64 bf16 per row)
__device__ __forceinline__ uint32_t swaddr2(uint32_t base, int row, int chunk) {
    return base + row * 128 + ((chunk ^ (row & 7)) << 4);
}

__device__ __forceinline__ bool gbit(const GMask& gm, int i) {
    return (gm.w[i >> 5] >> (i & 31)) & 1u;
}

__device__ __forceinline__ void store_chunk(char* smemc, uint32_t offH, uint32_t offL,
                                            float4 v0, float4 v1) {
    float xs[8] = {v0.x, v0.y, v0.z, v0.w, v1.x, v1.y, v1.z, v1.w};
    float hf[8], lf[8];
    #pragma unroll
    for (int e = 0; e < 8; e++) split2(xs[e], hf[e], lf[e]);
    uint4 H, L;
    H.x = packbf(hf[0], hf[1]); H.y = packbf(hf[2], hf[3]);
    H.z = packbf(hf[4], hf[5]); H.w = packbf(hf[6], hf[7]);
    L.x = packbf(lf[0], lf[1]); L.y = packbf(lf[2], lf[3]);
    L.z = packbf(lf[4], lf[5]); L.w = packbf(lf[6], lf[7]);
    *(uint4*)(smemc + offH) = H;
    *(uint4*)(smemc + offL) = L;
}

// ===========================================================================
// Projection GEMM via mma.sync bf16 hi/lo split.
// Epilogue also emits pre-split, pre-swizzled bf16 hi/lo 64-row tiles (g_bf).
// ===========================================================================
#define PROJ_SMEM 65536

__global__ __launch_bounds__(256)
void proj_mma_kernel(const float* __restrict__ xq, const float* __restrict__ xk, const float* __restrict__ xv,
                     const float* __restrict__ Wq, const float* __restrict__ bq,
                     const float* __restrict__ Wk, const float* __restrict__ bk,
                     const float* __restrict__ Wv, const float* __restrict__ bv)
{
    extern __shared__ char psm[];
    const uint32_t sb  = smem_to_u32(psm);
    const uint32_t sXH = sb;
    const uint32_t sXL = sb + 16384;
    const uint32_t sWH = sb + 32768;
    const uint32_t sWL = sb + 49152;

    const int proj = blockIdx.y;
    const float* X    = (proj == 0) ? xq : (proj == 1) ? xk : xv;
    const float* W    = (proj == 0) ? Wq : (proj == 1) ? Wk : Wv;
    const float* bias = (proj == 0) ? bq : (proj == 1) ? bk : bv;
    float* out = g_QKV[proj];

    const int tid  = threadIdx.x;
    const int w    = tid >> 5;
    const int lane = tid & 31;
    const int g    = lane >> 2;
    const int tg   = lane & 3;
    const int g4   = lane >> 3;
    const int lr   = lane & 7;
    const int m0   = w * 16;
    const int mb   = blockIdx.x * 128;

    float acc[16][4];
    #pragma unroll
    for (int j = 0; j < 16; j++)
        #pragma unroll
        for (int e = 0; e < 4; e++) acc[j][e] = 0.0f;

    for (int kc = 0; kc < NDIN / 64; kc++) {
        const int k0 = kc * 64;
        if (kc) __syncthreads();

        #pragma unroll
        for (int i = 0; i < 4; i++) {
            int u = tid + i * 256;
            int row = u >> 3, ch = u & 7;
            uint32_t off = (uint32_t)(row * 128 + ((ch ^ (row & 7)) << 4));
            const float4* xsrc = (const float4*)(X + (size_t)(mb + row) * NDIN + k0 + ch * 8);
            store_chunk(psm, (sXH - sb) + off, (sXL - sb) + off, xsrc[0], xsrc[1]);
            const float4* wsrc = (const float4*)(W + (size_t)row * NDIN + k0 + ch * 8);
            store_chunk(psm, (sWH - sb) + off, (sWL - sb) + off, wsrc[0], wsrc[1]);
        }
        __syncthreads();

        #pragma unroll
        for (int ks = 0; ks < 4; ks++) {
            uint32_t ah[4], al[4];
            const int arow = m0 + ((g4 & 1) << 3) + lr;
            const int ach  = 2 * ks + (g4 >> 1);
            LDSM_X4(ah, swaddr2(sXH, arow, ach));
            LDSM_X4(al, swaddr2(sXL, arow, ach));
            #pragma unroll
            for (int jp = 0; jp < 8; jp++) {
                uint32_t bh[4], bl[4];
                const int brow = 8 * (2 * jp + (g4 >> 1)) + lr;
                const int bch  = 2 * ks + (g4 & 1);
                LDSM_X4(bh, swaddr2(sWH, brow, bch));
                LDSM_X4(bl, swaddr2(sWL, brow, bch));
                MMA16816(acc[2 * jp],     ah, bh[0], bh[1]);
                MMA16816(acc[2 * jp + 1], ah, bh[2], bh[3]);
                MMA16816(acc[2 * jp],     al, bh[0], bh[1]);
                MMA16816(acc[2 * jp + 1], al, bh[2], bh[3]);
                MMA16816(acc[2 * jp],     ah, bl[0], bl[1]);
                MMA16816(acc[2 * jp + 1], ah, bl[2], bl[3]);
            }
        }
    }

    // ---- epilogue: + bias -> fp32 g_QKV AND bf16 hi/lo swizzled tiles ----
    const int r0   = mb + m0 + g;
    const int r1   = r0 + 8;
    const int bb_  = mb / NS;
    const int s0   = r0 % NS;
    const int tile = s0 >> 6;
    const int rin0 = s0 & 63;
    const int rin1 = rin0 + 8;

    float* o0 = out + (size_t)r0 * ND;
    float* o1 = out + (size_t)r1 * ND;
    unsigned char* pH = (unsigned char*)g_bf[2 * proj][bb_][tile];
    unsigned char* pL = (unsigned char*)g_bf[2 * proj + 1][bb_][tile];

    #pragma unroll
    for (int j = 0; j < 16; j++) {
        const int c = 8 * j + 2 * tg;
        const float b0 = bias[c], b1 = bias[c + 1];
        const float x00 = acc[j][0] + b0, x01 = acc[j][1] + b1;
        const float x10 = acc[j][2] + b0, x11 = acc[j][3] + b1;
        *(float2*)(o0 + c) = make_float2(x00, x01);
        *(float2*)(o1 + c) = make_float2(x10, x11);

        float h, l, h2, l2;
        split2(x00, h, l); split2(x01, h2, l2);
        uint32_t off0 = (uint32_t)(rin0 * 256 + ((j ^ (rin0 & 7)) << 4) + tg * 4);
        *(uint32_t*)(pH + off0) = packbf(h, h2);
        *(uint32_t*)(pL + off0) = packbf(l, l2);

        split2(x10, h, l); split2(x11, h2, l2);
        uint32_t off1 = (uint32_t)(rin1 * 256 + ((j ^ (rin1 & 7)) << 4) + tg * 4);
        *(uint32_t*)(pH + off1) = packbf(h, h2);
        *(uint32_t*)(pL + off1) = packbf(l, l2);
    }
}

// ===========================================================================
// Flash attention via mma.sync bf16 hi/lo split.
// R6 structure (full 32-tile loop, full mask) but tiles are pre-converted:
// all SMEM fills are pure uint4 copies from g_bf.
// CTA = 128 q rows, 8 warps (m16 each), 256 threads, key tiles of 64.
// SMEM: QH 32K | QL 32K | KH 16K | KL 16K | VH 16K | VL 16K = 128 KB.
// ===========================================================================
#define ATTN_SMEM 131072

__global__ __launch_bounds__(256)
void attn_mma_kernel(float* __restrict__ out, GMask gm)
{
    extern __shared__ char smem[];
    const uint32_t sb  = smem_to_u32(smem);
    const uint32_t sQH = sb;
    const uint32_t sQL = sb + 32768;
    const uint32_t sKH = sb + 65536;
    const uint32_t sKL = sb + 81920;
    const uint32_t sVH = sb + 98304;
    const uint32_t sVL = sb + 114688;

    const int tid  = threadIdx.x;
    const int w    = tid >> 5;
    const int lane = tid & 31;
    const int g    = lane >> 2;
    const int tg   = lane & 3;
    const int g4   = lane >> 3;
    const int lr   = lane & 7;
    const int b    = blockIdx.y;
    const int q0   = blockIdx.x * 128;
    const int m0   = w * 16;

    // ---- Q copy: two 64-row tiles per half (pure uint4 copy) ----
    // smem rows 0-63 = tile 2bx, rows 64-127 = tile 2bx+1 (offset +16 KB).
    {
        const int t0 = blockIdx.x * 2;
        #pragma unroll
        for (int seg = 0; seg < 4; seg++) {     // QH0,QH1,QL0,QL1
            const uint4* src = g_bf[seg >> 1][b][t0 + (seg & 1)];
            uint4* dst = (uint4*)(smem + (uint32_t)seg * 16384);
            for (int k = tid; k < 1024; k += 256)
                dst[k] = src[k];
        }
    }

    const int r0a = q0 + m0 + g;
    const int r1a = r0a + 8;
    const bool rg0 = gbit(gm, r0a);
    const bool rg1 = gbit(gm, r1a);
    const float inv_scale = 0.08838834764831844f;   // 1/sqrt(128)

    float l0 = 0.0f, l1 = 0.0f;
    float O[16][4];
    #pragma unroll
    for (int j = 0; j < 16; j++)
        #pragma unroll
        for (int e = 0; e < 4; e++) O[j][e] = 0.0f;

    for (int t = 0; t < NS / 64; t++) {
        const int k0 = t * 64;
        __syncthreads();

        // ---- K, V tile copies (pure uint4) ----
        #pragma unroll
        for (int seg = 0; seg < 4; seg++) {     // KH,KL,VH,VL
            const uint4* src = g_bf[2 + seg][b][t];
            uint4* dst = (uint4*)(smem + 65536u + (uint32_t)seg * 16384);
            for (int k = tid; k < 1024; k += 256)
                dst[k] = src[k];
        }
        __syncthreads();

        float S[8][4];
        #pragma unroll
        for (int j = 0; j < 8; j++)
            #pragma unroll
            for (int e = 0; e < 4; e++) S[j][e] = 0.0f;

        #pragma unroll
        for (int ks = 0; ks < 8; ks++) {
            uint32_t ah[4], al[4];
            const int arow = m0 + ((g4 & 1) << 3) + lr;
            const int ach  = 2 * ks + (g4 >> 1);
            LDSM_X4(ah, swaddr(sQH, arow, ach));
            LDSM_X4(al, swaddr(sQL, arow, ach));
            #pragma unroll
            for (int jp = 0; jp < 4; jp++) {
                uint32_t bh[4], bl[4];
                const int brow = 8 * (2 * jp + (g4 >> 1)) + lr;
                const int bch  = 2 * ks + (g4 & 1);
                LDSM_X4(bh, swaddr(sKH, brow, bch));
                LDSM_X4(bl, swaddr(sKL, brow, bch));
                MMA16816(S[2 * jp],     ah, bh[0], bh[1]);
                MMA16816(S[2 * jp + 1], ah, bh[2], bh[3]);
                MMA16816(S[2 * jp],     al, bh[0], bh[1]);
                MMA16816(S[2 * jp + 1], al, bh[2], bh[3]);
                MMA16816(S[2 * jp],     ah, bl[0], bl[1]);
                MMA16816(S[2 * jp + 1], ah, bl[2], bl[3]);
            }
        }

        float rs0 = 0.0f, rs1 = 0.0f;
        #pragma unroll
        for (int j = 0; j < 8; j++) {
            const int cb = k0 + 8 * j + 2 * tg;
            const bool cg0 = gbit(gm, cb);
            const bool cg1 = gbit(gm, cb + 1);
            S[j][0] = (cg0 | rg0 | (cb     <= r0a)) ? __expf(S[j][0] * inv_scale) : 0.0f;
            S[j][1] = (cg1 | rg0 | (cb + 1 <= r0a)) ? __expf(S[j][1] * inv_scale) : 0.0f;
            S[j][2] = (cg0 | rg1 | (cb     <= r1a)) ? __expf(S[j][2] * inv_scale) : 0.0f;
            S[j][3] = (cg1 | rg1 | (cb + 1 <= r1a)) ? __expf(S[j][3] * inv_scale) : 0.0f;
            rs0 += S[j][0] + S[j][1];
            rs1 += S[j][2] + S[j][3];
        }
        rs0 += __shfl_xor_sync(0xffffffffu, rs0, 1);
        rs0 += __shfl_xor_sync(0xffffffffu, rs0, 2);
        rs1 += __shfl_xor_sync(0xffffffffu, rs1, 1);
        rs1 += __shfl_xor_sync(0xffffffffu, rs1, 2);
        l0 += rs0;
        l1 += rs1;

        #pragma unroll
        for (int ks = 0; ks < 4; ks++) {
            const float* c0 = S[2 * ks];
            const float* c1 = S[2 * ks + 1];
            uint32_t pah[4], pal[4];
            {
                float h, l, h2, l2;
                split2(c0[0], h, l); split2(c0[1], h2, l2);
                pah[0] = packbf(h, h2); pal[0] = packbf(l, l2);
                split2(c0[2], h, l); split2(c0[3], h2, l2);
                pah[1] = packbf(h, h2); pal[1] = packbf(l, l2);
                split2(c1[0], h, l); split2(c1[1], h2, l2);
                pah[2] = packbf(h, h2); pal[2] = packbf(l, l2);
                split2(c1[2], h, l); split2(c1[3], h2, l2);
                pah[3] = packbf(h, h2); pal[3] = packbf(l, l2);
            }
            #pragma unroll
            for (int jp = 0; jp < 8; jp++) {
                uint32_t bh[4], bl[4];
                const int brow = 16 * ks + ((g4 & 1) << 3) + lr;
                const int bch  = 2 * jp + (g4 >> 1);
                LDSM_X4_T(bh, swaddr(sVH, brow, bch));
                LDSM_X4_T(bl, swaddr(sVL, brow, bch));
                MMA16816(O[2 * jp],     pah, bh[0], bh[1]);
                MMA16816(O[2 * jp + 1], pah, bh[2], bh[3]);
                MMA16816(O[2 * jp],     pal, bh[0], bh[1]);
                MMA16816(O[2 * jp + 1], pal, bh[2], bh[3]);
                MMA16816(O[2 * jp],     pah, bl[0], bl[1]);
                MMA16816(O[2 * jp + 1], pah, bl[2], bl[3]);
            }
        }
    }

    const float inv0 = 1.0f / l0;
    const float inv1 = 1.0f / l1;
    float* o0 = out + ((size_t)b * NS + r0a) * ND;
    float* o1 = out + ((size_t)b * NS + r1a) * ND;
    #pragma unroll
    for (int j = 0; j < 16; j++) {
        const int c = 8 * j + 2 * tg;
        *(float2*)(o0 + c) = make_float2(O[j][0] * inv0, O[j][1] * inv0);
        *(float2*)(o1 + c) = make_float2(O[j][2] * inv1, O[j][3] * inv1);
    }
}

// ---------------------------------------------------------------------------
// Host: exact port of np.random.default_rng(0).choice(2048, 32, replace=False)
// ---------------------------------------------------------------------------
static void compute_global_mask(GMask* gm)
{
    const uint32_t INIT_A = 0x43b0d7e5u, MULT_A = 0x931e8875u;
    const uint32_t INIT_B = 0x8b51f9ddu, MULT_B = 0x58f38dedu;
    const uint32_t MIX_L  = 0xca01f9ddu, MIX_R  = 0x4973f715u;

    uint32_t hc = INIT_A;
    auto hashf = [&](uint32_t v) -> uint32_t {
        v ^= hc; hc *= MULT_A; v *= hc; v ^= v >> 16; return v;
    };
    auto mixf = [&](uint32_t x, uint32_t y) -> uint32_t {
        uint32_t r = MIX_L * x - MIX_R * y;
        r ^= r >> 16; return r;
    };

    uint32_t pool[4];
    for (int i = 0; i < 4; i++) pool[i] = hashf(0u);
    for (int s = 0; s < 4; s++)
        for (int d = 0; d < 4; d++)
            if (s != d)
                pool[d] = mixf(pool[d], hashf(pool[s]));

    uint32_t gw[8]; uint32_t hb = INIT_B;
    for (int i = 0; i < 8; i++) {
        uint32_t dv = pool[i & 3];
        dv ^= hb; hb *= MULT_B; dv *= hb; dv ^= dv >> 16;
        gw[i] = dv;
    }
    uint64_t v64[4];
    for (int k = 0; k < 4; k++)
        v64[k] = (uint64_t)gw[2 * k] | ((uint64_t)gw[2 * k + 1] << 32);

    typedef __uint128_t u128;
    const u128 MULT = ((u128)0x2360ed051fc65da4ULL << 64) | 0x4385df649fccf645ULL;
    u128 inc = ((((u128)v64[2] << 64) | v64[3]) << 1) | 1;
    u128 st  = 0;
    st = st * MULT + inc;
    st += ((u128)v64[0] << 64) | v64[1];
    st = st * MULT + inc;

    int have = 0; uint32_t cache = 0;
    auto n64 = [&]() -> uint64_t {
        st = st * MULT + inc;
        uint64_t hi = (uint64_t)(st >> 64), lo = (uint64_t)st;
        unsigned rot = (unsigned)(hi >> 58);
        uint64_t x = hi ^ lo;
        return rot ? ((x >> rot) | (x << (64 - rot))) : x;
    };
    auto n32 = [&]() -> uint32_t {
        if (have) { have = 0; return cache; }
        uint64_t u = n64();
        have = 1; cache = (uint32_t)(u >> 32);
        return (uint32_t)u;
    };

    bool chosen[NS] = {false};
    for (uint32_t j = NS - 32; j < NS; j++) {
        uint32_t rng_excl = j + 1;
        uint64_t m = (uint64_t)n32() * rng_excl;
        uint32_t leftover = (uint32_t)m;
        if (leftover < rng_excl) {
            uint32_t threshold = (0xFFFFFFFFu - j) % rng_excl;
            while (leftover < threshold) {
                m = (uint64_t)n32() * rng_excl;
                leftover = (uint32_t)m;
            }
        }
        uint32_t val = (uint32_t)(m >> 32);
        if (chosen[val]) val = j;
        chosen[val] = true;
    }

    for (int w = 0; w < NS / 32; w++) gm->w[w] = 0u;
    for (int i = 0; i < NS; i++)
        if (chosen[i]) gm->w[i >> 5] |= (1u << (i & 31));
}

extern "C" void kernel_launch(void* const* d_in, const int* in_sizes, int n_in,
                              void* d_out, int out_size)
{
    (void)in_sizes; (void)n_in; (void)out_size;
    GMask gm;
    compute_global_mask(&gm);

    cudaFuncSetAttribute(proj_mma_kernel, cudaFuncAttributeMaxDynamicSharedMemorySize, PROJ_SMEM);
    proj_mma_kernel<<<dim3(NB * NS / 128, 3), 256, PROJ_SMEM>>>(
        (const float*)d_in[0], (const float*)d_in[1], (const float*)d_in[2],
        (const float*)d_in[3], (const float*)d_in[4],
        (const float*)d_in[5], (const float*)d_in[6],
        (const float*)d_in[7], (const float*)d_in[8]);

    cudaFuncSetAttribute(attn_mma_kernel, cudaFuncAttributeMaxDynamicSharedMemorySize, ATTN_SMEM);
    attn_mma_kernel<<<dim3(NS / 128, NB), 256, ATTN_SMEM>>>((float*)d_out, gm);
}

// round 9
// speedup vs baseline: 1.8588x; 1.4031x over previous
#include <cuda_runtime.h>
#include <cuda_bf16.h>
#include <cstdint>

#define NB   8
#define NS   2048
#define NDIN 1024
#define ND   128

// bf16 hi/lo pre-swizzled 64-row tiles: [QH,QL,KH,KL,VH,VL][b][tile][16KB] = 24 MB
__device__ uint4 g_bf[6][NB][32][1024];

struct GMask { unsigned int w[NS / 32]; };   // 2048-bit global-token mask

// ===========================================================================
// Warp-MMA helpers (mma.sync / ldmatrix / cp.async — baseline PTX)
// ===========================================================================
__device__ __forceinline__ uint32_t smem_to_u32(const void* smem_ptr) {
    uint32_t addr;
    asm("{ .reg .u64 tmp; cvta.to.shared.u64 tmp, %1; cvt.u32.u64 %0, tmp; }"
        : "=r"(addr) : "l"(smem_ptr));
    return addr;
}

__device__ __forceinline__ uint32_t packbf(float lo, float hi) {
    uint32_t r;
    asm("cvt.rn.bf16x2.f32 %0, %1, %2;" : "=r"(r) : "f"(hi), "f"(lo));
    return r;
}

__device__ __forceinline__ void split2(float x, float& hf, float& lf) {
    __nv_bfloat16 h = __float2bfloat16_rn(x);
    hf = __bfloat162float(h);
    lf = x - hf;
}

#define LDSM_X4(r, addr) \
    asm volatile("ldmatrix.sync.aligned.m8n8.x4.shared.b16 {%0,%1,%2,%3}, [%4];" \
        : "=r"((r)[0]), "=r"((r)[1]), "=r"((r)[2]), "=r"((r)[3]) : "r"(addr))

#define LDSM_X4_T(r, addr) \
    asm volatile("ldmatrix.sync.aligned.m8n8.x4.trans.shared.b16 {%0,%1,%2,%3}, [%4];" \
        : "=r"((r)[0]), "=r"((r)[1]), "=r"((r)[2]), "=r"((r)[3]) : "r"(addr))

#define MMA16816(d, a, b0, b1) \
    asm("mma.sync.aligned.m16n8k16.row.col.f32.bf16.bf16.f32 " \
        "{%0,%1,%2,%3}, {%4,%5,%6,%7}, {%8,%9}, {%0,%1,%2,%3};" \
        : "+f"((d)[0]), "+f"((d)[1]), "+f"((d)[2]), "+f"((d)[3]) \
        : "r"((a)[0]), "r"((a)[1]), "r"((a)[2]), "r"((a)[3]), "r"(b0), "r"(b1))

#define CP_ASYNC16(dst_u32, src_ptr) \
    asm volatile("cp.async.cg.shared.global [%0], [%1], 16;" \
        :: "r"(dst_u32), "l"(src_ptr) : "memory")
#define CP_COMMIT()  asm volatile("cp.async.commit_group;" ::: "memory")
#define CP_WAIT0()   asm volatile("cp.async.wait_group 0;" ::: "memory")
#define CP_WAIT1()   asm volatile("cp.async.wait_group 1;" ::: "memory")

// Swizzled address, 256-byte row stride (128 bf16 per row)
__device__ __forceinline__ uint32_t swaddr(uint32_t base, int row, int chunk) {
    return base + row * 256 + ((chunk ^ (row & 7)) << 4);
}
// Swizzled address, 128-byte row stride (proj tiles: 64 bf16 per row)
__device__ __forceinline__ uint32_t swaddr2(uint32_t base, int row, int chunk) {
    return base + row * 128 + ((chunk ^ (row & 7)) << 4);
}

__device__ __forceinline__ bool gbit(const GMask& gm, int i) {
    return (gm.w[i >> 5] >> (i & 31)) & 1u;
}

__device__ __forceinline__ void store_chunk(char* smemc, uint32_t offH, uint32_t offL,
                                            float4 v0, float4 v1) {
    float xs[8] = {v0.x, v0.y, v0.z, v0.w, v1.x, v1.y, v1.z, v1.w};
    float hf[8], lf[8];
    #pragma unroll
    for (int e = 0; e < 8; e++) split2(xs[e], hf[e], lf[e]);
    uint4 H, L;
    H.x = packbf(hf[0], hf[1]); H.y = packbf(hf[2], hf[3]);
    H.z = packbf(hf[4], hf[5]); H.w = packbf(hf[6], hf[7]);
    L.x = packbf(lf[0], lf[1]); L.y = packbf(lf[2], lf[3]);
    L.z = packbf(lf[4], lf[5]); L.w = packbf(lf[6], lf[7]);
    *(uint4*)(smemc + offH) = H;
    *(uint4*)(smemc + offL) = L;
}

// ===========================================================================
// Projection GEMM via mma.sync bf16 hi/lo split.
// Epilogue emits ONLY pre-split, pre-swizzled bf16 hi/lo tiles (g_bf).
// ===========================================================================
#define PROJ_SMEM 65536

__global__ __launch_bounds__(256)
void proj_mma_kernel(const float* __restrict__ xq, const float* __restrict__ xk, const float* __restrict__ xv,
                     const float* __restrict__ Wq, const float* __restrict__ bq,
                     const float* __restrict__ Wk, const float* __restrict__ bk,
                     const float* __restrict__ Wv, const float* __restrict__ bv)
{
    extern __shared__ char psm[];
    const uint32_t sb  = smem_to_u32(psm);
    const uint32_t sXH = sb;
    const uint32_t sXL = sb + 16384;
    const uint32_t sWH = sb + 32768;
    const uint32_t sWL = sb + 49152;

    const int proj = blockIdx.y;
    const float* X    = (proj == 0) ? xq : (proj == 1) ? xk : xv;
    const float* W    = (proj == 0) ? Wq : (proj == 1) ? Wk : Wv;
    const float* bias = (proj == 0) ? bq : (proj == 1) ? bk : bv;

    const int tid  = threadIdx.x;
    const int w    = tid >> 5;
    const int lane = tid & 31;
    const int g    = lane >> 2;
    const int tg   = lane & 3;
    const int g4   = lane >> 3;
    const int lr   = lane & 7;
    const int m0   = w * 16;
    const int mb   = blockIdx.x * 128;

    float acc[16][4];
    #pragma unroll
    for (int j = 0; j < 16; j++)
        #pragma unroll
        for (int e = 0; e < 4; e++) acc[j][e] = 0.0f;

    for (int kc = 0; kc < NDIN / 64; kc++) {
        const int k0 = kc * 64;
        if (kc) __syncthreads();

        #pragma unroll
        for (int i = 0; i < 4; i++) {
            int u = tid + i * 256;
            int row = u >> 3, ch = u & 7;
            uint32_t off = (uint32_t)(row * 128 + ((ch ^ (row & 7)) << 4));
            const float4* xsrc = (const float4*)(X + (size_t)(mb + row) * NDIN + k0 + ch * 8);
            store_chunk(psm, (sXH - sb) + off, (sXL - sb) + off, xsrc[0], xsrc[1]);
            const float4* wsrc = (const float4*)(W + (size_t)row * NDIN + k0 + ch * 8);
            store_chunk(psm, (sWH - sb) + off, (sWL - sb) + off, wsrc[0], wsrc[1]);
        }
        __syncthreads();

        #pragma unroll
        for (int ks = 0; ks < 4; ks++) {
            uint32_t ah[4], al[4];
            const int arow = m0 + ((g4 & 1) << 3) + lr;
            const int ach  = 2 * ks + (g4 >> 1);
            LDSM_X4(ah, swaddr2(sXH, arow, ach));
            LDSM_X4(al, swaddr2(sXL, arow, ach));
            #pragma unroll
            for (int jp = 0; jp < 8; jp++) {
                uint32_t bh[4], bl[4];
                const int brow = 8 * (2 * jp + (g4 >> 1)) + lr;
                const int bch  = 2 * ks + (g4 & 1);
                LDSM_X4(bh, swaddr2(sWH, brow, bch));
                LDSM_X4(bl, swaddr2(sWL, brow, bch));
                MMA16816(acc[2 * jp],     ah, bh[0], bh[1]);
                MMA16816(acc[2 * jp + 1], ah, bh[2], bh[3]);
                MMA16816(acc[2 * jp],     al, bh[0], bh[1]);
                MMA16816(acc[2 * jp + 1], al, bh[2], bh[3]);
                MMA16816(acc[2 * jp],     ah, bl[0], bl[1]);
                MMA16816(acc[2 * jp + 1], ah, bl[2], bl[3]);
            }
        }
    }

    // ---- epilogue: + bias -> bf16 hi/lo swizzled tiles ----
    const int r0   = mb + m0 + g;
    const int bb_  = mb / NS;
    const int s0   = r0 % NS;
    const int tile = s0 >> 6;
    const int rin0 = s0 & 63;
    const int rin1 = rin0 + 8;

    unsigned char* pH = (unsigned char*)g_bf[2 * proj][bb_][tile];
    unsigned char* pL = (unsigned char*)g_bf[2 * proj + 1][bb_][tile];

    #pragma unroll
    for (int j = 0; j < 16; j++) {
        const int c = 8 * j + 2 * tg;
        const float b0 = bias[c], b1 = bias[c + 1];
        const float x00 = acc[j][0] + b0, x01 = acc[j][1] + b1;
        const float x10 = acc[j][2] + b0, x11 = acc[j][3] + b1;

        float h, l, h2, l2;
        split2(x00, h, l); split2(x01, h2, l2);
        uint32_t off0 = (uint32_t)(rin0 * 256 + ((j ^ (rin0 & 7)) << 4) + tg * 4);
        *(uint32_t*)(pH + off0) = packbf(h, h2);
        *(uint32_t*)(pL + off0) = packbf(l, l2);

        split2(x10, h, l); split2(x11, h2, l2);
        uint32_t off1 = (uint32_t)(rin1 * 256 + ((j ^ (rin1 & 7)) << 4) + tg * 4);
        *(uint32_t*)(pH + off1) = packbf(h, h2);
        *(uint32_t*)(pL + off1) = packbf(l, l2);
    }
}

// ===========================================================================
// Flash attention: mma.sync bf16 hi/lo split, cp.async double-buffered tiles.
// CTA = 128 q rows, 8 warps (m16 each), 256 threads, key tiles of 64.
// SMEM: QH|QL 64K, then two 64K K/V buffers (KH|KL|VH|VL each) = 192 KB.
// ===========================================================================
#define ATTN_SMEM 196608

__global__ __launch_bounds__(256)
void attn_mma_kernel(float* __restrict__ out, GMask gm)
{
    extern __shared__ char smem[];
    const uint32_t sb  = smem_to_u32(smem);
    const uint32_t sQH = sb;
    const uint32_t sQL = sb + 32768;

    const int tid  = threadIdx.x;
    const int w    = tid >> 5;
    const int lane = tid & 31;
    const int g    = lane >> 2;
    const int tg   = lane & 3;
    const int g4   = lane >> 3;
    const int lr   = lane & 7;
    const int b    = blockIdx.y;
    const int q0   = blockIdx.x * 128;
    const int m0   = w * 16;

    // ---- group 0: Q tiles (2x 64-row) via cp.async ----
    #pragma unroll
    for (int seg = 0; seg < 4; seg++) {         // QH0,QH1,QL0,QL1
        const uint4* src = g_bf[seg >> 1][b][blockIdx.x * 2 + (seg & 1)];
        const uint32_t d0 = sb + (uint32_t)seg * 16384 + (uint32_t)tid * 16;
        #pragma unroll
        for (int k = 0; k < 4; k++)
            CP_ASYNC16(d0 + (uint32_t)k * 4096, src + tid + k * 256);
    }
    CP_COMMIT();

    // ---- group 1: tile 0 K/V into buffer 0 ----
    {
        const uint32_t bufb = sb + 65536u;
        #pragma unroll
        for (int seg = 0; seg < 4; seg++) {     // KH,KL,VH,VL
            const uint4* src = g_bf[2 + seg][b][0];
            const uint32_t d0 = bufb + (uint32_t)seg * 16384 + (uint32_t)tid * 16;
            #pragma unroll
            for (int k = 0; k < 4; k++)
                CP_ASYNC16(d0 + (uint32_t)k * 4096, src + tid + k * 256);
        }
    }
    CP_COMMIT();

    const int r0a = q0 + m0 + g;
    const int r1a = r0a + 8;
    const bool rg0 = gbit(gm, r0a);
    const bool rg1 = gbit(gm, r1a);
    const float inv_scale = 0.08838834764831844f;   // 1/sqrt(128)

    float l0 = 0.0f, l1 = 0.0f;
    float O[16][4];
    #pragma unroll
    for (int j = 0; j < 16; j++)
        #pragma unroll
        for (int e = 0; e < 4; e++) O[j][e] = 0.0f;

    for (int t = 0; t < NS / 64; t++) {
        const int k0 = t * 64;

        // prefetch tile t+1 into the other buffer
        if (t + 1 < NS / 64) {
            const uint32_t bufb = sb + 65536u + (uint32_t)((t + 1) & 1) * 65536u;
            #pragma unroll
            for (int seg = 0; seg < 4; seg++) {
                const uint4* src = g_bf[2 + seg][b][t + 1];
                const uint32_t d0 = bufb + (uint32_t)seg * 16384 + (uint32_t)tid * 16;
                #pragma unroll
                for (int k = 0; k < 4; k++)
                    CP_ASYNC16(d0 + (uint32_t)k * 4096, src + tid + k * 256);
            }
            CP_COMMIT();
            CP_WAIT1();       // tile t (and Q) complete; t+1 may be in flight
        } else {
            CP_WAIT0();
        }
        __syncthreads();

        const uint32_t bufb = sb + 65536u + (uint32_t)(t & 1) * 65536u;
        const uint32_t sKH = bufb;
        const uint32_t sKL = bufb + 16384;
        const uint32_t sVH = bufb + 32768;
        const uint32_t sVL = bufb + 49152;

        float S[8][4];
        #pragma unroll
        for (int j = 0; j < 8; j++)
            #pragma unroll
            for (int e = 0; e < 4; e++) S[j][e] = 0.0f;

        #pragma unroll
        for (int ks = 0; ks < 8; ks++) {
            uint32_t ah[4], al[4];
            const int arow = m0 + ((g4 & 1) << 3) + lr;
            const int ach  = 2 * ks + (g4 >> 1);
            LDSM_X4(ah, swaddr(sQH, arow, ach));
            LDSM_X4(al, swaddr(sQL, arow, ach));
            #pragma unroll
            for (int jp = 0; jp < 4; jp++) {
                uint32_t bh[4], bl[4];
                const int brow = 8 * (2 * jp + (g4 >> 1)) + lr;
                const int bch  = 2 * ks + (g4 & 1);
                LDSM_X4(bh, swaddr(sKH, brow, bch));
                LDSM_X4(bl, swaddr(sKL, brow, bch));
                MMA16816(S[2 * jp],     ah, bh[0], bh[1]);
                MMA16816(S[2 * jp + 1], ah, bh[2], bh[3]);
                MMA16816(S[2 * jp],     al, bh[0], bh[1]);
                MMA16816(S[2 * jp + 1], al, bh[2], bh[3]);
                MMA16816(S[2 * jp],     ah, bl[0], bl[1]);
                MMA16816(S[2 * jp + 1], ah, bl[2], bl[3]);
            }
        }

        float rs0 = 0.0f, rs1 = 0.0f;
        #pragma unroll
        for (int j = 0; j < 8; j++) {
            const int cb = k0 + 8 * j + 2 * tg;
            const bool cg0 = gbit(gm, cb);
            const bool cg1 = gbit(gm, cb + 1);
            S[j][0] = (cg0 | rg0 | (cb     <= r0a)) ? __expf(S[j][0] * inv_scale) : 0.0f;
            S[j][1] = (cg1 | rg0 | (cb + 1 <= r0a)) ? __expf(S[j][1] * inv_scale) : 0.0f;
            S[j][2] = (cg0 | rg1 | (cb     <= r1a)) ? __expf(S[j][2] * inv_scale) : 0.0f;
            S[j][3] = (cg1 | rg1 | (cb + 1 <= r1a)) ? __expf(S[j][3] * inv_scale) : 0.0f;
            rs0 += S[j][0] + S[j][1];
            rs1 += S[j][2] + S[j][3];
        }
        rs0 += __shfl_xor_sync(0xffffffffu, rs0, 1);
        rs0 += __shfl_xor_sync(0xffffffffu, rs0, 2);
        rs1 += __shfl_xor_sync(0xffffffffu, rs1, 1);
        rs1 += __shfl_xor_sync(0xffffffffu, rs1, 2);
        l0 += rs0;
        l1 += rs1;

        #pragma unroll
        for (int ks = 0; ks < 4; ks++) {
            const float* c0 = S[2 * ks];
            const float* c1 = S[2 * ks + 1];
            uint32_t pah[4], pal[4];
            {
                float h, l, h2, l2;
                split2(c0[0], h, l); split2(c0[1], h2, l2);
                pah[0] = packbf(h, h2); pal[0] = packbf(l, l2);
                split2(c0[2], h, l); split2(c0[3], h2, l2);
                pah[1] = packbf(h, h2); pal[1] = packbf(l, l2);
                split2(c1[0], h, l); split2(c1[1], h2, l2);
                pah[2] = packbf(h, h2); pal[2] = packbf(l, l2);
                split2(c1[2], h, l); split2(c1[3], h2, l2);
                pah[3] = packbf(h, h2); pal[3] = packbf(l, l2);
            }
            #pragma unroll
            for (int jp = 0; jp < 8; jp++) {
                uint32_t bh[4], bl[4];
                const int brow = 16 * ks + ((g4 & 1) << 3) + lr;
                const int bch  = 2 * jp + (g4 >> 1);
                LDSM_X4_T(bh, swaddr(sVH, brow, bch));
                LDSM_X4_T(bl, swaddr(sVL, brow, bch));
                MMA16816(O[2 * jp],     pah, bh[0], bh[1]);
                MMA16816(O[2 * jp + 1], pah, bh[2], bh[3]);
                MMA16816(O[2 * jp],     pal, bh[0], bh[1]);
                MMA16816(O[2 * jp + 1], pal, bh[2], bh[3]);
                MMA16816(O[2 * jp],     pah, bl[0], bl[1]);
                MMA16816(O[2 * jp + 1], pah, bl[2], bl[3]);
            }
        }
        __syncthreads();   // all warps done with buf[t&1] before t+2 prefetch
    }

    const float inv0 = 1.0f / l0;
    const float inv1 = 1.0f / l1;
    float* o0 = out + ((size_t)b * NS + r0a) * ND;
    float* o1 = out + ((size_t)b * NS + r1a) * ND;
    #pragma unroll
    for (int j = 0; j < 16; j++) {
        const int c = 8 * j + 2 * tg;
        *(float2*)(o0 + c) = make_float2(O[j][0] * inv0, O[j][1] * inv0);
        *(float2*)(o1 + c) = make_float2(O[j][2] * inv1, O[j][3] * inv1);
    }
}

// ---------------------------------------------------------------------------
// Host: exact port of np.random.default_rng(0).choice(2048, 32, replace=False)
// ---------------------------------------------------------------------------
static void compute_global_mask(GMask* gm)
{
    const uint32_t INIT_A = 0x43b0d7e5u, MULT_A = 0x931e8875u;
    const uint32_t INIT_B = 0x8b51f9ddu, MULT_B = 0x58f38dedu;
    const uint32_t MIX_L  = 0xca01f9ddu, MIX_R  = 0x4973f715u;

    uint32_t hc = INIT_A;
    auto hashf = [&](uint32_t v) -> uint32_t {
        v ^= hc; hc *= MULT_A; v *= hc; v ^= v >> 16; return v;
    };
    auto mixf = [&](uint32_t x, uint32_t y) -> uint32_t {
        uint32_t r = MIX_L * x - MIX_R * y;
        r ^= r >> 16; return r;
    };

    uint32_t pool[4];
    for (int i = 0; i < 4; i++) pool[i] = hashf(0u);
    for (int s = 0; s < 4; s++)
        for (int d = 0; d < 4; d++)
            if (s != d)
                pool[d] = mixf(pool[d], hashf(pool[s]));

    uint32_t gw[8]; uint32_t hb = INIT_B;
    for (int i = 0; i < 8; i++) {
        uint32_t dv = pool[i & 3];
        dv ^= hb; hb *= MULT_B; dv *= hb; dv ^= dv >> 16;
        gw[i] = dv;
    }
    uint64_t v64[4];
    for (int k = 0; k < 4; k++)
        v64[k] = (uint64_t)gw[2 * k] | ((uint64_t)gw[2 * k + 1] << 32);

    typedef __uint128_t u128;
    const u128 MULT = ((u128)0x2360ed051fc65da4ULL << 64) | 0x4385df649fccf645ULL;
    u128 inc = ((((u128)v64[2] << 64) | v64[3]) << 1) | 1;
    u128 st  = 0;
    st = st * MULT + inc;
    st += ((u128)v64[0] << 64) | v64[1];
    st = st * MULT + inc;

    int have = 0; uint32_t cache = 0;
    auto n64 = [&]() -> uint64_t {
        st = st * MULT + inc;
        uint64_t hi = (uint64_t)(st >> 64), lo = (uint64_t)st;
        unsigned rot = (unsigned)(hi >> 58);
        uint64_t x = hi ^ lo;
        return rot ? ((x >> rot) | (x << (64 - rot))) : x;
    };
    auto n32 = [&]() -> uint32_t {
        if (have) { have = 0; return cache; }
        uint64_t u = n64();
        have = 1; cache = (uint32_t)(u >> 32);
        return (uint32_t)u;
    };

    bool chosen[NS] = {false};
    for (uint32_t j = NS - 32; j < NS; j++) {
        uint32_t rng_excl = j + 1;
        uint64_t m = (uint64_t)n32() * rng_excl;
        uint32_t leftover = (uint32_t)m;
        if (leftover < rng_excl) {
            uint32_t threshold = (0xFFFFFFFFu - j) % rng_excl;
            while (leftover < threshold) {
                m = (uint64_t)n32() * rng_excl;
                leftover = (uint32_t)m;
            }
        }
        uint32_t val = (uint32_t)(m >> 32);
        if (chosen[val]) val = j;
        chosen[val] = true;
    }

    for (int w = 0; w < NS / 32; w++) gm->w[w] = 0u;
    for (int i = 0; i < NS; i++)
        if (chosen[i]) gm->w[i >> 5] |= (1u << (i & 31));
}

extern "C" void kernel_launch(void* const* d_in, const int* in_sizes, int n_in,
                              void* d_out, int out_size)
{
    (void)in_sizes; (void)n_in; (void)out_size;
    GMask gm;
    compute_global_mask(&gm);

    cudaFuncSetAttribute(proj_mma_kernel, cudaFuncAttributeMaxDynamicSharedMemorySize, PROJ_SMEM);
    proj_mma_kernel<<<dim3(NB * NS / 128, 3), 256, PROJ_SMEM>>>(
        (const float*)d_in[0], (const float*)d_in[1], (const float*)d_in[2],
        (const float*)d_in[3], (const float*)d_in[4],
        (const float*)d_in[5], (const float*)d_in[6],
        (const float*)d_in[7], (const float*)d_in[8]);

    cudaFuncSetAttribute(attn_mma_kernel, cudaFuncAttributeMaxDynamicSharedMemorySize, ATTN_SMEM);
    attn_mma_kernel<<<dim3(NS / 128, NB), 256, ATTN_SMEM>>>((float*)d_out, gm);
}

// round 10
// speedup vs baseline: 1.8715x; 1.0068x over previous
#include <cuda_runtime.h>
#include <cuda_bf16.h>
#include <cstdint>

#define NB   8
#define NS   2048
#define NDIN 1024
#define ND   128

// bf16 hi/lo pre-swizzled 64-row tiles: [QH,QL,KH,KL,VH,VL][b][tile][16KB] = 24 MB
__device__ uint4 g_bf[6][NB][32][1024];

struct GMask { unsigned int w[NS / 32]; };   // 2048-bit global-token mask

// ===========================================================================
// Warp-MMA helpers (mma.sync / ldmatrix / cp.async — baseline PTX)
// ===========================================================================
__device__ __forceinline__ uint32_t smem_to_u32(const void* smem_ptr) {
    uint32_t addr;
    asm("{ .reg .u64 tmp; cvta.to.shared.u64 tmp, %1; cvt.u32.u64 %0, tmp; }"
        : "=r"(addr) : "l"(smem_ptr));
    return addr;
}

__device__ __forceinline__ uint32_t packbf(float lo, float hi) {
    uint32_t r;
    asm("cvt.rn.bf16x2.f32 %0, %1, %2;" : "=r"(r) : "f"(hi), "f"(lo));
    return r;
}

__device__ __forceinline__ void split2(float x, float& hf, float& lf) {
    __nv_bfloat16 h = __float2bfloat16_rn(x);
    hf = __bfloat162float(h);
    lf = x - hf;
}

#define LDSM_X4(r, addr) \
    asm volatile("ldmatrix.sync.aligned.m8n8.x4.shared.b16 {%0,%1,%2,%3}, [%4];" \
        : "=r"((r)[0]), "=r"((r)[1]), "=r"((r)[2]), "=r"((r)[3]) : "r"(addr))

#define LDSM_X4_T(r, addr) \
    asm volatile("ldmatrix.sync.aligned.m8n8.x4.trans.shared.b16 {%0,%1,%2,%3}, [%4];" \
        : "=r"((r)[0]), "=r"((r)[1]), "=r"((r)[2]), "=r"((r)[3]) : "r"(addr))

#define MMA16816(d, a, b0, b1) \
    asm("mma.sync.aligned.m16n8k16.row.col.f32.bf16.bf16.f32 " \
        "{%0,%1,%2,%3}, {%4,%5,%6,%7}, {%8,%9}, {%0,%1,%2,%3};" \
        : "+f"((d)[0]), "+f"((d)[1]), "+f"((d)[2]), "+f"((d)[3]) \
        : "r"((a)[0]), "r"((a)[1]), "r"((a)[2]), "r"((a)[3]), "r"(b0), "r"(b1))

#define CP_ASYNC16(dst_u32, src_ptr) \
    asm volatile("cp.async.cg.shared.global [%0], [%1], 16;" \
        :: "r"(dst_u32), "l"(src_ptr) : "memory")
#define CP_COMMIT()  asm volatile("cp.async.commit_group;" ::: "memory")
#define CP_WAIT0()   asm volatile("cp.async.wait_group 0;" ::: "memory")
#define CP_WAIT1()   asm volatile("cp.async.wait_group 1;" ::: "memory")

// Swizzled address, 256-byte row stride (128 bf16 per row)
__device__ __forceinline__ uint32_t swaddr(uint32_t base, int row, int chunk) {
    return base + row * 256 + ((chunk ^ (row & 7)) << 4);
}

__device__ __forceinline__ bool gbit(const GMask& gm, int i) {
    return (gm.w[i >> 5] >> (i & 31)) & 1u;
}

// ===========================================================================
// Projection GEMM via mma.sync bf16 hi/lo split, cp.async-pipelined.
// out[m][n] = X[m][:] . W[n][:] + b.  M=16384, N=128, K=1024.
// CTA: BM=128 x BN=128, 8 warps (m16 each), K-chunks of 64.
// SMEM: XH|XL|WH|WL bf16 ops 64K  +  fp32 stage XF|WF 64K = 128 KB.
// Pipeline: prefetch chunk t+1 raw fp32 while MMAs run on chunk t;
// convert stage->bf16 (SMEM->SMEM) after compute.
// Epilogue emits pre-split, pre-swizzled bf16 hi/lo tiles (g_bf).
// ===========================================================================
#define PROJ_SMEM 131072

__global__ __launch_bounds__(256)
void proj_mma_kernel(const float* __restrict__ xq, const float* __restrict__ xk, const float* __restrict__ xv,
                     const float* __restrict__ Wq, const float* __restrict__ bq,
                     const float* __restrict__ Wk, const float* __restrict__ bk,
                     const float* __restrict__ Wv, const float* __restrict__ bv)
{
    extern __shared__ char psm[];
    const uint32_t sb  = smem_to_u32(psm);
    const uint32_t sXH = sb;
    const uint32_t sXL = sb + 16384;
    const uint32_t sWH = sb + 32768;
    const uint32_t sWL = sb + 49152;
    const uint32_t sXF = sb + 65536;    // fp32 X stage, 32 KB, linear
    const uint32_t sWF = sb + 98304;    // fp32 W stage, 32 KB, linear

    const int proj = blockIdx.y;
    const float* X    = (proj == 0) ? xq : (proj == 1) ? xk : xv;
    const float* W    = (proj == 0) ? Wq : (proj == 1) ? Wk : Wv;
    const float* bias = (proj == 0) ? bq : (proj == 1) ? bk : bv;

    const int tid  = threadIdx.x;
    const int w    = tid >> 5;
    const int lane = tid & 31;
    const int g    = lane >> 2;
    const int tg   = lane & 3;
    const int g4   = lane >> 3;
    const int lr   = lane & 7;
    const int m0   = w * 16;
    const int mb   = blockIdx.x * 128;

    // issue cp.async for chunk kc's raw fp32 tiles into the stage
    auto prefetch = [&](int kc) {
        const int k0 = kc * 64;
        #pragma unroll
        for (int k = 0; k < 8; k++) {
            const int p   = tid * 4 + k * 1024;     // float index within 128x64 tile
            const int row = p >> 6, col = p & 63;
            const uint32_t doff = (uint32_t)(tid * 16 + k * 4096);
            CP_ASYNC16(sXF + doff, X + (size_t)(mb + row) * NDIN + k0 + col);
            CP_ASYNC16(sWF + doff, W + (size_t)row * NDIN + k0 + col);
        }
        CP_COMMIT();
    };

    // convert staged fp32 -> bf16 hi/lo swizzled operand buffers
    auto convert = [&]() {
        #pragma unroll
        for (int i = 0; i < 8; i++) {
            const uint32_t soff = (uint32_t)(tid * 16 + i * 4096);
            const int p   = tid * 4 + i * 1024;
            const int row = p >> 6, col = p & 63;
            const int ch8 = col >> 3, sub = (col >> 2) & 1;
            const uint32_t doff = (uint32_t)(row * 128 + ((ch8 ^ (row & 7)) << 4) + sub * 8);

            float4 xv = *(const float4*)(psm + 65536 + soff);
            float h0, l0, h1, l1, h2, l2, h3, l3;
            split2(xv.x, h0, l0); split2(xv.y, h1, l1);
            split2(xv.z, h2, l2); split2(xv.w, h3, l3);
            uint2 H, L;
            H.x = packbf(h0, h1); H.y = packbf(h2, h3);
            L.x = packbf(l0, l1); L.y = packbf(l2, l3);
            *(uint2*)(psm + (sXH - sb) + doff) = H;
            *(uint2*)(psm + (sXL - sb) + doff) = L;

            float4 wv = *(const float4*)(psm + 98304 + soff);
            split2(wv.x, h0, l0); split2(wv.y, h1, l1);
            split2(wv.z, h2, l2); split2(wv.w, h3, l3);
            H.x = packbf(h0, h1); H.y = packbf(h2, h3);
            L.x = packbf(l0, l1); L.y = packbf(l2, l3);
            *(uint2*)(psm + (sWH - sb) + doff) = H;
            *(uint2*)(psm + (sWL - sb) + doff) = L;
        }
    };

    float acc[16][4];
    #pragma unroll
    for (int j = 0; j < 16; j++)
        #pragma unroll
        for (int e = 0; e < 4; e++) acc[j][e] = 0.0f;

    // prolog: chunk 0
    prefetch(0);
    CP_WAIT0();
    __syncthreads();
    convert();
    __syncthreads();

    for (int kc = 0; kc < NDIN / 64; kc++) {
        if (kc + 1 < NDIN / 64) prefetch(kc + 1);

        // ---- acc += Xh*Wh + Xl*Wh + Xh*Wl  (m16 x n128 x k64 per warp) ----
        #pragma unroll
        for (int ks = 0; ks < 4; ks++) {
            uint32_t ah[4], al[4];
            const int arow = m0 + ((g4 & 1) << 3) + lr;
            const int ach  = 2 * ks + (g4 >> 1);
            LDSM_X4(ah, sXH + (uint32_t)(arow * 128 + ((ach ^ (arow & 7)) << 4)));
            LDSM_X4(al, sXL + (uint32_t)(arow * 128 + ((ach ^ (arow & 7)) << 4)));
            #pragma unroll
            for (int jp = 0; jp < 8; jp++) {
                uint32_t bh[4], bl[4];
                const int brow = 8 * (2 * jp + (g4 >> 1)) + lr;
                const int bch  = 2 * ks + (g4 & 1);
                LDSM_X4(bh, sWH + (uint32_t)(brow * 128 + ((bch ^ (brow & 7)) << 4)));
                LDSM_X4(bl, sWL + (uint32_t)(brow * 128 + ((bch ^ (brow & 7)) << 4)));
                MMA16816(acc[2 * jp],     ah, bh[0], bh[1]);
                MMA16816(acc[2 * jp + 1], ah, bh[2], bh[3]);
                MMA16816(acc[2 * jp],     al, bh[0], bh[1]);
                MMA16816(acc[2 * jp + 1], al, bh[2], bh[3]);
                MMA16816(acc[2 * jp],     ah, bl[0], bl[1]);
                MMA16816(acc[2 * jp + 1], ah, bl[2], bl[3]);
            }
        }

        if (kc + 1 < NDIN / 64) {
            CP_WAIT0();
            __syncthreads();     // all MMA reads of bf16 bufs done; stage landed
            convert();
            __syncthreads();
        }
    }

    // ---- epilogue: + bias -> bf16 hi/lo swizzled tiles ----
    const int r0   = mb + m0 + g;
    const int bb_  = mb / NS;
    const int s0   = r0 % NS;
    const int tile = s0 >> 6;
    const int rin0 = s0 & 63;
    const int rin1 = rin0 + 8;

    unsigned char* pH = (unsigned char*)g_bf[2 * proj][bb_][tile];
    unsigned char* pL = (unsigned char*)g_bf[2 * proj + 1][bb_][tile];

    #pragma unroll
    for (int j = 0; j < 16; j++) {
        const int c = 8 * j + 2 * tg;
        const float b0 = bias[c], b1 = bias[c + 1];
        const float x00 = acc[j][0] + b0, x01 = acc[j][1] + b1;
        const float x10 = acc[j][2] + b0, x11 = acc[j][3] + b1;

        float h, l, h2, l2;
        split2(x00, h, l); split2(x01, h2, l2);
        uint32_t off0 = (uint32_t)(rin0 * 256 + ((j ^ (rin0 & 7)) << 4) + tg * 4);
        *(uint32_t*)(pH + off0) = packbf(h, h2);
        *(uint32_t*)(pL + off0) = packbf(l, l2);

        split2(x10, h, l); split2(x11, h2, l2);
        uint32_t off1 = (uint32_t)(rin1 * 256 + ((j ^ (rin1 & 7)) << 4) + tg * 4);
        *(uint32_t*)(pH + off1) = packbf(h, h2);
        *(uint32_t*)(pL + off1) = packbf(l, l2);
    }
}

// ===========================================================================
// Flash attention: mma.sync bf16 hi/lo split, cp.async double-buffered tiles.
// (unchanged from R9)
// ===========================================================================
#define ATTN_SMEM 196608

__global__ __launch_bounds__(256)
void attn_mma_kernel(float* __restrict__ out, GMask gm)
{
    extern __shared__ char smem[];
    const uint32_t sb  = smem_to_u32(smem);
    const uint32_t sQH = sb;
    const uint32_t sQL = sb + 32768;

    const int tid  = threadIdx.x;
    const int w    = tid >> 5;
    const int lane = tid & 31;
    const int g    = lane >> 2;
    const int tg   = lane & 3;
    const int g4   = lane >> 3;
    const int lr   = lane & 7;
    const int b    = blockIdx.y;
    const int q0   = blockIdx.x * 128;
    const int m0   = w * 16;

    // ---- group 0: Q tiles (2x 64-row) via cp.async ----
    #pragma unroll
    for (int seg = 0; seg < 4; seg++) {         // QH0,QH1,QL0,QL1
        const uint4* src = g_bf[seg >> 1][b][blockIdx.x * 2 + (seg & 1)];
        const uint32_t d0 = sb + (uint32_t)seg * 16384 + (uint32_t)tid * 16;
        #pragma unroll
        for (int k = 0; k < 4; k++)
            CP_ASYNC16(d0 + (uint32_t)k * 4096, src + tid + k * 256);
    }
    CP_COMMIT();

    // ---- group 1: tile 0 K/V into buffer 0 ----
    {
        const uint32_t bufb = sb + 65536u;
        #pragma unroll
        for (int seg = 0; seg < 4; seg++) {     // KH,KL,VH,VL
            const uint4* src = g_bf[2 + seg][b][0];
            const uint32_t d0 = bufb + (uint32_t)seg * 16384 + (uint32_t)tid * 16;
            #pragma unroll
            for (int k = 0; k < 4; k++)
                CP_ASYNC16(d0 + (uint32_t)k * 4096, src + tid + k * 256);
        }
    }
    CP_COMMIT();

    const int r0a = q0 + m0 + g;
    const int r1a = r0a + 8;
    const bool rg0 = gbit(gm, r0a);
    const bool rg1 = gbit(gm, r1a);
    const float inv_scale = 0.08838834764831844f;   // 1/sqrt(128)

    float l0 = 0.0f, l1 = 0.0f;
    float O[16][4];
    #pragma unroll
    for (int j = 0; j < 16; j++)
        #pragma unroll
        for (int e = 0; e < 4; e++) O[j][e] = 0.0f;

    for (int t = 0; t < NS / 64; t++) {
        const int k0 = t * 64;

        // prefetch tile t+1 into the other buffer
        if (t + 1 < NS / 64) {
            const uint32_t bufb = sb + 65536u + (uint32_t)((t + 1) & 1) * 65536u;
            #pragma unroll
            for (int seg = 0; seg < 4; seg++) {
                const uint4* src = g_bf[2 + seg][b][t + 1];
                const uint32_t d0 = bufb + (uint32_t)seg * 16384 + (uint32_t)tid * 16;
                #pragma unroll
                for (int k = 0; k < 4; k++)
                    CP_ASYNC16(d0 + (uint32_t)k * 4096, src + tid + k * 256);
            }
            CP_COMMIT();
            CP_WAIT1();       // tile t (and Q) complete; t+1 may be in flight
        } else {
            CP_WAIT0();
        }
        __syncthreads();

        const uint32_t bufb = sb + 65536u + (uint32_t)(t & 1) * 65536u;
        const uint32_t sKH = bufb;
        const uint32_t sKL = bufb + 16384;
        const uint32_t sVH = bufb + 32768;
        const uint32_t sVL = bufb + 49152;

        float S[8][4];
        #pragma unroll
        for (int j = 0; j < 8; j++)
            #pragma unroll
            for (int e = 0; e < 4; e++) S[j][e] = 0.0f;

        #pragma unroll
        for (int ks = 0; ks < 8; ks++) {
            uint32_t ah[4], al[4];
            const int arow = m0 + ((g4 & 1) << 3) + lr;
            const int ach  = 2 * ks + (g4 >> 1);
            LDSM_X4(ah, swaddr(sQH, arow, ach));
            LDSM_X4(al, swaddr(sQL, arow, ach));
            #pragma unroll
            for (int jp = 0; jp < 4; jp++) {
                uint32_t bh[4], bl[4];
                const int brow = 8 * (2 * jp + (g4 >> 1)) + lr;
                const int bch  = 2 * ks + (g4 & 1);
                LDSM_X4(bh, swaddr(sKH, brow, bch));
                LDSM_X4(bl, swaddr(sKL, brow, bch));
                MMA16816(S[2 * jp],     ah, bh[0], bh[1]);
                MMA16816(S[2 * jp + 1], ah, bh[2], bh[3]);
                MMA16816(S[2 * jp],     al, bh[0], bh[1]);
                MMA16816(S[2 * jp + 1], al, bh[2], bh[3]);
                MMA16816(S[2 * jp],     ah, bl[0], bl[1]);
                MMA16816(S[2 * jp + 1], ah, bl[2], bl[3]);
            }
        }

        float rs0 = 0.0f, rs1 = 0.0f;
        #pragma unroll
        for (int j = 0; j < 8; j++) {
            const int cb = k0 + 8 * j + 2 * tg;
            const bool cg0 = gbit(gm, cb);
            const bool cg1 = gbit(gm, cb + 1);
            S[j][0] = (cg0 | rg0 | (cb     <= r0a)) ? __expf(S[j][0] * inv_scale) : 0.0f;
            S[j][1] = (cg1 | rg0 | (cb + 1 <= r0a)) ? __expf(S[j][1] * inv_scale) : 0.0f;
            S[j][2] = (cg0 | rg1 | (cb     <= r1a)) ? __expf(S[j][2] * inv_scale) : 0.0f;
            S[j][3] = (cg1 | rg1 | (cb + 1 <= r1a)) ? __expf(S[j][3] * inv_scale) : 0.0f;
            rs0 += S[j][0] + S[j][1];
            rs1 += S[j][2] + S[j][3];
        }
        rs0 += __shfl_xor_sync(0xffffffffu, rs0, 1);
        rs0 += __shfl_xor_sync(0xffffffffu, rs0, 2);
        rs1 += __shfl_xor_sync(0xffffffffu, rs1, 1);
        rs1 += __shfl_xor_sync(0xffffffffu, rs1, 2);
        l0 += rs0;
        l1 += rs1;

        #pragma unroll
        for (int ks = 0; ks < 4; ks++) {
            const float* c0 = S[2 * ks];
            const float* c1 = S[2 * ks + 1];
            uint32_t pah[4], pal[4];
            {
                float h, l, h2, l2;
                split2(c0[0], h, l); split2(c0[1], h2, l2);
                pah[0] = packbf(h, h2); pal[0] = packbf(l, l2);
                split2(c0[2], h, l); split2(c0[3], h2, l2);
                pah[1] = packbf(h, h2); pal[1] = packbf(l, l2);
                split2(c1[0], h, l); split2(c1[1], h2, l2);
                pah[2] = packbf(h, h2); pal[2] = packbf(l, l2);
                split2(c1[2], h, l); split2(c1[3], h2, l2);
                pah[3] = packbf(h, h2); pal[3] = packbf(l, l2);
            }
            #pragma unroll
            for (int jp = 0; jp < 8; jp++) {
                uint32_t bh[4], bl[4];
                const int brow = 16 * ks + ((g4 & 1) << 3) + lr;
                const int bch  = 2 * jp + (g4 >> 1);
                LDSM_X4_T(bh, swaddr(sVH, brow, bch));
                LDSM_X4_T(bl, swaddr(sVL, brow, bch));
                MMA16816(O[2 * jp],     pah, bh[0], bh[1]);
                MMA16816(O[2 * jp + 1], pah, bh[2], bh[3]);
                MMA16816(O[2 * jp],     pal, bh[0], bh[1]);
                MMA16816(O[2 * jp + 1], pal, bh[2], bh[3]);
                MMA16816(O[2 * jp],     pah, bl[0], bl[1]);
                MMA16816(O[2 * jp + 1], pah, bl[2], bl[3]);
            }
        }
        __syncthreads();   // all warps done with buf[t&1] before t+2 prefetch
    }

    const float inv0 = 1.0f / l0;
    const float inv1 = 1.0f / l1;
    float* o0 = out + ((size_t)b * NS + r0a) * ND;
    float* o1 = out + ((size_t)b * NS + r1a) * ND;
    #pragma unroll
    for (int j = 0; j < 16; j++) {
        const int c = 8 * j + 2 * tg;
        *(float2*)(o0 + c) = make_float2(O[j][0] * inv0, O[j][1] * inv0);
        *(float2*)(o1 + c) = make_float2(O[j][2] * inv1, O[j][3] * inv1);
    }
}

// ---------------------------------------------------------------------------
// Host: exact port of np.random.default_rng(0).choice(2048, 32, replace=False)
// ---------------------------------------------------------------------------
static void compute_global_mask(GMask* gm)
{
    const uint32_t INIT_A = 0x43b0d7e5u, MULT_A = 0x931e8875u;
    const uint32_t INIT_B = 0x8b51f9ddu, MULT_B = 0x58f38dedu;
    const uint32_t MIX_L  = 0xca01f9ddu, MIX_R  = 0x4973f715u;

    uint32_t hc = INIT_A;
    auto hashf = [&](uint32_t v) -> uint32_t {
        v ^= hc; hc *= MULT_A; v *= hc; v ^= v >> 16; return v;
    };
    auto mixf = [&](uint32_t x, uint32_t y) -> uint32_t {
        uint32_t r = MIX_L * x - MIX_R * y;
        r ^= r >> 16; return r;
    };

    uint32_t pool[4];
    for (int i = 0; i < 4; i++) pool[i] = hashf(0u);
    for (int s = 0; s < 4; s++)
        for (int d = 0; d < 4; d++)
            if (s != d)
                pool[d] = mixf(pool[d], hashf(pool[s]));

    uint32_t gw[8]; uint32_t hb = INIT_B;
    for (int i = 0; i < 8; i++) {
        uint32_t dv = pool[i & 3];
        dv ^= hb; hb *= MULT_B; dv *= hb; dv ^= dv >> 16;
        gw[i] = dv;
    }
    uint64_t v64[4];
    for (int k = 0; k < 4; k++)
        v64[k] = (uint64_t)gw[2 * k] | ((uint64_t)gw[2 * k + 1] << 32);

    typedef __uint128_t u128;
    const u128 MULT = ((u128)0x2360ed051fc65da4ULL << 64) | 0x4385df649fccf645ULL;
    u128 inc = ((((u128)v64[2] << 64) | v64[3]) << 1) | 1;
    u128 st  = 0;
    st = st * MULT + inc;
    st += ((u128)v64[0] << 64) | v64[1];
    st = st * MULT + inc;

    int have = 0; uint32_t cache = 0;
    auto n64 = [&]() -> uint64_t {
        st = st * MULT + inc;
        uint64_t hi = (uint64_t)(st >> 64), lo = (uint64_t)st;
        unsigned rot = (unsigned)(hi >> 58);
        uint64_t x = hi ^ lo;
        return rot ? ((x >> rot) | (x << (64 - rot))) : x;
    };
    auto n32 = [&]() -> uint32_t {
        if (have) { have = 0; return cache; }
        uint64_t u = n64();
        have = 1; cache = (uint32_t)(u >> 32);
        return (uint32_t)u;
    };

    bool chosen[NS] = {false};
    for (uint32_t j = NS - 32; j < NS; j++) {
        uint32_t rng_excl = j + 1;
        uint64_t m = (uint64_t)n32() * rng_excl;
        uint32_t leftover = (uint32_t)m;
        if (leftover < rng_excl) {
            uint32_t threshold = (0xFFFFFFFFu - j) % rng_excl;
            while (leftover < threshold) {
                m = (uint64_t)n32() * rng_excl;
                leftover = (uint32_t)m;
            }
        }
        uint32_t val = (uint32_t)(m >> 32);
        if (chosen[val]) val = j;
        chosen[val] = true;
    }

    for (int w = 0; w < NS / 32; w++) gm->w[w] = 0u;
    for (int i = 0; i < NS; i++)
        if (chosen[i]) gm->w[i >> 5] |= (1u << (i & 31));
}

extern "C" void kernel_launch(void* const* d_in, const int* in_sizes, int n_in,
                              void* d_out, int out_size)
{
    (void)in_sizes; (void)n_in; (void)out_size;
    GMask gm;
    compute_global_mask(&gm);

    cudaFuncSetAttribute(proj_mma_kernel, cudaFuncAttributeMaxDynamicSharedMemorySize, PROJ_SMEM);
    proj_mma_kernel<<<dim3(NB * NS / 128, 3), 256, PROJ_SMEM>>>(
        (const float*)d_in[0], (const float*)d_in[1], (const float*)d_in[2],
        (const float*)d_in[3], (const float*)d_in[4],
        (const float*)d_in[5], (const float*)d_in[6],
        (const float*)d_in[7], (const float*)d_in[8]);

    cudaFuncSetAttribute(attn_mma_kernel, cudaFuncAttributeMaxDynamicSharedMemorySize, ATTN_SMEM);
    attn_mma_kernel<<<dim3(NS / 128, NB), 256, ATTN_SMEM>>>((float*)d_out, gm);
}

// round 11
// speedup vs baseline: 2.0638x; 1.1027x over previous
#include <cuda_runtime.h>
#include <cuda_bf16.h>
#include <cstdint>

#define NB   8
#define NS   2048
#define NDIN 1024
#define ND   128

// bf16 hi/lo pre-swizzled 64-row tiles: [QH,QL,KH,KL,VH,VL][b][tile][16KB] = 24 MB
__device__ uint4 g_bf[6][NB][32][1024];

struct GMask { unsigned int w[NS / 32]; };   // 2048-bit global-token mask

// ===========================================================================
// Warp-MMA helpers (mma.sync / ldmatrix / cp.async — baseline PTX)
// ===========================================================================
__device__ __forceinline__ uint32_t smem_to_u32(const void* smem_ptr) {
    uint32_t addr;
    asm("{ .reg .u64 tmp; cvta.to.shared.u64 tmp, %1; cvt.u32.u64 %0, tmp; }"
        : "=r"(addr) : "l"(smem_ptr));
    return addr;
}

__device__ __forceinline__ uint32_t packbf(float lo, float hi) {
    uint32_t r;
    asm("cvt.rn.bf16x2.f32 %0, %1, %2;" : "=r"(r) : "f"(hi), "f"(lo));
    return r;
}

__device__ __forceinline__ void split2(float x, float& hf, float& lf) {
    __nv_bfloat16 h = __float2bfloat16_rn(x);
    hf = __bfloat162float(h);
    lf = x - hf;
}

#define LDSM_X4(r, addr) \
    asm volatile("ldmatrix.sync.aligned.m8n8.x4.shared.b16 {%0,%1,%2,%3}, [%4];" \
        : "=r"((r)[0]), "=r"((r)[1]), "=r"((r)[2]), "=r"((r)[3]) : "r"(addr))

#define LDSM_X4_T(r, addr) \
    asm volatile("ldmatrix.sync.aligned.m8n8.x4.trans.shared.b16 {%0,%1,%2,%3}, [%4];" \
        : "=r"((r)[0]), "=r"((r)[1]), "=r"((r)[2]), "=r"((r)[3]) : "r"(addr))

#define MMA16816(d, a, b0, b1) \
    asm("mma.sync.aligned.m16n8k16.row.col.f32.bf16.bf16.f32 " \
        "{%0,%1,%2,%3}, {%4,%5,%6,%7}, {%8,%9}, {%0,%1,%2,%3};" \
        : "+f"((d)[0]), "+f"((d)[1]), "+f"((d)[2]), "+f"((d)[3]) \
        : "r"((a)[0]), "r"((a)[1]), "r"((a)[2]), "r"((a)[3]), "r"(b0), "r"(b1))

#define CP_ASYNC16(dst_u32, src_ptr) \
    asm volatile("cp.async.cg.shared.global [%0], [%1], 16;" \
        :: "r"(dst_u32), "l"(src_ptr) : "memory")
#define CP_COMMIT()  asm volatile("cp.async.commit_group;" ::: "memory")
#define CP_WAIT0()   asm volatile("cp.async.wait_group 0;" ::: "memory")
#define CP_WAIT1()   asm volatile("cp.async.wait_group 1;" ::: "memory")

// Swizzled address, 256-byte row stride (128 bf16 per row)
__device__ __forceinline__ uint32_t swaddr(uint32_t base, int row, int chunk) {
    return base + row * 256 + ((chunk ^ (row & 7)) << 4);
}

__device__ __forceinline__ bool gbit(const GMask& gm, int i) {
    return (gm.w[i >> 5] >> (i & 31)) & 1u;
}

// ===========================================================================
// Projection GEMM: 512 threads, 16 warps. Warp w: rows (w&7)*16, cols (w>>3)*64.
// cp.async-pipelined fp32 stage -> bf16 hi/lo convert (as R10).
// SMEM: XH|XL|WH|WL 64K + fp32 stage XF|WF 64K = 128 KB.
// ===========================================================================
#define PROJ_SMEM 131072

__global__ __launch_bounds__(512)
void proj_mma_kernel(const float* __restrict__ xq, const float* __restrict__ xk, const float* __restrict__ xv,
                     const float* __restrict__ Wq, const float* __restrict__ bq,
                     const float* __restrict__ Wk, const float* __restrict__ bk,
                     const float* __restrict__ Wv, const float* __restrict__ bv)
{
    extern __shared__ char psm[];
    const uint32_t sb  = smem_to_u32(psm);
    const uint32_t sXH = sb;
    const uint32_t sXL = sb + 16384;
    const uint32_t sWH = sb + 32768;
    const uint32_t sWL = sb + 49152;
    const uint32_t sXF = sb + 65536;
    const uint32_t sWF = sb + 98304;

    const int proj = blockIdx.y;
    const float* X    = (proj == 0) ? xq : (proj == 1) ? xk : xv;
    const float* W    = (proj == 0) ? Wq : (proj == 1) ? Wk : Wv;
    const float* bias = (proj == 0) ? bq : (proj == 1) ? bk : bv;

    const int tid  = threadIdx.x;
    const int w    = tid >> 5;
    const int wm   = w & 7;
    const int ng   = w >> 3;
    const int lane = tid & 31;
    const int g    = lane >> 2;
    const int tg   = lane & 3;
    const int g4   = lane >> 3;
    const int lr   = lane & 7;
    const int m0   = wm * 16;
    const int co   = ng * 64;
    const int mb   = blockIdx.x * 128;

    auto prefetch = [&](int kc) {
        const int k0 = kc * 64;
        #pragma unroll
        for (int k = 0; k < 4; k++) {
            const int p4  = tid + k * 512;
            const int p   = p4 * 4;
            const int row = p >> 6, col = p & 63;
            const uint32_t doff = (uint32_t)(p4 * 16);
            CP_ASYNC16(sXF + doff, X + (size_t)(mb + row) * NDIN + k0 + col);
            CP_ASYNC16(sWF + doff, W + (size_t)row * NDIN + k0 + col);
        }
        CP_COMMIT();
    };

    auto convert = [&]() {
        #pragma unroll
        for (int i = 0; i < 4; i++) {
            const int p4  = tid + i * 512;
            const int p   = p4 * 4;
            const int row = p >> 6, col = p & 63;
            const int ch8 = col >> 3, sub = (col >> 2) & 1;
            const uint32_t soff = (uint32_t)(p4 * 16);
            const uint32_t doff = (uint32_t)(row * 128 + ((ch8 ^ (row & 7)) << 4) + sub * 8);

            float4 xv = *(const float4*)(psm + 65536 + soff);
            float h0, l0, h1, l1, h2, l2, h3, l3;
            split2(xv.x, h0, l0); split2(xv.y, h1, l1);
            split2(xv.z, h2, l2); split2(xv.w, h3, l3);
            uint2 H, L;
            H.x = packbf(h0, h1); H.y = packbf(h2, h3);
            L.x = packbf(l0, l1); L.y = packbf(l2, l3);
            *(uint2*)(psm + (sXH - sb) + doff) = H;
            *(uint2*)(psm + (sXL - sb) + doff) = L;

            float4 wv = *(const float4*)(psm + 98304 + soff);
            split2(wv.x, h0, l0); split2(wv.y, h1, l1);
            split2(wv.z, h2, l2); split2(wv.w, h3, l3);
            H.x = packbf(h0, h1); H.y = packbf(h2, h3);
            L.x = packbf(l0, l1); L.y = packbf(l2, l3);
            *(uint2*)(psm + (sWH - sb) + doff) = H;
            *(uint2*)(psm + (sWL - sb) + doff) = L;
        }
    };

    float acc[8][4];
    #pragma unroll
    for (int j = 0; j < 8; j++)
        #pragma unroll
        for (int e = 0; e < 4; e++) acc[j][e] = 0.0f;

    prefetch(0);
    CP_WAIT0();
    __syncthreads();
    convert();
    __syncthreads();

    for (int kc = 0; kc < NDIN / 64; kc++) {
        if (kc + 1 < NDIN / 64) prefetch(kc + 1);

        #pragma unroll
        for (int ks = 0; ks < 4; ks++) {
            uint32_t ah[4], al[4];
            const int arow = m0 + ((g4 & 1) << 3) + lr;
            const int ach  = 2 * ks + (g4 >> 1);
            LDSM_X4(ah, sXH + (uint32_t)(arow * 128 + ((ach ^ (arow & 7)) << 4)));
            LDSM_X4(al, sXL + (uint32_t)(arow * 128 + ((ach ^ (arow & 7)) << 4)));
            #pragma unroll
            for (int jp = 0; jp < 4; jp++) {
                uint32_t bh[4], bl[4];
                const int brow = co + 8 * (2 * jp + (g4 >> 1)) + lr;
                const int bch  = 2 * ks + (g4 & 1);
                LDSM_X4(bh, sWH + (uint32_t)(brow * 128 + ((bch ^ (brow & 7)) << 4)));
                LDSM_X4(bl, sWL + (uint32_t)(brow * 128 + ((bch ^ (brow & 7)) << 4)));
                MMA16816(acc[2 * jp],     ah, bh[0], bh[1]);
                MMA16816(acc[2 * jp + 1], ah, bh[2], bh[3]);
                MMA16816(acc[2 * jp],     al, bh[0], bh[1]);
                MMA16816(acc[2 * jp + 1], al, bh[2], bh[3]);
                MMA16816(acc[2 * jp],     ah, bl[0], bl[1]);
                MMA16816(acc[2 * jp + 1], ah, bl[2], bl[3]);
            }
        }

        if (kc + 1 < NDIN / 64) {
            CP_WAIT0();
            __syncthreads();
            convert();
            __syncthreads();
        }
    }

    // ---- epilogue: + bias -> bf16 hi/lo swizzled tiles ----
    const int r0   = mb + m0 + g;
    const int bb_  = mb / NS;
    const int s0   = r0 % NS;
    const int tile = s0 >> 6;
    const int rin0 = s0 & 63;
    const int rin1 = rin0 + 8;

    unsigned char* pH = (unsigned char*)g_bf[2 * proj][bb_][tile];
    unsigned char* pL = (unsigned char*)g_bf[2 * proj + 1][bb_][tile];

    #pragma unroll
    for (int j = 0; j < 8; j++) {
        const int c   = co + 8 * j + 2 * tg;
        const int chk = (c >> 3);
        const float b0 = bias[c], b1 = bias[c + 1];
        const float x00 = acc[j][0] + b0, x01 = acc[j][1] + b1;
        const float x10 = acc[j][2] + b0, x11 = acc[j][3] + b1;

        float h, l, h2, l2;
        split2(x00, h, l); split2(x01, h2, l2);
        uint32_t off0 = (uint32_t)(rin0 * 256 + ((chk ^ (rin0 & 7)) << 4) + tg * 4);
        *(uint32_t*)(pH + off0) = packbf(h, h2);
        *(uint32_t*)(pL + off0) = packbf(l, l2);

        split2(x10, h, l); split2(x11, h2, l2);
        uint32_t off1 = (uint32_t)(rin1 * 256 + ((chk ^ (rin1 & 7)) << 4) + tg * 4);
        *(uint32_t*)(pH + off1) = packbf(h, h2);
        *(uint32_t*)(pL + off1) = packbf(l, l2);
    }
}

// ===========================================================================
// Flash attention: 512 threads, 16 warps. Warp group ng=w>>3 owns key-cols
// ng*32 of each tile; partial l/O summed in epilogue via SMEM (Q region).
// cp.async double-buffered K/V. SMEM 192 KB.
// ===========================================================================
#define ATTN_SMEM 196608

__global__ __launch_bounds__(512)
void attn_mma_kernel(float* __restrict__ out, GMask gm)
{
    extern __shared__ char smem[];
    const uint32_t sb  = smem_to_u32(smem);
    const uint32_t sQH = sb;
    const uint32_t sQL = sb + 32768;

    const int tid  = threadIdx.x;
    const int w    = tid >> 5;
    const int wm   = w & 7;
    const int ng   = w >> 3;
    const int lane = tid & 31;
    const int g    = lane >> 2;
    const int tg   = lane & 3;
    const int g4   = lane >> 3;
    const int lr   = lane & 7;
    const int b    = blockIdx.y;
    const int q0   = blockIdx.x * 128;
    const int m0   = wm * 16;
    const int co   = ng * 32;

    // ---- group 0: Q tiles via cp.async ----
    #pragma unroll
    for (int seg = 0; seg < 4; seg++) {
        const uint4* src = g_bf[seg >> 1][b][blockIdx.x * 2 + (seg & 1)];
        const uint32_t d0 = sb + (uint32_t)seg * 16384 + (uint32_t)tid * 16;
        #pragma unroll
        for (int k = 0; k < 2; k++)
            CP_ASYNC16(d0 + (uint32_t)k * 8192, src + tid + k * 512);
    }
    CP_COMMIT();

    // ---- group 1: tile 0 K/V into buffer 0 ----
    {
        const uint32_t bufb = sb + 65536u;
        #pragma unroll
        for (int seg = 0; seg < 4; seg++) {
            const uint4* src = g_bf[2 + seg][b][0];
            const uint32_t d0 = bufb + (uint32_t)seg * 16384 + (uint32_t)tid * 16;
            #pragma unroll
            for (int k = 0; k < 2; k++)
                CP_ASYNC16(d0 + (uint32_t)k * 8192, src + tid + k * 512);
        }
    }
    CP_COMMIT();

    const int r0a = q0 + m0 + g;
    const int r1a = r0a + 8;
    const bool rg0 = gbit(gm, r0a);
    const bool rg1 = gbit(gm, r1a);
    const float inv_scale = 0.08838834764831844f;   // 1/sqrt(128)

    float l0 = 0.0f, l1 = 0.0f;
    float O[16][4];
    #pragma unroll
    for (int j = 0; j < 16; j++)
        #pragma unroll
        for (int e = 0; e < 4; e++) O[j][e] = 0.0f;

    for (int t = 0; t < NS / 64; t++) {
        const int k0 = t * 64;

        if (t + 1 < NS / 64) {
            const uint32_t bufb = sb + 65536u + (uint32_t)((t + 1) & 1) * 65536u;
            #pragma unroll
            for (int seg = 0; seg < 4; seg++) {
                const uint4* src = g_bf[2 + seg][b][t + 1];
                const uint32_t d0 = bufb + (uint32_t)seg * 16384 + (uint32_t)tid * 16;
                #pragma unroll
                for (int k = 0; k < 2; k++)
                    CP_ASYNC16(d0 + (uint32_t)k * 8192, src + tid + k * 512);
            }
            CP_COMMIT();
            CP_WAIT1();
        } else {
            CP_WAIT0();
        }
        __syncthreads();

        const uint32_t bufb = sb + 65536u + (uint32_t)(t & 1) * 65536u;
        const uint32_t sKH = bufb;
        const uint32_t sKL = bufb + 16384;
        const uint32_t sVH = bufb + 32768;
        const uint32_t sVL = bufb + 49152;

        // ---- S = Q K^T over this group's 32 key cols ----
        float S[4][4];
        #pragma unroll
        for (int j = 0; j < 4; j++)
            #pragma unroll
            for (int e = 0; e < 4; e++) S[j][e] = 0.0f;

        #pragma unroll
        for (int ks = 0; ks < 8; ks++) {
            uint32_t ah[4], al[4];
            const int arow = m0 + ((g4 & 1) << 3) + lr;
            const int ach  = 2 * ks + (g4 >> 1);
            LDSM_X4(ah, swaddr(sQH, arow, ach));
            LDSM_X4(al, swaddr(sQL, arow, ach));
            #pragma unroll
            for (int jp = 0; jp < 2; jp++) {
                uint32_t bh[4], bl[4];
                const int brow = co + 8 * (2 * jp + (g4 >> 1)) + lr;
                const int bch  = 2 * ks + (g4 & 1);
                LDSM_X4(bh, swaddr(sKH, brow, bch));
                LDSM_X4(bl, swaddr(sKL, brow, bch));
                MMA16816(S[2 * jp],     ah, bh[0], bh[1]);
                MMA16816(S[2 * jp + 1], ah, bh[2], bh[3]);
                MMA16816(S[2 * jp],     al, bh[0], bh[1]);
                MMA16816(S[2 * jp + 1], al, bh[2], bh[3]);
                MMA16816(S[2 * jp],     ah, bl[0], bl[1]);
                MMA16816(S[2 * jp + 1], ah, bl[2], bl[3]);
            }
        }

        // ---- masked exp + partial row sums ----
        float rs0 = 0.0f, rs1 = 0.0f;
        #pragma unroll
        for (int j = 0; j < 4; j++) {
            const int cb = k0 + co + 8 * j + 2 * tg;
            const bool cg0 = gbit(gm, cb);
            const bool cg1 = gbit(gm, cb + 1);
            S[j][0] = (cg0 | rg0 | (cb     <= r0a)) ? __expf(S[j][0] * inv_scale) : 0.0f;
            S[j][1] = (cg1 | rg0 | (cb + 1 <= r0a)) ? __expf(S[j][1] * inv_scale) : 0.0f;
            S[j][2] = (cg0 | rg1 | (cb     <= r1a)) ? __expf(S[j][2] * inv_scale) : 0.0f;
            S[j][3] = (cg1 | rg1 | (cb + 1 <= r1a)) ? __expf(S[j][3] * inv_scale) : 0.0f;
            rs0 += S[j][0] + S[j][1];
            rs1 += S[j][2] + S[j][3];
        }
        rs0 += __shfl_xor_sync(0xffffffffu, rs0, 1);
        rs0 += __shfl_xor_sync(0xffffffffu, rs0, 2);
        rs1 += __shfl_xor_sync(0xffffffffu, rs1, 1);
        rs1 += __shfl_xor_sync(0xffffffffu, rs1, 2);
        l0 += rs0;
        l1 += rs1;

        // ---- O += P V over this group's 32 keys ----
        #pragma unroll
        for (int ks = 0; ks < 2; ks++) {
            const float* c0 = S[2 * ks];
            const float* c1 = S[2 * ks + 1];
            uint32_t pah[4], pal[4];
            {
                float h, l, h2, l2;
                split2(c0[0], h, l); split2(c0[1], h2, l2);
                pah[0] = packbf(h, h2); pal[0] = packbf(l, l2);
                split2(c0[2], h, l); split2(c0[3], h2, l2);
                pah[1] = packbf(h, h2); pal[1] = packbf(l, l2);
                split2(c1[0], h, l); split2(c1[1], h2, l2);
                pah[2] = packbf(h, h2); pal[2] = packbf(l, l2);
                split2(c1[2], h, l); split2(c1[3], h2, l2);
                pah[3] = packbf(h, h2); pal[3] = packbf(l, l2);
            }
            #pragma unroll
            for (int jp = 0; jp < 8; jp++) {
                uint32_t bh[4], bl[4];
                const int brow = co + 16 * ks + ((g4 & 1) << 3) + lr;
                const int bch  = 2 * jp + (g4 >> 1);
                LDSM_X4_T(bh, swaddr(sVH, brow, bch));
                LDSM_X4_T(bl, swaddr(sVL, brow, bch));
                MMA16816(O[2 * jp],     pah, bh[0], bh[1]);
                MMA16816(O[2 * jp + 1], pah, bh[2], bh[3]);
                MMA16816(O[2 * jp],     pal, bh[0], bh[1]);
                MMA16816(O[2 * jp + 1], pal, bh[2], bh[3]);
                MMA16816(O[2 * jp],     pah, bl[0], bl[1]);
                MMA16816(O[2 * jp + 1], pah, bl[2], bl[3]);
            }
        }
        __syncthreads();
    }

    // ---- cross-group reduction (Q region is dead now) ----
    float* lsm = (float*)(smem + 65536);    // buffer-0 region start, dead
    if (ng == 1) {
        float* ob = (float*)(smem + wm * 8192);
        #pragma unroll
        for (int j = 0; j < 16; j++) {
            const int c = 8 * j + 2 * tg;
            *(float2*)(ob + g * 128 + c)       = make_float2(O[j][0], O[j][1]);
            *(float2*)(ob + (g + 8) * 128 + c) = make_float2(O[j][2], O[j][3]);
        }
        lsm[wm * 16 + g]     = l0;
        lsm[wm * 16 + g + 8] = l1;
    }
    __syncthreads();
    if (ng == 0) {
        const float* ob = (const float*)(smem + wm * 8192);
        l0 += lsm[wm * 16 + g];
        l1 += lsm[wm * 16 + g + 8];
        const float inv0 = 1.0f / l0;
        const float inv1 = 1.0f / l1;
        float* o0 = out + ((size_t)b * NS + r0a) * ND;
        float* o1 = out + ((size_t)b * NS + r1a) * ND;
        #pragma unroll
        for (int j = 0; j < 16; j++) {
            const int c = 8 * j + 2 * tg;
            float2 p0 = *(const float2*)(ob + g * 128 + c);
            float2 p1 = *(const float2*)(ob + (g + 8) * 128 + c);
            *(float2*)(o0 + c) = make_float2((O[j][0] + p0.x) * inv0, (O[j][1] + p0.y) * inv0);
            *(float2*)(o1 + c) = make_float2((O[j][2] + p1.x) * inv1, (O[j][3] + p1.y) * inv1);
        }
    }
}

// ---------------------------------------------------------------------------
// Host: exact port of np.random.default_rng(0).choice(2048, 32, replace=False)
// ---------------------------------------------------------------------------
static void compute_global_mask(GMask* gm)
{
    const uint32_t INIT_A = 0x43b0d7e5u, MULT_A = 0x931e8875u;
    const uint32_t INIT_B = 0x8b51f9ddu, MULT_B = 0x58f38dedu;
    const uint32_t MIX_L  = 0xca01f9ddu, MIX_R  = 0x4973f715u;

    uint32_t hc = INIT_A;
    auto hashf = [&](uint32_t v) -> uint32_t {
        v ^= hc; hc *= MULT_A; v *= hc; v ^= v >> 16; return v;
    };
    auto mixf = [&](uint32_t x, uint32_t y) -> uint32_t {
        uint32_t r = MIX_L * x - MIX_R * y;
        r ^= r >> 16; return r;
    };

    uint32_t pool[4];
    for (int i = 0; i < 4; i++) pool[i] = hashf(0u);
    for (int s = 0; s < 4; s++)
        for (int d = 0; d < 4; d++)
            if (s != d)
                pool[d] = mixf(pool[d], hashf(pool[s]));

    uint32_t gw[8]; uint32_t hb = INIT_B;
    for (int i = 0; i < 8; i++) {
        uint32_t dv = pool[i & 3];
        dv ^= hb; hb *= MULT_B; dv *= hb; dv ^= dv >> 16;
        gw[i] = dv;
    }
    uint64_t v64[4];
    for (int k = 0; k < 4; k++)
        v64[k] = (uint64_t)gw[2 * k] | ((uint64_t)gw[2 * k + 1] << 32);

    typedef __uint128_t u128;
    const u128 MULT = ((u128)0x2360ed051fc65da4ULL << 64) | 0x4385df649fccf645ULL;
    u128 inc = ((((u128)v64[2] << 64) | v64[3]) << 1) | 1;
    u128 st  = 0;
    st = st * MULT + inc;
    st += ((u128)v64[0] << 64) | v64[1];
    st = st * MULT + inc;

    int have = 0; uint32_t cache = 0;
    auto n64 = [&]() -> uint64_t {
        st = st * MULT + inc;
        uint64_t hi = (uint64_t)(st >> 64), lo = (uint64_t)st;
        unsigned rot = (unsigned)(hi >> 58);
        uint64_t x = hi ^ lo;
        return rot ? ((x >> rot) | (x << (64 - rot))) : x;
    };
    auto n32 = [&]() -> uint32_t {
        if (have) { have = 0; return cache; }
        uint64_t u = n64();
        have = 1; cache = (uint32_t)(u >> 32);
        return (uint32_t)u;
    };

    bool chosen[NS] = {false};
    for (uint32_t j = NS - 32; j < NS; j++) {
        uint32_t rng_excl = j + 1;
        uint64_t m = (uint64_t)n32() * rng_excl;
        uint32_t leftover = (uint32_t)m;
        if (leftover < rng_excl) {
            uint32_t threshold = (0xFFFFFFFFu - j) % rng_excl;
            while (leftover < threshold) {
                m = (uint64_t)n32() * rng_excl;
                leftover = (uint32_t)m;
            }
        }
        uint32_t val = (uint32_t)(m >> 32);
        if (chosen[val]) val = j;
        chosen[val] = true;
    }

    for (int w = 0; w < NS / 32; w++) gm->w[w] = 0u;
    for (int i = 0; i < NS; i++)
        if (chosen[i]) gm->w[i >> 5] |= (1u << (i & 31));
}

extern "C" void kernel_launch(void* const* d_in, const int* in_sizes, int n_in,
                              void* d_out, int out_size)
{
    (void)in_sizes; (void)n_in; (void)out_size;
    GMask gm;
    compute_global_mask(&gm);

    cudaFuncSetAttribute(proj_mma_kernel, cudaFuncAttributeMaxDynamicSharedMemorySize, PROJ_SMEM);
    proj_mma_kernel<<<dim3(NB * NS / 128, 3), 512, PROJ_SMEM>>>(
        (const float*)d_in[0], (const float*)d_in[1], (const float*)d_in[2],
        (const float*)d_in[3], (const float*)d_in[4],
        (const float*)d_in[5], (const float*)d_in[6],
        (const float*)d_in[7], (const float*)d_in[8]);

    cudaFuncSetAttribute(attn_mma_kernel, cudaFuncAttributeMaxDynamicSharedMemorySize, ATTN_SMEM);
    attn_mma_kernel<<<dim3(NS / 128, NB), 512, ATTN_SMEM>>>((float*)d_out, gm);
}

// round 12
// speedup vs baseline: 2.0890x; 1.0122x over previous
#include <cuda_runtime.h>
#include <cuda_bf16.h>
#include <cstdint>

#define NB   8
#define NS   2048
#define NDIN 1024
#define ND   128

// bf16 hi/lo pre-swizzled 64-row tiles: [QH,QL,KH,KL,VH,VL][b][tile][16KB] = 24 MB
__device__ uint4 g_bf[6][NB][32][1024];

struct GMask { unsigned int w[NS / 32]; };   // 2048-bit global-token mask

// ===========================================================================
// Warp-MMA helpers (mma.sync / ldmatrix / cp.async — baseline PTX)
// ===========================================================================
__device__ __forceinline__ uint32_t smem_to_u32(const void* smem_ptr) {
    uint32_t addr;
    asm("{ .reg .u64 tmp; cvta.to.shared.u64 tmp, %1; cvt.u32.u64 %0, tmp; }"
        : "=r"(addr) : "l"(smem_ptr));
    return addr;
}

__device__ __forceinline__ uint32_t packbf(float lo, float hi) {
    uint32_t r;
    asm("cvt.rn.bf16x2.f32 %0, %1, %2;" : "=r"(r) : "f"(hi), "f"(lo));
    return r;
}

// pack hi-halves of two fp32 as bf16x2 (truncation split, exact hi): 1 PRMT
__device__ __forceinline__ uint32_t prmt_hi(uint32_t a, uint32_t b) {
    uint32_t d;
    asm("prmt.b32 %0, %1, %2, 0x7632;" : "=r"(d) : "r"(a), "r"(b));
    return d;
}
// lo residue of truncation split
__device__ __forceinline__ float trunc_lo(float x, uint32_t xb) {
    return x - __uint_as_float(xb & 0xFFFF0000u);
}

#define LDSM_X4(r, addr) \
    asm volatile("ldmatrix.sync.aligned.m8n8.x4.shared.b16 {%0,%1,%2,%3}, [%4];" \
        : "=r"((r)[0]), "=r"((r)[1]), "=r"((r)[2]), "=r"((r)[3]) : "r"(addr))

#define LDSM_X4_T(r, addr) \
    asm volatile("ldmatrix.sync.aligned.m8n8.x4.trans.shared.b16 {%0,%1,%2,%3}, [%4];" \
        : "=r"((r)[0]), "=r"((r)[1]), "=r"((r)[2]), "=r"((r)[3]) : "r"(addr))

#define MMA16816(d, a, b0, b1) \
    asm("mma.sync.aligned.m16n8k16.row.col.f32.bf16.bf16.f32 " \
        "{%0,%1,%2,%3}, {%4,%5,%6,%7}, {%8,%9}, {%0,%1,%2,%3};" \
        : "+f"((d)[0]), "+f"((d)[1]), "+f"((d)[2]), "+f"((d)[3]) \
        : "r"((a)[0]), "r"((a)[1]), "r"((a)[2]), "r"((a)[3]), "r"(b0), "r"(b1))

#define CP_ASYNC16(dst_u32, src_ptr) \
    asm volatile("cp.async.cg.shared.global [%0], [%1], 16;" \
        :: "r"(dst_u32), "l"(src_ptr) : "memory")
#define CP_COMMIT()  asm volatile("cp.async.commit_group;" ::: "memory")
#define CP_WAIT0()   asm volatile("cp.async.wait_group 0;" ::: "memory")
#define CP_WAIT1()   asm volatile("cp.async.wait_group 1;" ::: "memory")

// Swizzled address, 256-byte row stride (128 bf16 per row)
__device__ __forceinline__ uint32_t swaddr(uint32_t base, int row, int chunk) {
    return base + row * 256 + ((chunk ^ (row & 7)) << 4);
}

__device__ __forceinline__ bool gbit(const GMask& gm, int i) {
    return (gm.w[i >> 5] >> (i & 31)) & 1u;
}

// truncation-split repack of a C-fragment pair (c0[4], c1[4]) -> A-frags hi/lo
__device__ __forceinline__ void repack_frag(const float* c0, const float* c1,
                                            uint32_t* pah, uint32_t* pal) {
    uint32_t a0 = __float_as_uint(c0[0]), a1 = __float_as_uint(c0[1]);
    uint32_t a2 = __float_as_uint(c0[2]), a3 = __float_as_uint(c0[3]);
    uint32_t b0 = __float_as_uint(c1[0]), b1 = __float_as_uint(c1[1]);
    uint32_t b2 = __float_as_uint(c1[2]), b3 = __float_as_uint(c1[3]);
    pah[0] = prmt_hi(a0, a1);
    pah[1] = prmt_hi(a2, a3);
    pah[2] = prmt_hi(b0, b1);
    pah[3] = prmt_hi(b2, b3);
    pal[0] = packbf(trunc_lo(c0[0], a0), trunc_lo(c0[1], a1));
    pal[1] = packbf(trunc_lo(c0[2], a2), trunc_lo(c0[3], a3));
    pal[2] = packbf(trunc_lo(c1[0], b0), trunc_lo(c1[1], b1));
    pal[3] = packbf(trunc_lo(c1[2], b2), trunc_lo(c1[3], b3));
}

// ===========================================================================
// Projection GEMM: 512 threads, 16 warps. Warp w: rows (w&7)*16, cols (w>>3)*64.
// cp.async-pipelined fp32 stage -> bf16 hi/lo convert (truncation split).
// SMEM: XH|XL|WH|WL 64K + fp32 stage XF|WF 64K = 128 KB.
// ===========================================================================
#define PROJ_SMEM 131072

__global__ __launch_bounds__(512)
void proj_mma_kernel(const float* __restrict__ xq, const float* __restrict__ xk, const float* __restrict__ xv,
                     const float* __restrict__ Wq, const float* __restrict__ bq,
                     const float* __restrict__ Wk, const float* __restrict__ bk,
                     const float* __restrict__ Wv, const float* __restrict__ bv)
{
    extern __shared__ char psm[];
    const uint32_t sb  = smem_to_u32(psm);
    const uint32_t sXH = sb;
    const uint32_t sXL = sb + 16384;
    const uint32_t sWH = sb + 32768;
    const uint32_t sWL = sb + 49152;
    const uint32_t sXF = sb + 65536;
    const uint32_t sWF = sb + 98304;

    const int proj = blockIdx.y;
    const float* X    = (proj == 0) ? xq : (proj == 1) ? xk : xv;
    const float* W    = (proj == 0) ? Wq : (proj == 1) ? Wk : Wv;
    const float* bias = (proj == 0) ? bq : (proj == 1) ? bk : bv;

    const int tid  = threadIdx.x;
    const int w    = tid >> 5;
    const int wm   = w & 7;
    const int ng   = w >> 3;
    const int lane = tid & 31;
    const int g    = lane >> 2;
    const int tg   = lane & 3;
    const int g4   = lane >> 3;
    const int lr   = lane & 7;
    const int m0   = wm * 16;
    const int co   = ng * 64;
    const int mb   = blockIdx.x * 128;

    auto prefetch = [&](int kc) {
        const int k0 = kc * 64;
        #pragma unroll
        for (int k = 0; k < 4; k++) {
            const int p4  = tid + k * 512;
            const int p   = p4 * 4;
            const int row = p >> 6, col = p & 63;
            const uint32_t doff = (uint32_t)(p4 * 16);
            CP_ASYNC16(sXF + doff, X + (size_t)(mb + row) * NDIN + k0 + col);
            CP_ASYNC16(sWF + doff, W + (size_t)row * NDIN + k0 + col);
        }
        CP_COMMIT();
    };

    auto convert = [&]() {
        #pragma unroll
        for (int i = 0; i < 4; i++) {
            const int p4  = tid + i * 512;
            const int p   = p4 * 4;
            const int row = p >> 6, col = p & 63;
            const int ch8 = col >> 3, sub = (col >> 2) & 1;
            const uint32_t soff = (uint32_t)(p4 * 16);
            const uint32_t doff = (uint32_t)(row * 128 + ((ch8 ^ (row & 7)) << 4) + sub * 8);

            float4 xv = *(const float4*)(psm + 65536 + soff);
            uint32_t xb0 = __float_as_uint(xv.x), xb1 = __float_as_uint(xv.y);
            uint32_t xb2 = __float_as_uint(xv.z), xb3 = __float_as_uint(xv.w);
            uint2 H, L;
            H.x = prmt_hi(xb0, xb1); H.y = prmt_hi(xb2, xb3);
            L.x = packbf(trunc_lo(xv.x, xb0), trunc_lo(xv.y, xb1));
            L.y = packbf(trunc_lo(xv.z, xb2), trunc_lo(xv.w, xb3));
            *(uint2*)(psm + (sXH - sb) + doff) = H;
            *(uint2*)(psm + (sXL - sb) + doff) = L;

            float4 wv = *(const float4*)(psm + 98304 + soff);
            uint32_t wb0 = __float_as_uint(wv.x), wb1 = __float_as_uint(wv.y);
            uint32_t wb2 = __float_as_uint(wv.z), wb3 = __float_as_uint(wv.w);
            H.x = prmt_hi(wb0, wb1); H.y = prmt_hi(wb2, wb3);
            L.x = packbf(trunc_lo(wv.x, wb0), trunc_lo(wv.y, wb1));
            L.y = packbf(trunc_lo(wv.z, wb2), trunc_lo(wv.w, wb3));
            *(uint2*)(psm + (sWH - sb) + doff) = H;
            *(uint2*)(psm + (sWL - sb) + doff) = L;
        }
    };

    float acc[8][4];
    #pragma unroll
    for (int j = 0; j < 8; j++)
        #pragma unroll
        for (int e = 0; e < 4; e++) acc[j][e] = 0.0f;

    prefetch(0);
    CP_WAIT0();
    __syncthreads();
    convert();
    __syncthreads();

    for (int kc = 0; kc < NDIN / 64; kc++) {
        if (kc + 1 < NDIN / 64) prefetch(kc + 1);

        #pragma unroll
        for (int ks = 0; ks < 4; ks++) {
            uint32_t ah[4], al[4];
            const int arow = m0 + ((g4 & 1) << 3) + lr;
            const int ach  = 2 * ks + (g4 >> 1);
            LDSM_X4(ah, sXH + (uint32_t)(arow * 128 + ((ach ^ (arow & 7)) << 4)));
            LDSM_X4(al, sXL + (uint32_t)(arow * 128 + ((ach ^ (arow & 7)) << 4)));
            #pragma unroll
            for (int jp = 0; jp < 4; jp++) {
                uint32_t bh[4], bl[4];
                const int brow = co + 8 * (2 * jp + (g4 >> 1)) + lr;
                const int bch  = 2 * ks + (g4 & 1);
                LDSM_X4(bh, sWH + (uint32_t)(brow * 128 + ((bch ^ (brow & 7)) << 4)));
                LDSM_X4(bl, sWL + (uint32_t)(brow * 128 + ((bch ^ (brow & 7)) << 4)));
                MMA16816(acc[2 * jp],     ah, bh[0], bh[1]);
                MMA16816(acc[2 * jp + 1], ah, bh[2], bh[3]);
                MMA16816(acc[2 * jp],     al, bh[0], bh[1]);
                MMA16816(acc[2 * jp + 1], al, bh[2], bh[3]);
                MMA16816(acc[2 * jp],     ah, bl[0], bl[1]);
                MMA16816(acc[2 * jp + 1], ah, bl[2], bl[3]);
            }
        }

        if (kc + 1 < NDIN / 64) {
            CP_WAIT0();
            __syncthreads();
            convert();
            __syncthreads();
        }
    }

    // ---- epilogue: + bias -> bf16 hi/lo swizzled tiles ----
    const int r0   = mb + m0 + g;
    const int bb_  = mb / NS;
    const int s0   = r0 % NS;
    const int tile = s0 >> 6;
    const int rin0 = s0 & 63;
    const int rin1 = rin0 + 8;

    unsigned char* pH = (unsigned char*)g_bf[2 * proj][bb_][tile];
    unsigned char* pL = (unsigned char*)g_bf[2 * proj + 1][bb_][tile];

    #pragma unroll
    for (int j = 0; j < 8; j++) {
        const int c   = co + 8 * j + 2 * tg;
        const int chk = (c >> 3);
        const float b0 = bias[c], b1 = bias[c + 1];
        const float x00 = acc[j][0] + b0, x01 = acc[j][1] + b1;
        const float x10 = acc[j][2] + b0, x11 = acc[j][3] + b1;

        uint32_t u00 = __float_as_uint(x00), u01 = __float_as_uint(x01);
        uint32_t off0 = (uint32_t)(rin0 * 256 + ((chk ^ (rin0 & 7)) << 4) + tg * 4);
        *(uint32_t*)(pH + off0) = prmt_hi(u00, u01);
        *(uint32_t*)(pL + off0) = packbf(trunc_lo(x00, u00), trunc_lo(x01, u01));

        uint32_t u10 = __float_as_uint(x10), u11 = __float_as_uint(x11);
        uint32_t off1 = (uint32_t)(rin1 * 256 + ((chk ^ (rin1 & 7)) << 4) + tg * 4);
        *(uint32_t*)(pH + off1) = prmt_hi(u10, u11);
        *(uint32_t*)(pL + off1) = packbf(trunc_lo(x10, u10), trunc_lo(x11, u11));
    }
}

// ===========================================================================
// Flash attention: 512 threads, 16 warps. Warp group ng=w>>3 owns key-cols
// ng*32 of each tile; partial l/O summed in epilogue via SMEM.
// cp.async double-buffered K/V. SMEM 192 KB.
// R12: deferred l-shuffles, truncation-split repack, fully-causal fast path.
// ===========================================================================
#define ATTN_SMEM 196608

__global__ __launch_bounds__(512)
void attn_mma_kernel(float* __restrict__ out, GMask gm)
{
    extern __shared__ char smem[];
    const uint32_t sb  = smem_to_u32(smem);
    const uint32_t sQH = sb;
    const uint32_t sQL = sb + 32768;

    const int tid  = threadIdx.x;
    const int w    = tid >> 5;
    const int wm   = w & 7;
    const int ng   = w >> 3;
    const int lane = tid & 31;
    const int g    = lane >> 2;
    const int tg   = lane & 3;
    const int g4   = lane >> 3;
    const int lr   = lane & 7;
    const int b    = blockIdx.y;
    const int q0   = blockIdx.x * 128;
    const int m0   = wm * 16;
    const int co   = ng * 32;

    // ---- group 0: Q tiles via cp.async ----
    #pragma unroll
    for (int seg = 0; seg < 4; seg++) {
        const uint4* src = g_bf[seg >> 1][b][blockIdx.x * 2 + (seg & 1)];
        const uint32_t d0 = sb + (uint32_t)seg * 16384 + (uint32_t)tid * 16;
        #pragma unroll
        for (int k = 0; k < 2; k++)
            CP_ASYNC16(d0 + (uint32_t)k * 8192, src + tid + k * 512);
    }
    CP_COMMIT();

    // ---- group 1: tile 0 K/V into buffer 0 ----
    {
        const uint32_t bufb = sb + 65536u;
        #pragma unroll
        for (int seg = 0; seg < 4; seg++) {
            const uint4* src = g_bf[2 + seg][b][0];
            const uint32_t d0 = bufb + (uint32_t)seg * 16384 + (uint32_t)tid * 16;
            #pragma unroll
            for (int k = 0; k < 2; k++)
                CP_ASYNC16(d0 + (uint32_t)k * 8192, src + tid + k * 512);
        }
    }
    CP_COMMIT();

    const int r0a = q0 + m0 + g;
    const int r1a = r0a + 8;
    const bool rg0 = gbit(gm, r0a);
    const bool rg1 = gbit(gm, r1a);
    const float inv_scale = 0.08838834764831844f;   // 1/sqrt(128)

    float l0 = 0.0f, l1 = 0.0f;
    float O[16][4];
    #pragma unroll
    for (int j = 0; j < 16; j++)
        #pragma unroll
        for (int e = 0; e < 4; e++) O[j][e] = 0.0f;

    for (int t = 0; t < NS / 64; t++) {
        const int k0 = t * 64;

        if (t + 1 < NS / 64) {
            const uint32_t bufb = sb + 65536u + (uint32_t)((t + 1) & 1) * 65536u;
            #pragma unroll
            for (int seg = 0; seg < 4; seg++) {
                const uint4* src = g_bf[2 + seg][b][t + 1];
                const uint32_t d0 = bufb + (uint32_t)seg * 16384 + (uint32_t)tid * 16;
                #pragma unroll
                for (int k = 0; k < 2; k++)
                    CP_ASYNC16(d0 + (uint32_t)k * 8192, src + tid + k * 512);
            }
            CP_COMMIT();
            CP_WAIT1();
        } else {
            CP_WAIT0();
        }
        __syncthreads();

        const uint32_t bufb = sb + 65536u + (uint32_t)(t & 1) * 65536u;
        const uint32_t sKH = bufb;
        const uint32_t sKL = bufb + 16384;
        const uint32_t sVH = bufb + 32768;
        const uint32_t sVL = bufb + 49152;

        // ---- S = Q K^T over this group's 32 key cols ----
        float S[4][4];
        #pragma unroll
        for (int j = 0; j < 4; j++)
            #pragma unroll
            for (int e = 0; e < 4; e++) S[j][e] = 0.0f;

        #pragma unroll
        for (int ks = 0; ks < 8; ks++) {
            uint32_t ah[4], al[4];
            const int arow = m0 + ((g4 & 1) << 3) + lr;
            const int ach  = 2 * ks + (g4 >> 1);
            LDSM_X4(ah, swaddr(sQH, arow, ach));
            LDSM_X4(al, swaddr(sQL, arow, ach));
            #pragma unroll
            for (int jp = 0; jp < 2; jp++) {
                uint32_t bh[4], bl[4];
                const int brow = co + 8 * (2 * jp + (g4 >> 1)) + lr;
                const int bch  = 2 * ks + (g4 & 1);
                LDSM_X4(bh, swaddr(sKH, brow, bch));
                LDSM_X4(bl, swaddr(sKL, brow, bch));
                MMA16816(S[2 * jp],     ah, bh[0], bh[1]);
                MMA16816(S[2 * jp + 1], ah, bh[2], bh[3]);
                MMA16816(S[2 * jp],     al, bh[0], bh[1]);
                MMA16816(S[2 * jp + 1], al, bh[2], bh[3]);
                MMA16816(S[2 * jp],     ah, bl[0], bl[1]);
                MMA16816(S[2 * jp + 1], ah, bl[2], bl[3]);
            }
        }

        // ---- masked exp + per-thread partial row sums (no shuffles here) ----
        if (k0 + 63 <= q0 + m0) {
            // fully-causal tile for every (row, col) this warp owns
            #pragma unroll
            for (int j = 0; j < 4; j++) {
                S[j][0] = __expf(S[j][0] * inv_scale);
                S[j][1] = __expf(S[j][1] * inv_scale);
                S[j][2] = __expf(S[j][2] * inv_scale);
                S[j][3] = __expf(S[j][3] * inv_scale);
                l0 += S[j][0] + S[j][1];
                l1 += S[j][2] + S[j][3];
            }
        } else {
            #pragma unroll
            for (int j = 0; j < 4; j++) {
                const int cb = k0 + co + 8 * j + 2 * tg;
                const bool cg0 = gbit(gm, cb);
                const bool cg1 = gbit(gm, cb + 1);
                S[j][0] = (cg0 | rg0 | (cb     <= r0a)) ? __expf(S[j][0] * inv_scale) : 0.0f;
                S[j][1] = (cg1 | rg0 | (cb + 1 <= r0a)) ? __expf(S[j][1] * inv_scale) : 0.0f;
                S[j][2] = (cg0 | rg1 | (cb     <= r1a)) ? __expf(S[j][2] * inv_scale) : 0.0f;
                S[j][3] = (cg1 | rg1 | (cb + 1 <= r1a)) ? __expf(S[j][3] * inv_scale) : 0.0f;
                l0 += S[j][0] + S[j][1];
                l1 += S[j][2] + S[j][3];
            }
        }

        // ---- O += P V over this group's 32 keys ----
        #pragma unroll
        for (int ks = 0; ks < 2; ks++) {
            uint32_t pah[4], pal[4];
            repack_frag(S[2 * ks], S[2 * ks + 1], pah, pal);
            #pragma unroll
            for (int jp = 0; jp < 8; jp++) {
                uint32_t bh[4], bl[4];
                const int brow = co + 16 * ks + ((g4 & 1) << 3) + lr;
                const int bch  = 2 * jp + (g4 >> 1);
                LDSM_X4_T(bh, swaddr(sVH, brow, bch));
                LDSM_X4_T(bl, swaddr(sVL, brow, bch));
                MMA16816(O[2 * jp],     pah, bh[0], bh[1]);
                MMA16816(O[2 * jp + 1], pah, bh[2], bh[3]);
                MMA16816(O[2 * jp],     pal, bh[0], bh[1]);
                MMA16816(O[2 * jp + 1], pal, bh[2], bh[3]);
                MMA16816(O[2 * jp],     pah, bl[0], bl[1]);
                MMA16816(O[2 * jp + 1], pah, bl[2], bl[3]);
            }
        }
        __syncthreads();
    }

    // ---- deferred cross-lane row-sum reduction ----
    l0 += __shfl_xor_sync(0xffffffffu, l0, 1);
    l0 += __shfl_xor_sync(0xffffffffu, l0, 2);
    l1 += __shfl_xor_sync(0xffffffffu, l1, 1);
    l1 += __shfl_xor_sync(0xffffffffu, l1, 2);

    // ---- cross-group reduction (Q region is dead now) ----
    float* lsm = (float*)(smem + 65536);    // buffer-0 region start, dead
    if (ng == 1) {
        float* ob = (float*)(smem + wm * 8192);
        #pragma unroll
        for (int j = 0; j < 16; j++) {
            const int c = 8 * j + 2 * tg;
            *(float2*)(ob + g * 128 + c)       = make_float2(O[j][0], O[j][1]);
            *(float2*)(ob + (g + 8) * 128 + c) = make_float2(O[j][2], O[j][3]);
        }
        lsm[wm * 16 + g]     = l0;
        lsm[wm * 16 + g + 8] = l1;
    }
    __syncthreads();
    if (ng == 0) {
        const float* ob = (const float*)(smem + wm * 8192);
        l0 += lsm[wm * 16 + g];
        l1 += lsm[wm * 16 + g + 8];
        const float inv0 = 1.0f / l0;
        const float inv1 = 1.0f / l1;
        float* o0 = out + ((size_t)b * NS + r0a) * ND;
        float* o1 = out + ((size_t)b * NS + r1a) * ND;
        #pragma unroll
        for (int j = 0; j < 16; j++) {
            const int c = 8 * j + 2 * tg;
            float2 p0 = *(const float2*)(ob + g * 128 + c);
            float2 p1 = *(const float2*)(ob + (g + 8) * 128 + c);
            *(float2*)(o0 + c) = make_float2((O[j][0] + p0.x) * inv0, (O[j][1] + p0.y) * inv0);
            *(float2*)(o1 + c) = make_float2((O[j][2] + p1.x) * inv1, (O[j][3] + p1.y) * inv1);
        }
    }
}

// ---------------------------------------------------------------------------
// Host: exact port of np.random.default_rng(0).choice(2048, 32, replace=False)
// ---------------------------------------------------------------------------
static void compute_global_mask(GMask* gm)
{
    const uint32_t INIT_A = 0x43b0d7e5u, MULT_A = 0x931e8875u;
    const uint32_t INIT_B = 0x8b51f9ddu, MULT_B = 0x58f38dedu;
    const uint32_t MIX_L  = 0xca01f9ddu, MIX_R  = 0x4973f715u;

    uint32_t hc = INIT_A;
    auto hashf = [&](uint32_t v) -> uint32_t {
        v ^= hc; hc *= MULT_A; v *= hc; v ^= v >> 16; return v;
    };
    auto mixf = [&](uint32_t x, uint32_t y) -> uint32_t {
        uint32_t r = MIX_L * x - MIX_R * y;
        r ^= r >> 16; return r;
    };

    uint32_t pool[4];
    for (int i = 0; i < 4; i++) pool[i] = hashf(0u);
    for (int s = 0; s < 4; s++)
        for (int d = 0; d < 4; d++)
            if (s != d)
                pool[d] = mixf(pool[d], hashf(pool[s]));

    uint32_t gw[8]; uint32_t hb = INIT_B;
    for (int i = 0; i < 8; i++) {
        uint32_t dv = pool[i & 3];
        dv ^= hb; hb *= MULT_B; dv *= hb; dv ^= dv >> 16;
        gw[i] = dv;
    }
    uint64_t v64[4];
    for (int k = 0; k < 4; k++)
        v64[k] = (uint64_t)gw[2 * k] | ((uint64_t)gw[2 * k + 1] << 32);

    typedef __uint128_t u128;
    const u128 MULT = ((u128)0x2360ed051fc65da4ULL << 64) | 0x4385df649fccf645ULL;
    u128 inc = ((((u128)v64[2] << 64) | v64[3]) << 1) | 1;
    u128 st  = 0;
    st = st * MULT + inc;
    st += ((u128)v64[0] << 64) | v64[1];
    st = st * MULT + inc;

    int have = 0; uint32_t cache = 0;
    auto n64 = [&]() -> uint64_t {
        st = st * MULT + inc;
        uint64_t hi = (uint64_t)(st >> 64), lo = (uint64_t)st;
        unsigned rot = (unsigned)(hi >> 58);
        uint64_t x = hi ^ lo;
        return rot ? ((x >> rot) | (x << (64 - rot))) : x;
    };
    auto n32 = [&]() -> uint32_t {
        if (have) { have = 0; return cache; }
        uint64_t u = n64();
        have = 1; cache = (uint32_t)(u >> 32);
        return (uint32_t)u;
    };

    bool chosen[NS] = {false};
    for (uint32_t j = NS - 32; j < NS; j++) {
        uint32_t rng_excl = j + 1;
        uint64_t m = (uint64_t)n32() * rng_excl;
        uint32_t leftover = (uint32_t)m;
        if (leftover < rng_excl) {
            uint32_t threshold = (0xFFFFFFFFu - j) % rng_excl;
            while (leftover < threshold) {
                m = (uint64_t)n32() * rng_excl;
                leftover = (uint32_t)m;
            }
        }
        uint32_t val = (uint32_t)(m >> 32);
        if (chosen[val]) val = j;
        chosen[val] = true;
    }

    for (int w = 0; w < NS / 32; w++) gm->w[w] = 0u;
    for (int i = 0; i < NS; i++)
        if (chosen[i]) gm->w[i >> 5] |= (1u << (i & 31));
}

extern "C" void kernel_launch(void* const* d_in, const int* in_sizes, int n_in,
                              void* d_out, int out_size)
{
    (void)in_sizes; (void)n_in; (void)out_size;
    GMask gm;
    compute_global_mask(&gm);

    cudaFuncSetAttribute(proj_mma_kernel, cudaFuncAttributeMaxDynamicSharedMemorySize, PROJ_SMEM);
    proj_mma_kernel<<<dim3(NB * NS / 128, 3), 512, PROJ_SMEM>>>(
        (const float*)d_in[0], (const float*)d_in[1], (const float*)d_in[2],
        (const float*)d_in[3], (const float*)d_in[4],
        (const float*)d_in[5], (const float*)d_in[6],
        (const float*)d_in[7], (const float*)d_in[8]);

    cudaFuncSetAttribute(attn_mma_kernel, cudaFuncAttributeMaxDynamicSharedMemorySize, ATTN_SMEM);
    attn_mma_kernel<<<dim3(NS / 128, NB), 512, ATTN_SMEM>>>((float*)d_out, gm);
}

// round 13
// speedup vs baseline: 2.5878x; 1.2388x over previous
#include <cuda_runtime.h>
#include <cuda_bf16.h>
#include <cstdint>

#define NB   8
#define NS   2048
#define NDIN 1024
#define ND   128

// bf16 hi/lo pre-swizzled 64-row tiles: [QH,QL,KH,KL,VH,VL][b][tile][16KB] = 24 MB
// Q tiles (indices 0,1) are in PERMUTED row order; K/V natural.
__device__ uint4 g_bf[6][NB][32][1024];
// compact global-token K/V tail tiles (swizzled, rows 32-63 zero)
__device__ uint4 g_tail[4][NB][1024];
// inverse permutation: permuted row -> original row
__device__ int g_inv[NS];

struct GMask { unsigned int w[NS / 32]; };   // 2048-bit global-token mask
struct GIdx  { int idx[32]; };               // sorted global token indices

// ===========================================================================
// Warp-MMA helpers (mma.sync / ldmatrix / cp.async — baseline PTX)
// ===========================================================================
__device__ __forceinline__ uint32_t smem_to_u32(const void* smem_ptr) {
    uint32_t addr;
    asm("{ .reg .u64 tmp; cvta.to.shared.u64 tmp, %1; cvt.u32.u64 %0, tmp; }"
        : "=r"(addr) : "l"(smem_ptr));
    return addr;
}

__device__ __forceinline__ uint32_t packbf(float lo, float hi) {
    uint32_t r;
    asm("cvt.rn.bf16x2.f32 %0, %1, %2;" : "=r"(r) : "f"(hi), "f"(lo));
    return r;
}

__device__ __forceinline__ uint32_t prmt_hi(uint32_t a, uint32_t b) {
    uint32_t d;
    asm("prmt.b32 %0, %1, %2, 0x7632;" : "=r"(d) : "r"(a), "r"(b));
    return d;
}
__device__ __forceinline__ float trunc_lo(float x, uint32_t xb) {
    return x - __uint_as_float(xb & 0xFFFF0000u);
}

#define LDSM_X4(r, addr) \
    asm volatile("ldmatrix.sync.aligned.m8n8.x4.shared.b16 {%0,%1,%2,%3}, [%4];" \
        : "=r"((r)[0]), "=r"((r)[1]), "=r"((r)[2]), "=r"((r)[3]) : "r"(addr))

#define LDSM_X4_T(r, addr) \
    asm volatile("ldmatrix.sync.aligned.m8n8.x4.trans.shared.b16 {%0,%1,%2,%3}, [%4];" \
        : "=r"((r)[0]), "=r"((r)[1]), "=r"((r)[2]), "=r"((r)[3]) : "r"(addr))

#define MMA16816(d, a, b0, b1) \
    asm("mma.sync.aligned.m16n8k16.row.col.f32.bf16.bf16.f32 " \
        "{%0,%1,%2,%3}, {%4,%5,%6,%7}, {%8,%9}, {%0,%1,%2,%3};" \
        : "+f"((d)[0]), "+f"((d)[1]), "+f"((d)[2]), "+f"((d)[3]) \
        : "r"((a)[0]), "r"((a)[1]), "r"((a)[2]), "r"((a)[3]), "r"(b0), "r"(b1))

#define CP_ASYNC16(dst_u32, src_ptr) \
    asm volatile("cp.async.cg.shared.global [%0], [%1], 16;" \
        :: "r"(dst_u32), "l"(src_ptr) : "memory")
#define CP_COMMIT()  asm volatile("cp.async.commit_group;" ::: "memory")
#define CP_WAIT0()   asm volatile("cp.async.wait_group 0;" ::: "memory")
#define CP_WAIT1()   asm volatile("cp.async.wait_group 1;" ::: "memory")

__device__ __forceinline__ uint32_t swaddr(uint32_t base, int row, int chunk) {
    return base + row * 256 + ((chunk ^ (row & 7)) << 4);
}

__device__ __forceinline__ bool gbit(const GMask& gm, int i) {
    return (gm.w[i >> 5] >> (i & 31)) & 1u;
}

// permuted index of original row r: non-globals keep order, globals -> 2016+rank
__device__ __forceinline__ int newidx(const GMask& gm, int r) {
    int cnt = 0;
    const int wr = r >> 5;
    for (int w = 0; w < wr; w++) cnt += __popc(gm.w[w]);
    cnt += __popc(gm.w[wr] & ((1u << (r & 31)) - 1u));
    return gbit(gm, r) ? (NS - 32) + cnt : r - cnt;
}

__device__ __forceinline__ void repack_frag(const float* c0, const float* c1,
                                            uint32_t* pah, uint32_t* pal) {
    uint32_t a0 = __float_as_uint(c0[0]), a1 = __float_as_uint(c0[1]);
    uint32_t a2 = __float_as_uint(c0[2]), a3 = __float_as_uint(c0[3]);
    uint32_t b0 = __float_as_uint(c1[0]), b1 = __float_as_uint(c1[1]);
    uint32_t b2 = __float_as_uint(c1[2]), b3 = __float_as_uint(c1[3]);
    pah[0] = prmt_hi(a0, a1);
    pah[1] = prmt_hi(a2, a3);
    pah[2] = prmt_hi(b0, b1);
    pah[3] = prmt_hi(b2, b3);
    pal[0] = packbf(trunc_lo(c0[0], a0), trunc_lo(c0[1], a1));
    pal[1] = packbf(trunc_lo(c0[2], a2), trunc_lo(c0[3], a3));
    pal[2] = packbf(trunc_lo(c1[0], b0), trunc_lo(c1[1], b1));
    pal[3] = packbf(trunc_lo(c1[2], b2), trunc_lo(c1[3], b3));
}

// ===========================================================================
// Setup: inverse permutation table
// ===========================================================================
__global__ void setup_inv_kernel(GMask gm)
{
    const int r = blockIdx.x * 256 + threadIdx.x;
    if (r < NS) g_inv[newidx(gm, r)] = r;
}

// ===========================================================================
// Gather 32 global tokens' K/V rows (bf16, swizzled) into compact tail tiles.
// grid (NB), 256 threads. Rows 32-63 zeroed.
// ===========================================================================
__global__ void gather_tail_kernel(GIdx gi)
{
    const int b = blockIdx.x, tid = threadIdx.x;
    for (int task = tid; task < 4096; task += 256) {
        const int seg = task >> 10;            // KH,KL,VH,VL
        const int rem = task & 1023;
        const int row = rem >> 4, ch = rem & 15;
        uint4 v = make_uint4(0, 0, 0, 0);
        if (row < 32) {
            const int tok = gi.idx[row];
            const int tn = tok >> 6, rr = tok & 63;
            v = g_bf[2 + seg][b][tn][rr * 16 + (ch ^ (rr & 7))];
        }
        g_tail[seg][b][row * 16 + (ch ^ (row & 7))] = v;
    }
}

// ===========================================================================
// Projection GEMM: 512 threads, 16 warps (as R12). Q epilogue writes rows at
// PERMUTED positions; K/V natural.
// ===========================================================================
#define PROJ_SMEM 131072

__global__ __launch_bounds__(512)
void proj_mma_kernel(const float* __restrict__ xq, const float* __restrict__ xk, const float* __restrict__ xv,
                     const float* __restrict__ Wq, const float* __restrict__ bq,
                     const float* __restrict__ Wk, const float* __restrict__ bk,
                     const float* __restrict__ Wv, const float* __restrict__ bv,
                     GMask gm)
{
    extern __shared__ char psm[];
    const uint32_t sb  = smem_to_u32(psm);
    const uint32_t sXH = sb;
    const uint32_t sXL = sb + 16384;
    const uint32_t sWH = sb + 32768;
    const uint32_t sWL = sb + 49152;
    const uint32_t sXF = sb + 65536;
    const uint32_t sWF = sb + 98304;

    const int proj = blockIdx.y;
    const float* X    = (proj == 0) ? xq : (proj == 1) ? xk : xv;
    const float* W    = (proj == 0) ? Wq : (proj == 1) ? Wk : Wv;
    const float* bias = (proj == 0) ? bq : (proj == 1) ? bk : bv;

    const int tid  = threadIdx.x;
    const int w    = tid >> 5;
    const int wm   = w & 7;
    const int ng   = w >> 3;
    const int lane = tid & 31;
    const int g    = lane >> 2;
    const int tg   = lane & 3;
    const int g4   = lane >> 3;
    const int lr   = lane & 7;
    const int m0   = wm * 16;
    const int co   = ng * 64;
    const int mb   = blockIdx.x * 128;

    auto prefetch = [&](int kc) {
        const int k0 = kc * 64;
        #pragma unroll
        for (int k = 0; k < 4; k++) {
            const int p4  = tid + k * 512;
            const int p   = p4 * 4;
            const int row = p >> 6, col = p & 63;
            const uint32_t doff = (uint32_t)(p4 * 16);
            CP_ASYNC16(sXF + doff, X + (size_t)(mb + row) * NDIN + k0 + col);
            CP_ASYNC16(sWF + doff, W + (size_t)row * NDIN + k0 + col);
        }
        CP_COMMIT();
    };

    auto convert = [&]() {
        #pragma unroll
        for (int i = 0; i < 4; i++) {
            const int p4  = tid + i * 512;
            const int p   = p4 * 4;
            const int row = p >> 6, col = p & 63;
            const int ch8 = col >> 3, sub = (col >> 2) & 1;
            const uint32_t soff = (uint32_t)(p4 * 16);
            const uint32_t doff = (uint32_t)(row * 128 + ((ch8 ^ (row & 7)) << 4) + sub * 8);

            float4 xv = *(const float4*)(psm + 65536 + soff);
            uint32_t xb0 = __float_as_uint(xv.x), xb1 = __float_as_uint(xv.y);
            uint32_t xb2 = __float_as_uint(xv.z), xb3 = __float_as_uint(xv.w);
            uint2 H, L;
            H.x = prmt_hi(xb0, xb1); H.y = prmt_hi(xb2, xb3);
            L.x = packbf(trunc_lo(xv.x, xb0), trunc_lo(xv.y, xb1));
            L.y = packbf(trunc_lo(xv.z, xb2), trunc_lo(xv.w, xb3));
            *(uint2*)(psm + (sXH - sb) + doff) = H;
            *(uint2*)(psm + (sXL - sb) + doff) = L;

            float4 wv = *(const float4*)(psm + 98304 + soff);
            uint32_t wb0 = __float_as_uint(wv.x), wb1 = __float_as_uint(wv.y);
            uint32_t wb2 = __float_as_uint(wv.z), wb3 = __float_as_uint(wv.w);
            H.x = prmt_hi(wb0, wb1); H.y = prmt_hi(wb2, wb3);
            L.x = packbf(trunc_lo(wv.x, wb0), trunc_lo(wv.y, wb1));
            L.y = packbf(trunc_lo(wv.z, wb2), trunc_lo(wv.w, wb3));
            *(uint2*)(psm + (sWH - sb) + doff) = H;
            *(uint2*)(psm + (sWL - sb) + doff) = L;
        }
    };

    float acc[8][4];
    #pragma unroll
    for (int j = 0; j < 8; j++)
        #pragma unroll
        for (int e = 0; e < 4; e++) acc[j][e] = 0.0f;

    prefetch(0);
    CP_WAIT0();
    __syncthreads();
    convert();
    __syncthreads();

    for (int kc = 0; kc < NDIN / 64; kc++) {
        if (kc + 1 < NDIN / 64) prefetch(kc + 1);

        #pragma unroll
        for (int ks = 0; ks < 4; ks++) {
            uint32_t ah[4], al[4];
            const int arow = m0 + ((g4 & 1) << 3) + lr;
            const int ach  = 2 * ks + (g4 >> 1);
            LDSM_X4(ah, sXH + (uint32_t)(arow * 128 + ((ach ^ (arow & 7)) << 4)));
            LDSM_X4(al, sXL + (uint32_t)(arow * 128 + ((ach ^ (arow & 7)) << 4)));
            #pragma unroll
            for (int jp = 0; jp < 4; jp++) {
                uint32_t bh[4], bl[4];
                const int brow = co + 8 * (2 * jp + (g4 >> 1)) + lr;
                const int bch  = 2 * ks + (g4 & 1);
                LDSM_X4(bh, sWH + (uint32_t)(brow * 128 + ((bch ^ (brow & 7)) << 4)));
                LDSM_X4(bl, sWL + (uint32_t)(brow * 128 + ((bch ^ (brow & 7)) << 4)));
                MMA16816(acc[2 * jp],     ah, bh[0], bh[1]);
                MMA16816(acc[2 * jp + 1], ah, bh[2], bh[3]);
                MMA16816(acc[2 * jp],     al, bh[0], bh[1]);
                MMA16816(acc[2 * jp + 1], al, bh[2], bh[3]);
                MMA16816(acc[2 * jp],     ah, bl[0], bl[1]);
                MMA16816(acc[2 * jp + 1], ah, bl[2], bl[3]);
            }
        }

        if (kc + 1 < NDIN / 64) {
            CP_WAIT0();
            __syncthreads();
            convert();
            __syncthreads();
        }
    }

    // ---- epilogue: + bias -> bf16 hi/lo swizzled tiles (Q permuted) ----
    const int r0  = mb + m0 + g;
    const int bb_ = mb / NS;
    const int s0  = r0 % NS;
    int p0 = s0, p1 = s0 + 8;
    if (proj == 0) { p0 = newidx(gm, s0); p1 = newidx(gm, s0 + 8); }
    const int t0 = p0 >> 6, rin0 = p0 & 63;
    const int t1 = p1 >> 6, rin1 = p1 & 63;

    unsigned char* pH0 = (unsigned char*)g_bf[2 * proj][bb_][t0];
    unsigned char* pL0 = (unsigned char*)g_bf[2 * proj + 1][bb_][t0];
    unsigned char* pH1 = (unsigned char*)g_bf[2 * proj][bb_][t1];
    unsigned char* pL1 = (unsigned char*)g_bf[2 * proj + 1][bb_][t1];

    #pragma unroll
    for (int j = 0; j < 8; j++) {
        const int c   = co + 8 * j + 2 * tg;
        const int chk = (c >> 3);
        const float b0 = bias[c], b1 = bias[c + 1];
        const float x00 = acc[j][0] + b0, x01 = acc[j][1] + b1;
        const float x10 = acc[j][2] + b0, x11 = acc[j][3] + b1;

        uint32_t u00 = __float_as_uint(x00), u01 = __float_as_uint(x01);
        uint32_t off0 = (uint32_t)(rin0 * 256 + ((chk ^ (rin0 & 7)) << 4) + tg * 4);
        *(uint32_t*)(pH0 + off0) = prmt_hi(u00, u01);
        *(uint32_t*)(pL0 + off0) = packbf(trunc_lo(x00, u00), trunc_lo(x01, u01));

        uint32_t u10 = __float_as_uint(x10), u11 = __float_as_uint(x11);
        uint32_t off1 = (uint32_t)(rin1 * 256 + ((chk ^ (rin1 & 7)) << 4) + tg * 4);
        *(uint32_t*)(pH1 + off1) = prmt_hi(u10, u11);
        *(uint32_t*)(pL1 + off1) = packbf(trunc_lo(x10, u10), trunc_lo(x11, u11));
    }
}

// ===========================================================================
// Flash attention with causal tile skipping on permuted rows.
// CTA bx: heavy block 31-bx (warps 0-7), light block bx (warps 8-15).
// Tile loop i=0..Lcta-1 + tail (compact global columns). 512 thr, smem 192 KB.
// ===========================================================================
#define ATTN_SMEM 196608

__global__ __launch_bounds__(512)
void attn_mma_kernel(float* __restrict__ out, GMask gm, GIdx gi)
{
    extern __shared__ char smem[];
    const uint32_t sb  = smem_to_u32(smem);
    const uint32_t sQH = sb;
    const uint32_t sQL = sb + 32768;

    const int tid  = threadIdx.x;
    const int w    = tid >> 5;
    const int sub  = w >> 3;            // 0 heavy, 1 light
    const int wm   = (w >> 1) & 3;
    const int ng   = w & 1;
    const int lane = tid & 31;
    const int g    = lane >> 2;
    const int tg   = lane & 3;
    const int g4   = lane >> 3;
    const int lr   = lane & 7;
    const int b    = blockIdx.y;
    const int bx   = blockIdx.x;        // 0..15
    const int hj   = 31 - bx;
    const int lj   = bx;
    const int myj  = sub ? lj : hj;
    const int L0   = (hj + 2 < 32) ? hj + 2 : 32;   // heavy tile count
    const int L1   = lj + 2;                        // light tile count
    const int Lcta = L0;
    const int N    = Lcta + 1;                      // + tail iteration
    const int myL  = sub ? L1 : L0;

    const int srow  = sub * 64 + wm * 16;           // smem Q row base
    const int pbase = myj * 64 + wm * 16;           // permuted row base
    const int co    = ng * 32;

    // ---- group 0: Q tiles (heavy -> rows 0-63, light -> rows 64-127) ----
    #pragma unroll
    for (int seg = 0; seg < 4; seg++) {     // QH hj, QH lj, QL hj, QL lj
        const uint4* src = g_bf[seg >> 1][b][(seg & 1) ? lj : hj];
        const uint32_t d0 = sb + (uint32_t)seg * 16384 + (uint32_t)tid * 16;
        #pragma unroll
        for (int k = 0; k < 2; k++)
            CP_ASYNC16(d0 + (uint32_t)k * 8192, src + tid + k * 512);
    }
    CP_COMMIT();

    auto kv_prefetch = [&](int i) {
        const uint32_t bufb = sb + 65536u + (uint32_t)(i & 1) * 65536u;
        #pragma unroll
        for (int seg = 0; seg < 4; seg++) {
            const uint4* src = (i < Lcta) ? g_bf[2 + seg][b][i] : g_tail[seg][b];
            const uint32_t d0 = bufb + (uint32_t)seg * 16384 + (uint32_t)tid * 16;
            #pragma unroll
            for (int k = 0; k < 2; k++)
                CP_ASYNC16(d0 + (uint32_t)k * 8192, src + tid + k * 512);
        }
        CP_COMMIT();
    };
    kv_prefetch(0);

    const int r0a = g_inv[pbase + g];
    const int r1a = g_inv[pbase + g + 8];
    const bool rg0 = gbit(gm, r0a);
    const bool rg1 = gbit(gm, r1a);
    const float inv_scale = 0.08838834764831844f;   // 1/sqrt(128)

    float l0 = 0.0f, l1 = 0.0f;
    float O[16][4];
    #pragma unroll
    for (int j = 0; j < 16; j++)
        #pragma unroll
        for (int e = 0; e < 4; e++) O[j][e] = 0.0f;

    for (int i = 0; i < N; i++) {
        if (i + 1 < N) {
            kv_prefetch(i + 1);
            CP_WAIT1();
        } else {
            CP_WAIT0();
        }
        __syncthreads();

        const bool is_tail = (i == Lcta);
        const bool active  = (i < myL) || is_tail;

        if (active) {
            const uint32_t bufb = sb + 65536u + (uint32_t)(i & 1) * 65536u;
            const uint32_t sKH = bufb;
            const uint32_t sKL = bufb + 16384;
            const uint32_t sVH = bufb + 32768;
            const uint32_t sVL = bufb + 49152;

            float S[4][4];
            #pragma unroll
            for (int j = 0; j < 4; j++)
                #pragma unroll
                for (int e = 0; e < 4; e++) S[j][e] = 0.0f;

            #pragma unroll
            for (int ks = 0; ks < 8; ks++) {
                uint32_t ah[4], al[4];
                const int arow = srow + ((g4 & 1) << 3) + lr;
                const int ach  = 2 * ks + (g4 >> 1);
                LDSM_X4(ah, swaddr(sQH, arow, ach));
                LDSM_X4(al, swaddr(sQL, arow, ach));
                #pragma unroll
                for (int jp = 0; jp < 2; jp++) {
                    uint32_t bh[4], bl[4];
                    const int brow = co + 8 * (2 * jp + (g4 >> 1)) + lr;
                    const int bch  = 2 * ks + (g4 & 1);
                    LDSM_X4(bh, swaddr(sKH, brow, bch));
                    LDSM_X4(bl, swaddr(sKL, brow, bch));
                    MMA16816(S[2 * jp],     ah, bh[0], bh[1]);
                    MMA16816(S[2 * jp + 1], ah, bh[2], bh[3]);
                    MMA16816(S[2 * jp],     al, bh[0], bh[1]);
                    MMA16816(S[2 * jp + 1], al, bh[2], bh[3]);
                    MMA16816(S[2 * jp],     ah, bl[0], bl[1]);
                    MMA16816(S[2 * jp + 1], ah, bl[2], bl[3]);
                }
            }

            if (is_tail) {
                const int bound = 64 * myL;
                #pragma unroll
                for (int j = 0; j < 4; j++) {
                    const int c0i = co + 8 * j + 2 * tg;
                    const int o0 = (c0i     < 32) ? gi.idx[c0i]     : -1;
                    const int o1 = (c0i + 1 < 32) ? gi.idx[c0i + 1] : -1;
                    const bool a0 = (o0 >= bound);
                    const bool a1 = (o1 >= bound);
                    S[j][0] = a0 ? __expf(S[j][0] * inv_scale) : 0.0f;
                    S[j][1] = a1 ? __expf(S[j][1] * inv_scale) : 0.0f;
                    S[j][2] = a0 ? __expf(S[j][2] * inv_scale) : 0.0f;
                    S[j][3] = a1 ? __expf(S[j][3] * inv_scale) : 0.0f;
                    l0 += S[j][0] + S[j][1];
                    l1 += S[j][2] + S[j][3];
                }
            } else if (i * 64 + 63 <= pbase) {
                // fully causal for all rows this warp owns (orig >= permuted)
                #pragma unroll
                for (int j = 0; j < 4; j++) {
                    S[j][0] = __expf(S[j][0] * inv_scale);
                    S[j][1] = __expf(S[j][1] * inv_scale);
                    S[j][2] = __expf(S[j][2] * inv_scale);
                    S[j][3] = __expf(S[j][3] * inv_scale);
                    l0 += S[j][0] + S[j][1];
                    l1 += S[j][2] + S[j][3];
                }
            } else {
                const int k0 = i * 64;
                #pragma unroll
                for (int j = 0; j < 4; j++) {
                    const int cb = k0 + co + 8 * j + 2 * tg;
                    const bool cg0 = gbit(gm, cb);
                    const bool cg1 = gbit(gm, cb + 1);
                    S[j][0] = (cg0 | rg0 | (cb     <= r0a)) ? __expf(S[j][0] * inv_scale) : 0.0f;
                    S[j][1] = (cg1 | rg0 | (cb + 1 <= r0a)) ? __expf(S[j][1] * inv_scale) : 0.0f;
                    S[j][2] = (cg0 | rg1 | (cb     <= r1a)) ? __expf(S[j][2] * inv_scale) : 0.0f;
                    S[j][3] = (cg1 | rg1 | (cb + 1 <= r1a)) ? __expf(S[j][3] * inv_scale) : 0.0f;
                    l0 += S[j][0] + S[j][1];
                    l1 += S[j][2] + S[j][3];
                }
            }

            #pragma unroll
            for (int ks = 0; ks < 2; ks++) {
                uint32_t pah[4], pal[4];
                repack_frag(S[2 * ks], S[2 * ks + 1], pah, pal);
                #pragma unroll
                for (int jp = 0; jp < 8; jp++) {
                    uint32_t bh[4], bl[4];
                    const int brow = co + 16 * ks + ((g4 & 1) << 3) + lr;
                    const int bch  = 2 * jp + (g4 >> 1);
                    LDSM_X4_T(bh, swaddr(sVH, brow, bch));
                    LDSM_X4_T(bl, swaddr(sVL, brow, bch));
                    MMA16816(O[2 * jp],     pah, bh[0], bh[1]);
                    MMA16816(O[2 * jp + 1], pah, bh[2], bh[3]);
                    MMA16816(O[2 * jp],     pal, bh[0], bh[1]);
                    MMA16816(O[2 * jp + 1], pal, bh[2], bh[3]);
                    MMA16816(O[2 * jp],     pah, bl[0], bl[1]);
                    MMA16816(O[2 * jp + 1], pah, bl[2], bl[3]);
                }
            }
        }
        __syncthreads();
    }

    // ---- deferred cross-lane row-sum reduction ----
    l0 += __shfl_xor_sync(0xffffffffu, l0, 1);
    l0 += __shfl_xor_sync(0xffffffffu, l0, 2);
    l1 += __shfl_xor_sync(0xffffffffu, l1, 1);
    l1 += __shfl_xor_sync(0xffffffffu, l1, 2);

    // ---- cross-ng reduction (warp pairs (2k, 2k+1)); Q/KV smem dead ----
    float* lsm = (float*)(smem + 131072);
    const int reg = sub * 4 + wm;               // 8 disjoint regions
    if (ng == 1) {
        float* ob = (float*)(smem + reg * 8192);
        #pragma unroll
        for (int j = 0; j < 16; j++) {
            const int c = 8 * j + 2 * tg;
            *(float2*)(ob + g * 128 + c)       = make_float2(O[j][0], O[j][1]);
            *(float2*)(ob + (g + 8) * 128 + c) = make_float2(O[j][2], O[j][3]);
        }
        lsm[reg * 16 + g]     = l0;
        lsm[reg * 16 + g + 8] = l1;
    }
    __syncthreads();
    if (ng == 0) {
        const float* ob = (const float*)(smem + reg * 8192);
        l0 += lsm[reg * 16 + g];
        l1 += lsm[reg * 16 + g + 8];
        const float inv0 = 1.0f / l0;
        const float inv1 = 1.0f / l1;
        float* o0 = out + ((size_t)b * NS + r0a) * ND;
        float* o1 = out + ((size_t)b * NS + r1a) * ND;
        #pragma unroll
        for (int j = 0; j < 16; j++) {
            const int c = 8 * j + 2 * tg;
            float2 p0 = *(const float2*)(ob + g * 128 + c);
            float2 p1 = *(const float2*)(ob + (g + 8) * 128 + c);
            *(float2*)(o0 + c) = make_float2((O[j][0] + p0.x) * inv0, (O[j][1] + p0.y) * inv0);
            *(float2*)(o1 + c) = make_float2((O[j][2] + p1.x) * inv1, (O[j][3] + p1.y) * inv1);
        }
    }
}

// ---------------------------------------------------------------------------
// Host: exact port of np.random.default_rng(0).choice(2048, 32, replace=False)
// ---------------------------------------------------------------------------
static void compute_global_mask(GMask* gm, GIdx* gidx)
{
    const uint32_t INIT_A = 0x43b0d7e5u, MULT_A = 0x931e8875u;
    const uint32_t INIT_B = 0x8b51f9ddu, MULT_B = 0x58f38dedu;
    const uint32_t MIX_L  = 0xca01f9ddu, MIX_R  = 0x4973f715u;

    uint32_t hc = INIT_A;
    auto hashf = [&](uint32_t v) -> uint32_t {
        v ^= hc; hc *= MULT_A; v *= hc; v ^= v >> 16; return v;
    };
    auto mixf = [&](uint32_t x, uint32_t y) -> uint32_t {
        uint32_t r = MIX_L * x - MIX_R * y;
        r ^= r >> 16; return r;
    };

    uint32_t pool[4];
    for (int i = 0; i < 4; i++) pool[i] = hashf(0u);
    for (int s = 0; s < 4; s++)
        for (int d = 0; d < 4; d++)
            if (s != d)
                pool[d] = mixf(pool[d], hashf(pool[s]));

    uint32_t gw[8]; uint32_t hb = INIT_B;
    for (int i = 0; i < 8; i++) {
        uint32_t dv = pool[i & 3];
        dv ^= hb; hb *= MULT_B; dv *= hb; dv ^= dv >> 16;
        gw[i] = dv;
    }
    uint64_t v64[4];
    for (int k = 0; k < 4; k++)
        v64[k] = (uint64_t)gw[2 * k] | ((uint64_t)gw[2 * k + 1] << 32);

    typedef __uint128_t u128;
    const u128 MULT = ((u128)0x2360ed051fc65da4ULL << 64) | 0x4385df649fccf645ULL;
    u128 inc = ((((u128)v64[2] << 64) | v64[3]) << 1) | 1;
    u128 st  = 0;
    st = st * MULT + inc;
    st += ((u128)v64[0] << 64) | v64[1];
    st = st * MULT + inc;

    int have = 0; uint32_t cache = 0;
    auto n64 = [&]() -> uint64_t {
        st = st * MULT + inc;
        uint64_t hi = (uint64_t)(st >> 64), lo = (uint64_t)st;
        unsigned rot = (unsigned)(hi >> 58);
        uint64_t x = hi ^ lo;
        return rot ? ((x >> rot) | (x << (64 - rot))) : x;
    };
    auto n32 = [&]() -> uint32_t {
        if (have) { have = 0; return cache; }
        uint64_t u = n64();
        have = 1; cache = (uint32_t)(u >> 32);
        return (uint32_t)u;
    };

    bool chosen[NS] = {false};
    for (uint32_t j = NS - 32; j < NS; j++) {
        uint32_t rng_excl = j + 1;
        uint64_t m = (uint64_t)n32() * rng_excl;
        uint32_t leftover = (uint32_t)m;
        if (leftover < rng_excl) {
            uint32_t threshold = (0xFFFFFFFFu - j) % rng_excl;
            while (leftover < threshold) {
                m = (uint64_t)n32() * rng_excl;
                leftover = (uint32_t)m;
            }
        }
        uint32_t val = (uint32_t)(m >> 32);
        if (chosen[val]) val = j;
        chosen[val] = true;
    }

    for (int w = 0; w < NS / 32; w++) gm->w[w] = 0u;
    int n = 0;
    for (int i = 0; i < NS; i++)
        if (chosen[i]) {
            gm->w[i >> 5] |= (1u << (i & 31));
            gidx->idx[n++] = i;
        }
}

extern "C" void kernel_launch(void* const* d_in, const int* in_sizes, int n_in,
                              void* d_out, int out_size)
{
    (void)in_sizes; (void)n_in; (void)out_size;
    GMask gm; GIdx gi;
    compute_global_mask(&gm, &gi);

    cudaFuncSetAttribute(proj_mma_kernel, cudaFuncAttributeMaxDynamicSharedMemorySize, PROJ_SMEM);
    proj_mma_kernel<<<dim3(NB * NS / 128, 3), 512, PROJ_SMEM>>>(
        (const float*)d_in[0], (const float*)d_in[1], (const float*)d_in[2],
        (const float*)d_in[3], (const float*)d_in[4],
        (const float*)d_in[5], (const float*)d_in[6],
        (const float*)d_in[7], (const float*)d_in[8], gm);

    setup_inv_kernel<<<NS / 256, 256>>>(gm);
    gather_tail_kernel<<<NB, 256>>>(gi);

    cudaFuncSetAttribute(attn_mma_kernel, cudaFuncAttributeMaxDynamicSharedMemorySize, ATTN_SMEM);
    attn_mma_kernel<<<dim3(16, NB), 512, ATTN_SMEM>>>((float*)d_out, gm, gi);
}

// round 15
// speedup vs baseline: 2.6050x; 1.0067x over previous
#include <cuda_runtime.h>
#include <cuda_bf16.h>
#include <cstdint>

#define NB   8
#define NS   2048
#define NDIN 1024
#define ND   128

// bf16 hi/lo pre-swizzled 64-row tiles: [QH,QL,KH,KL,VH,VL][b][tile][16KB] = 24 MB
// Q tiles (indices 0,1) are in PERMUTED row order; K/V natural.
__device__ uint4 g_bf[6][NB][32][1024];
// compact global-token K/V tail tiles (swizzled, rows 32-63 zero)
__device__ uint4 g_tail[4][NB][1024];
// inverse permutation: permuted row -> original row
__device__ int g_inv[NS];
// pre-converted W operand tiles: [proj][kc][hi|lo contiguous 32KB]
__device__ uint4 g_wt[3][16][2][1024];

struct GMask { unsigned int w[NS / 32]; };   // 2048-bit global-token mask
struct GIdx  { int idx[32]; };               // sorted global token indices

// ===========================================================================
// Warp-MMA helpers (mma.sync / ldmatrix / cp.async — baseline PTX)
// ===========================================================================
__device__ __forceinline__ uint32_t smem_to_u32(const void* smem_ptr) {
    uint32_t addr;
    asm("{ .reg .u64 tmp; cvta.to.shared.u64 tmp, %1; cvt.u32.u64 %0, tmp; }"
        : "=r"(addr) : "l"(smem_ptr));
    return addr;
}

__device__ __forceinline__ uint32_t packbf(float lo, float hi) {
    uint32_t r;
    asm("cvt.rn.bf16x2.f32 %0, %1, %2;" : "=r"(r) : "f"(hi), "f"(lo));
    return r;
}

__device__ __forceinline__ uint32_t prmt_hi(uint32_t a, uint32_t b) {
    uint32_t d;
    asm("prmt.b32 %0, %1, %2, 0x7632;" : "=r"(d) : "r"(a), "r"(b));
    return d;
}
__device__ __forceinline__ float trunc_lo(float x, uint32_t xb) {
    return x - __uint_as_float(xb & 0xFFFF0000u);
}

#define LDSM_X4(r, addr) \
    asm volatile("ldmatrix.sync.aligned.m8n8.x4.shared.b16 {%0,%1,%2,%3}, [%4];" \
        : "=r"((r)[0]), "=r"((r)[1]), "=r"((r)[2]), "=r"((r)[3]) : "r"(addr))

#define LDSM_X4_T(r, addr) \
    asm volatile("ldmatrix.sync.aligned.m8n8.x4.trans.shared.b16 {%0,%1,%2,%3}, [%4];" \
        : "=r"((r)[0]), "=r"((r)[1]), "=r"((r)[2]), "=r"((r)[3]) : "r"(addr))

#define MMA16816(d, a, b0, b1) \
    asm("mma.sync.aligned.m16n8k16.row.col.f32.bf16.bf16.f32 " \
        "{%0,%1,%2,%3}, {%4,%5,%6,%7}, {%8,%9}, {%0,%1,%2,%3};" \
        : "+f"((d)[0]), "+f"((d)[1]), "+f"((d)[2]), "+f"((d)[3]) \
        : "r"((a)[0]), "r"((a)[1]), "r"((a)[2]), "r"((a)[3]), "r"(b0), "r"(b1))

#define CP_ASYNC16(dst_u32, src_ptr) \
    asm volatile("cp.async.cg.shared.global [%0], [%1], 16;" \
        :: "r"(dst_u32), "l"(src_ptr) : "memory")
#define CP_COMMIT()  asm volatile("cp.async.commit_group;" ::: "memory")
#define CP_WAIT0()   asm volatile("cp.async.wait_group 0;" ::: "memory")
#define CP_WAIT1()   asm volatile("cp.async.wait_group 1;" ::: "memory")

__device__ __forceinline__ uint32_t swaddr(uint32_t base, int row, int chunk) {
    return base + row * 256 + ((chunk ^ (row & 7)) << 4);
}

__device__ __forceinline__ bool gbit(const GMask& gm, int i) {
    return (gm.w[i >> 5] >> (i & 31)) & 1u;
}

// permuted index of original row r: non-globals keep order, globals -> 2016+rank
__device__ __forceinline__ int newidx(const GMask& gm, int r) {
    int cnt = 0;
    const int wr = r >> 5;
    for (int w = 0; w < wr; w++) cnt += __popc(gm.w[w]);
    cnt += __popc(gm.w[wr] & ((1u << (r & 31)) - 1u));
    return gbit(gm, r) ? (NS - 32) + cnt : r - cnt;
}

__device__ __forceinline__ void repack_frag(const float* c0, const float* c1,
                                            uint32_t* pah, uint32_t* pal) {
    uint32_t a0 = __float_as_uint(c0[0]), a1 = __float_as_uint(c0[1]);
    uint32_t a2 = __float_as_uint(c0[2]), a3 = __float_as_uint(c0[3]);
    uint32_t b0 = __float_as_uint(c1[0]), b1 = __float_as_uint(c1[1]);
    uint32_t b2 = __float_as_uint(c1[2]), b3 = __float_as_uint(c1[3]);
    pah[0] = prmt_hi(a0, a1);
    pah[1] = prmt_hi(a2, a3);
    pah[2] = prmt_hi(b0, b1);
    pah[3] = prmt_hi(b2, b3);
    pal[0] = packbf(trunc_lo(c0[0], a0), trunc_lo(c0[1], a1));
    pal[1] = packbf(trunc_lo(c0[2], a2), trunc_lo(c0[3], a3));
    pal[2] = packbf(trunc_lo(c1[0], b0), trunc_lo(c1[1], b1));
    pal[3] = packbf(trunc_lo(c1[2], b2), trunc_lo(c1[3], b3));
}

// ===========================================================================
// Setup kernels
// ===========================================================================
__global__ void setup_inv_kernel(GMask gm)
{
    const int r = blockIdx.x * 256 + threadIdx.x;
    if (r < NS) g_inv[newidx(gm, r)] = r;
}

// Pre-convert W (3 x [128,1024] fp32) into chunk operand tiles (hi/lo, swizzled).
// grid (16, 3), 256 threads.
__global__ void conv_w_kernel(const float* __restrict__ Wq,
                              const float* __restrict__ Wk,
                              const float* __restrict__ Wv)
{
    const int kc = blockIdx.x, proj = blockIdx.y, tid = threadIdx.x;
    const float* W = (proj == 0) ? Wq : (proj == 1) ? Wk : Wv;
    unsigned char* dH = (unsigned char*)g_wt[proj][kc][0];
    unsigned char* dL = (unsigned char*)g_wt[proj][kc][1];
    #pragma unroll
    for (int i = 0; i < 8; i++) {
        const int p4  = tid + i * 256;
        const int p   = p4 * 4;
        const int row = p >> 6, col = p & 63;
        const int ch8 = col >> 3, sub = (col >> 2) & 1;
        float4 wv = *(const float4*)(W + (size_t)row * NDIN + kc * 64 + col);
        uint32_t b0 = __float_as_uint(wv.x), b1 = __float_as_uint(wv.y);
        uint32_t b2 = __float_as_uint(wv.z), b3 = __float_as_uint(wv.w);
        uint2 H, L;
        H.x = prmt_hi(b0, b1); H.y = prmt_hi(b2, b3);
        L.x = packbf(trunc_lo(wv.x, b0), trunc_lo(wv.y, b1));
        L.y = packbf(trunc_lo(wv.z, b2), trunc_lo(wv.w, b3));
        const uint32_t off = (uint32_t)(row * 128 + ((ch8 ^ (row & 7)) << 4) + sub * 8);
        *(uint2*)(dH + off) = H;
        *(uint2*)(dL + off) = L;
    }
}

// Gather 32 global tokens' K/V rows into compact tail tiles (rows 32-63 zero).
__global__ void gather_tail_kernel(GIdx gi)
{
    const int b = blockIdx.x, tid = threadIdx.x;
    for (int task = tid; task < 4096; task += 256) {
        const int seg = task >> 10;
        const int rem = task & 1023;
        const int row = rem >> 4, ch = rem & 15;
        uint4 v = make_uint4(0, 0, 0, 0);
        if (row < 32) {
            const int tok = gi.idx[row];
            const int tn = tok >> 6, rr = tok & 63;
            v = g_bf[2 + seg][b][tn][rr * 16 + (ch ^ (rr & 7))];
        }
        g_tail[seg][b][row * 16 + (ch ^ (row & 7))] = v;
    }
}

// ===========================================================================
// Projection GEMM: 512 threads, 16 warps. W operands cp.async'd pre-converted
// (double-buffered); X staged fp32 + converted. Q epilogue row-permuted.
// SMEM: XH|XL 32K | Wops buf0 32K | Wops buf1 32K | X stage 32K = 128 KB.
// ===========================================================================
#define PROJ_SMEM 131072

__global__ __launch_bounds__(512)
void proj_mma_kernel(const float* __restrict__ xq, const float* __restrict__ xk, const float* __restrict__ xv,
                     const float* __restrict__ bq, const float* __restrict__ bk, const float* __restrict__ bv,
                     GMask gm)
{
    extern __shared__ char psm[];
    const uint32_t sb  = smem_to_u32(psm);
    const uint32_t sXH = sb;
    const uint32_t sXL = sb + 16384;
    const uint32_t sWb = sb + 32768;     // two 32KB W operand buffers
    const uint32_t sXF = sb + 98304;     // fp32 X stage, 32KB

    const int proj = blockIdx.y;
    const float* X    = (proj == 0) ? xq : (proj == 1) ? xk : xv;
    const float* bias = (proj == 0) ? bq : (proj == 1) ? bk : bv;

    const int tid  = threadIdx.x;
    const int w    = tid >> 5;
    const int wm   = w & 7;
    const int ng   = w >> 3;
    const int lane = tid & 31;
    const int g    = lane >> 2;
    const int tg   = lane & 3;
    const int g4   = lane >> 3;
    const int lr   = lane & 7;
    const int m0   = wm * 16;
    const int co   = ng * 64;
    const int mb   = blockIdx.x * 128;

    auto prefetch = [&](int kc) {
        const int k0 = kc * 64;
        const uint32_t wdst = sWb + (uint32_t)(kc & 1) * 32768u;
        const uint4* wsrc = g_wt[proj][kc][0];
        #pragma unroll
        for (int k = 0; k < 4; k++) {
            const int p4  = tid + k * 512;
            const int p   = p4 * 4;
            const int row = p >> 6, col = p & 63;
            CP_ASYNC16(sXF + (uint32_t)(p4 * 16), X + (size_t)(mb + row) * NDIN + k0 + col);
            CP_ASYNC16(wdst + (uint32_t)(p4 * 16), wsrc + p4);
        }
        CP_COMMIT();
    };

    auto convert = [&]() {
        #pragma unroll
        for (int i = 0; i < 4; i++) {
            const int p4  = tid + i * 512;
            const int p   = p4 * 4;
            const int row = p >> 6, col = p & 63;
            const int ch8 = col >> 3, sub = (col >> 2) & 1;
            const uint32_t soff = (uint32_t)(p4 * 16);
            const uint32_t doff = (uint32_t)(row * 128 + ((ch8 ^ (row & 7)) << 4) + sub * 8);

            float4 xv = *(const float4*)(psm + 98304 + soff);
            uint32_t xb0 = __float_as_uint(xv.x), xb1 = __float_as_uint(xv.y);
            uint32_t xb2 = __float_as_uint(xv.z), xb3 = __float_as_uint(xv.w);
            uint2 H, L;
            H.x = prmt_hi(xb0, xb1); H.y = prmt_hi(xb2, xb3);
            L.x = packbf(trunc_lo(xv.x, xb0), trunc_lo(xv.y, xb1));
            L.y = packbf(trunc_lo(xv.z, xb2), trunc_lo(xv.w, xb3));
            *(uint2*)(psm + (sXH - sb) + doff) = H;
            *(uint2*)(psm + (sXL - sb) + doff) = L;
        }
    };

    float acc[8][4];
    #pragma unroll
    for (int j = 0; j < 8; j++)
        #pragma unroll
        for (int e = 0; e < 4; e++) acc[j][e] = 0.0f;

    prefetch(0);
    CP_WAIT0();
    __syncthreads();
    convert();
    __syncthreads();

    for (int kc = 0; kc < NDIN / 64; kc++) {
        if (kc + 1 < NDIN / 64) prefetch(kc + 1);

        const uint32_t sWH = sWb + (uint32_t)(kc & 1) * 32768u;
        const uint32_t sWL = sWH + 16384;

        #pragma unroll
        for (int ks = 0; ks < 4; ks++) {
            uint32_t ah[4], al[4];
            const int arow = m0 + ((g4 & 1) << 3) + lr;
            const int ach  = 2 * ks + (g4 >> 1);
            LDSM_X4(ah, sXH + (uint32_t)(arow * 128 + ((ach ^ (arow & 7)) << 4)));
            LDSM_X4(al, sXL + (uint32_t)(arow * 128 + ((ach ^ (arow & 7)) << 4)));
            #pragma unroll
            for (int jp = 0; jp < 4; jp++) {
                uint32_t bh[4], bl[4];
                const int brow = co + 8 * (2 * jp + (g4 >> 1)) + lr;
                const int bch  = 2 * ks + (g4 & 1);
                LDSM_X4(bh, sWH + (uint32_t)(brow * 128 + ((bch ^ (brow & 7)) << 4)));
                LDSM_X4(bl, sWL + (uint32_t)(brow * 128 + ((bch ^ (brow & 7)) << 4)));
                MMA16816(acc[2 * jp],     ah, bh[0], bh[1]);
                MMA16816(acc[2 * jp + 1], ah, bh[2], bh[3]);
                MMA16816(acc[2 * jp],     al, bh[0], bh[1]);
                MMA16816(acc[2 * jp + 1], al, bh[2], bh[3]);
                MMA16816(acc[2 * jp],     ah, bl[0], bl[1]);
                MMA16816(acc[2 * jp + 1], ah, bl[2], bl[3]);
            }
        }

        if (kc + 1 < NDIN / 64) {
            CP_WAIT0();
            __syncthreads();
            convert();
            __syncthreads();
        }
    }

    // ---- epilogue: + bias -> bf16 hi/lo swizzled tiles (Q permuted) ----
    const int r0  = mb + m0 + g;
    const int bb_ = mb / NS;
    const int s0  = r0 % NS;
    int p0 = s0, p1 = s0 + 8;
    if (proj == 0) { p0 = newidx(gm, s0); p1 = newidx(gm, s0 + 8); }
    const int t0 = p0 >> 6, rin0 = p0 & 63;
    const int t1 = p1 >> 6, rin1 = p1 & 63;

    unsigned char* pH0 = (unsigned char*)g_bf[2 * proj][bb_][t0];
    unsigned char* pL0 = (unsigned char*)g_bf[2 * proj + 1][bb_][t0];
    unsigned char* pH1 = (unsigned char*)g_bf[2 * proj][bb_][t1];
    unsigned char* pL1 = (unsigned char*)g_bf[2 * proj + 1][bb_][t1];

    #pragma unroll
    for (int j = 0; j < 8; j++) {
        const int c   = co + 8 * j + 2 * tg;
        const int chk = (c >> 3);
        const float b0 = bias[c], b1 = bias[c + 1];
        const float x00 = acc[j][0] + b0, x01 = acc[j][1] + b1;
        const float x10 = acc[j][2] + b0, x11 = acc[j][3] + b1;

        uint32_t u00 = __float_as_uint(x00), u01 = __float_as_uint(x01);
        uint32_t off0 = (uint32_t)(rin0 * 256 + ((chk ^ (rin0 & 7)) << 4) + tg * 4);
        *(uint32_t*)(pH0 + off0) = prmt_hi(u00, u01);
        *(uint32_t*)(pL0 + off0) = packbf(trunc_lo(x00, u00), trunc_lo(x01, u01));

        uint32_t u10 = __float_as_uint(x10), u11 = __float_as_uint(x11);
        uint32_t off1 = (uint32_t)(rin1 * 256 + ((chk ^ (rin1 & 7)) << 4) + tg * 4);
        *(uint32_t*)(pH1 + off1) = prmt_hi(u10, u11);
        *(uint32_t*)(pL1 + off1) = packbf(trunc_lo(x10, u10), trunc_lo(x11, u11));
    }
}

// ===========================================================================
// Flash attention with causal tile skipping on permuted rows (as R13).
// Tail computed by ng==0 warps only (cols 32-63 are zero-padded).
// ===========================================================================
#define ATTN_SMEM 196608

__global__ __launch_bounds__(512)
void attn_mma_kernel(float* __restrict__ out, GMask gm, GIdx gi)
{
    extern __shared__ char smem[];
    const uint32_t sb  = smem_to_u32(smem);
    const uint32_t sQH = sb;
    const uint32_t sQL = sb + 32768;

    const int tid  = threadIdx.x;
    const int w    = tid >> 5;
    const int sub  = w >> 3;
    const int wm   = (w >> 1) & 3;
    const int ng   = w & 1;
    const int lane = tid & 31;
    const int g    = lane >> 2;
    const int tg   = lane & 3;
    const int g4   = lane >> 3;
    const int lr   = lane & 7;
    const int b    = blockIdx.y;
    const int bx   = blockIdx.x;
    const int hj   = 31 - bx;
    const int lj   = bx;
    const int myj  = sub ? lj : hj;
    const int L0   = (hj + 2 < 32) ? hj + 2 : 32;
    const int L1   = lj + 2;
    const int Lcta = L0;
    const int N    = Lcta + 1;
    const int myL  = sub ? L1 : L0;

    const int srow  = sub * 64 + wm * 16;
    const int pbase = myj * 64 + wm * 16;
    const int co    = ng * 32;

    #pragma unroll
    for (int seg = 0; seg < 4; seg++) {
        const uint4* src = g_bf[seg >> 1][b][(seg & 1) ? lj : hj];
        const uint32_t d0 = sb + (uint32_t)seg * 16384 + (uint32_t)tid * 16;
        #pragma unroll
        for (int k = 0; k < 2; k++)
            CP_ASYNC16(d0 + (uint32_t)k * 8192, src + tid + k * 512);
    }
    CP_COMMIT();

    auto kv_prefetch = [&](int i) {
        const uint32_t bufb = sb + 65536u + (uint32_t)(i & 1) * 65536u;
        #pragma unroll
        for (int seg = 0; seg < 4; seg++) {
            const uint4* src = (i < Lcta) ? g_bf[2 + seg][b][i] : g_tail[seg][b];
            const uint32_t d0 = bufb + (uint32_t)seg * 16384 + (uint32_t)tid * 16;
            #pragma unroll
            for (int k = 0; k < 2; k++)
                CP_ASYNC16(d0 + (uint32_t)k * 8192, src + tid + k * 512);
        }
        CP_COMMIT();
    };
    kv_prefetch(0);

    const int r0a = g_inv[pbase + g];
    const int r1a = g_inv[pbase + g + 8];
    const bool rg0 = gbit(gm, r0a);
    const bool rg1 = gbit(gm, r1a);
    const float inv_scale = 0.08838834764831844f;   // 1/sqrt(128)

    float l0 = 0.0f, l1 = 0.0f;
    float O[16][4];
    #pragma unroll
    for (int j = 0; j < 16; j++)
        #pragma unroll
        for (int e = 0; e < 4; e++) O[j][e] = 0.0f;

    for (int i = 0; i < N; i++) {
        if (i + 1 < N) {
            kv_prefetch(i + 1);
            CP_WAIT1();
        } else {
            CP_WAIT0();
        }
        __syncthreads();

        const bool is_tail = (i == Lcta);
        const bool active  = (i < myL) || (is_tail && ng == 0);

        if (active) {
            const uint32_t bufb = sb + 65536u + (uint32_t)(i & 1) * 65536u;
            const uint32_t sKH = bufb;
            const uint32_t sKL = bufb + 16384;
            const uint32_t sVH = bufb + 32768;
            const uint32_t sVL = bufb + 49152;

            float S[4][4];
            #pragma unroll
            for (int j = 0; j < 4; j++)
                #pragma unroll
                for (int e = 0; e < 4; e++) S[j][e] = 0.0f;

            #pragma unroll
            for (int ks = 0; ks < 8; ks++) {
                uint32_t ah[4], al[4];
                const int arow = srow + ((g4 & 1) << 3) + lr;
                const int ach  = 2 * ks + (g4 >> 1);
                LDSM_X4(ah, swaddr(sQH, arow, ach));
                LDSM_X4(al, swaddr(sQL, arow, ach));
                #pragma unroll
                for (int jp = 0; jp < 2; jp++) {
                    uint32_t bh[4], bl[4];
                    const int brow = co + 8 * (2 * jp + (g4 >> 1)) + lr;
                    const int bch  = 2 * ks + (g4 & 1);
                    LDSM_X4(bh, swaddr(sKH, brow, bch));
                    LDSM_X4(bl, swaddr(sKL, brow, bch));
                    MMA16816(S[2 * jp],     ah, bh[0], bh[1]);
                    MMA16816(S[2 * jp + 1], ah, bh[2], bh[3]);
                    MMA16816(S[2 * jp],     al, bh[0], bh[1]);
                    MMA16816(S[2 * jp + 1], al, bh[2], bh[3]);
                    MMA16816(S[2 * jp],     ah, bl[0], bl[1]);
                    MMA16816(S[2 * jp + 1], ah, bl[2], bl[3]);
                }
            }

            if (is_tail) {
                const int bound = 64 * myL;
                #pragma unroll
                for (int j = 0; j < 4; j++) {
                    const int c0i = co + 8 * j + 2 * tg;
                    const int o0 = (c0i     < 32) ? gi.idx[c0i]     : -1;
                    const int o1 = (c0i + 1 < 32) ? gi.idx[c0i + 1] : -1;
                    const bool a0 = (o0 >= bound);
                    const bool a1 = (o1 >= bound);
                    S[j][0] = a0 ? __expf(S[j][0] * inv_scale) : 0.0f;
                    S[j][1] = a1 ? __expf(S[j][1] * inv_scale) : 0.0f;
                    S[j][2] = a0 ? __expf(S[j][2] * inv_scale) : 0.0f;
                    S[j][3] = a1 ? __expf(S[j][3] * inv_scale) : 0.0f;
                    l0 += S[j][0] + S[j][1];
                    l1 += S[j][2] + S[j][3];
                }
            } else if (i * 64 + 63 <= pbase) {
                #pragma unroll
                for (int j = 0; j < 4; j++) {
                    S[j][0] = __expf(S[j][0] * inv_scale);
                    S[j][1] = __expf(S[j][1] * inv_scale);
                    S[j][2] = __expf(S[j][2] * inv_scale);
                    S[j][3] = __expf(S[j][3] * inv_scale);
                    l0 += S[j][0] + S[j][1];
                    l1 += S[j][2] + S[j][3];
                }
            } else {
                const int k0 = i * 64;
                #pragma unroll
                for (int j = 0; j < 4; j++) {
                    const int cb = k0 + co + 8 * j + 2 * tg;
                    const bool cg0 = gbit(gm, cb);
                    const bool cg1 = gbit(gm, cb + 1);
                    S[j][0] = (cg0 | rg0 | (cb     <= r0a)) ? __expf(S[j][0] * inv_scale) : 0.0f;
                    S[j][1] = (cg1 | rg0 | (cb + 1 <= r0a)) ? __expf(S[j][1] * inv_scale) : 0.0f;
                    S[j][2] = (cg0 | rg1 | (cb     <= r1a)) ? __expf(S[j][2] * inv_scale) : 0.0f;
                    S[j][3] = (cg1 | rg1 | (cb + 1 <= r1a)) ? __expf(S[j][3] * inv_scale) : 0.0f;
                    l0 += S[j][0] + S[j][1];
                    l1 += S[j][2] + S[j][3];
                }
            }

            #pragma unroll
            for (int ks = 0; ks < 2; ks++) {
                uint32_t pah[4], pal[4];
                repack_frag(S[2 * ks], S[2 * ks + 1], pah, pal);
                #pragma unroll
                for (int jp = 0; jp < 8; jp++) {
                    uint32_t bh[4], bl[4];
                    const int brow = co + 16 * ks + ((g4 & 1) << 3) + lr;
                    const int bch  = 2 * jp + (g4 >> 1);
                    LDSM_X4_T(bh, swaddr(sVH, brow, bch));
                    LDSM_X4_T(bl, swaddr(sVL, brow, bch));
                    MMA16816(O[2 * jp],     pah, bh[0], bh[1]);
                    MMA16816(O[2 * jp + 1], pah, bh[2], bh[3]);
                    MMA16816(O[2 * jp],     pal, bh[0], bh[1]);
                    MMA16816(O[2 * jp + 1], pal, bh[2], bh[3]);
                    MMA16816(O[2 * jp],     pah, bl[0], bl[1]);
                    MMA16816(O[2 * jp + 1], pah, bl[2], bl[3]);
                }
            }
        }
        __syncthreads();
    }

    l0 += __shfl_xor_sync(0xffffffffu, l0, 1);
    l0 += __shfl_xor_sync(0xffffffffu, l0, 2);
    l1 += __shfl_xor_sync(0xffffffffu, l1, 1);
    l1 += __shfl_xor_sync(0xffffffffu, l1, 2);

    float* lsm = (float*)(smem + 131072);
    const int reg = sub * 4 + wm;
    if (ng == 1) {
        float* ob = (float*)(smem + reg * 8192);
        #pragma unroll
        for (int j = 0; j < 16; j++) {
            const int c = 8 * j + 2 * tg;
            *(float2*)(ob + g * 128 + c)       = make_float2(O[j][0], O[j][1]);
            *(float2*)(ob + (g + 8) * 128 + c) = make_float2(O[j][2], O[j][3]);
        }
        lsm[reg * 16 + g]     = l0;
        lsm[reg * 16 + g + 8] = l1;
    }
    __syncthreads();
    if (ng == 0) {
        const float* ob = (const float*)(smem + reg * 8192);
        l0 += lsm[reg * 16 + g];
        l1 += lsm[reg * 16 + g + 8];
        const float inv0 = 1.0f / l0;
        const float inv1 = 1.0f / l1;
        float* o0 = out + ((size_t)b * NS + r0a) * ND;
        float* o1 = out + ((size_t)b * NS + r1a) * ND;
        #pragma unroll
        for (int j = 0; j < 16; j++) {
            const int c = 8 * j + 2 * tg;
            float2 p0 = *(const float2*)(ob + g * 128 + c);
            float2 p1 = *(const float2*)(ob + (g + 8) * 128 + c);
            *(float2*)(o0 + c) = make_float2((O[j][0] + p0.x) * inv0, (O[j][1] + p0.y) * inv0);
            *(float2*)(o1 + c) = make_float2((O[j][2] + p1.x) * inv1, (O[j][3] + p1.y) * inv1);
        }
    }
}

// ---------------------------------------------------------------------------
// Host: exact port of np.random.default_rng(0).choice(2048, 32, replace=False)
// ---------------------------------------------------------------------------
static void compute_global_mask(GMask* gm, GIdx* gidx)
{
    const uint32_t INIT_A = 0x43b0d7e5u, MULT_A = 0x931e8875u;
    const uint32_t INIT_B = 0x8b51f9ddu, MULT_B = 0x58f38dedu;
    const uint32_t MIX_L  = 0xca01f9ddu, MIX_R  = 0x4973f715u;

    uint32_t hc = INIT_A;
    auto hashf = [&](uint32_t v) -> uint32_t {
        v ^= hc; hc *= MULT_A; v *= hc; v ^= v >> 16; return v;
    };
    auto mixf = [&](uint32_t x, uint32_t y) -> uint32_t {
        uint32_t r = MIX_L * x - MIX_R * y;
        r ^= r >> 16; return r;
    };

    uint32_t pool[4];
    for (int i = 0; i < 4; i++) pool[i] = hashf(0u);
    for (int s = 0; s < 4; s++)
        for (int d = 0; d < 4; d++)
            if (s != d)
                pool[d] = mixf(pool[d], hashf(pool[s]));

    uint32_t gw[8]; uint32_t hb = INIT_B;
    for (int i = 0; i < 8; i++) {
        uint32_t dv = pool[i & 3];
        dv ^= hb; hb *= MULT_B; dv *= hb; dv ^= dv >> 16;
        gw[i] = dv;
    }
    uint64_t v64[4];
    for (int k = 0; k < 4; k++)
        v64[k] = (uint64_t)gw[2 * k] | ((uint64_t)gw[2 * k + 1] << 32);

    typedef __uint128_t u128;
    const u128 MULT = ((u128)0x2360ed051fc65da4ULL << 64) | 0x4385df649fccf645ULL;
    u128 inc = ((((u128)v64[2] << 64) | v64[3]) << 1) | 1;
    u128 st  = 0;
    st = st * MULT + inc;
    st += ((u128)v64[0] << 64) | v64[1];
    st = st * MULT + inc;

    int have = 0; uint32_t cache = 0;
    auto n64 = [&]() -> uint64_t {
        st = st * MULT + inc;
        uint64_t hi = (uint64_t)(st >> 64), lo = (uint64_t)st;
        unsigned rot = (unsigned)(hi >> 58);
        uint64_t x = hi ^ lo;
        return rot ? ((x >> rot) | (x << (64 - rot))) : x;
    };
    auto n32 = [&]() -> uint32_t {
        if (have) { have = 0; return cache; }
        uint64_t u = n64();
        have = 1; cache = (uint32_t)(u >> 32);
        return (uint32_t)u;
    };

    bool chosen[NS] = {false};
    for (uint32_t j = NS - 32; j < NS; j++) {
        uint32_t rng_excl = j + 1;
        uint64_t m = (uint64_t)n32() * rng_excl;
        uint32_t leftover = (uint32_t)m;
        if (leftover < rng_excl) {
            uint32_t threshold = (0xFFFFFFFFu - j) % rng_excl;
            while (leftover < threshold) {
                m = (uint64_t)n32() * rng_excl;
                leftover = (uint32_t)m;
            }
        }
        uint32_t val = (uint32_t)(m >> 32);
        if (chosen[val]) val = j;
        chosen[val] = true;
    }

    for (int w = 0; w < NS / 32; w++) gm->w[w] = 0u;
    int n = 0;
    for (int i = 0; i < NS; i++)
        if (chosen[i]) {
            gm->w[i >> 5] |= (1u << (i & 31));
            gidx->idx[n++] = i;
        }
}

extern "C" void kernel_launch(void* const* d_in, const int* in_sizes, int n_in,
                              void* d_out, int out_size)
{
    (void)in_sizes; (void)n_in; (void)out_size;
    GMask gm; GIdx gi;
    compute_global_mask(&gm, &gi);

    conv_w_kernel<<<dim3(16, 3), 256>>>(
        (const float*)d_in[3], (const float*)d_in[5], (const float*)d_in[7]);

    cudaFuncSetAttribute(proj_mma_kernel, cudaFuncAttributeMaxDynamicSharedMemorySize, PROJ_SMEM);
    proj_mma_kernel<<<dim3(NB * NS / 128, 3), 512, PROJ_SMEM>>>(
        (const float*)d_in[0], (const float*)d_in[1], (const float*)d_in[2],
        (const float*)d_in[4], (const float*)d_in[6], (const float*)d_in[8], gm);

    setup_inv_kernel<<<NS / 256, 256>>>(gm);
    gather_tail_kernel<<<NB, 256>>>(gi);

    cudaFuncSetAttribute(attn_mma_kernel, cudaFuncAttributeMaxDynamicSharedMemorySize, ATTN_SMEM);
    attn_mma_kernel<<<dim3(16, NB), 512, ATTN_SMEM>>>((float*)d_out, gm, gi);
}

// round 16
// speedup vs baseline: 2.7661x; 1.0619x over previous
#include <cuda_runtime.h>
#include <cuda_bf16.h>
#include <cstdint>

#define NB   8
#define NS   2048
#define NDIN 1024
#define ND   128

// bf16 hi/lo pre-swizzled 64-row tiles: [QH,QL,KH,KL,VH,VL][b][tile][16KB] = 24 MB
// Q tiles (indices 0,1) are in PERMUTED row order; K/V natural.
__device__ uint4 g_bf[6][NB][32][1024];
// inverse permutation: permuted row -> original row
__device__ int g_inv[NS];
// pre-converted W operand tiles: [proj][kc][hi|lo contiguous 32KB]
__device__ uint4 g_wt[3][16][2][1024];

struct GMask { unsigned int w[NS / 32]; };   // 2048-bit global-token mask
struct GIdx  { int idx[32]; };               // sorted global token indices

// ===========================================================================
// Warp-MMA helpers (mma.sync / ldmatrix / cp.async — baseline PTX)
// ===========================================================================
__device__ __forceinline__ uint32_t smem_to_u32(const void* smem_ptr) {
    uint32_t addr;
    asm("{ .reg .u64 tmp; cvta.to.shared.u64 tmp, %1; cvt.u32.u64 %0, tmp; }"
        : "=r"(addr) : "l"(smem_ptr));
    return addr;
}

__device__ __forceinline__ uint32_t packbf(float lo, float hi) {
    uint32_t r;
    asm("cvt.rn.bf16x2.f32 %0, %1, %2;" : "=r"(r) : "f"(hi), "f"(lo));
    return r;
}

__device__ __forceinline__ uint32_t prmt_hi(uint32_t a, uint32_t b) {
    uint32_t d;
    asm("prmt.b32 %0, %1, %2, 0x7632;" : "=r"(d) : "r"(a), "r"(b));
    return d;
}
__device__ __forceinline__ float trunc_lo(float x, uint32_t xb) {
    return x - __uint_as_float(xb & 0xFFFF0000u);
}

#define LDSM_X4(r, addr) \
    asm volatile("ldmatrix.sync.aligned.m8n8.x4.shared.b16 {%0,%1,%2,%3}, [%4];" \
        : "=r"((r)[0]), "=r"((r)[1]), "=r"((r)[2]), "=r"((r)[3]) : "r"(addr))

#define LDSM_X4_T(r, addr) \
    asm volatile("ldmatrix.sync.aligned.m8n8.x4.trans.shared.b16 {%0,%1,%2,%3}, [%4];" \
        : "=r"((r)[0]), "=r"((r)[1]), "=r"((r)[2]), "=r"((r)[3]) : "r"(addr))

#define MMA16816(d, a, b0, b1) \
    asm("mma.sync.aligned.m16n8k16.row.col.f32.bf16.bf16.f32 " \
        "{%0,%1,%2,%3}, {%4,%5,%6,%7}, {%8,%9}, {%0,%1,%2,%3};" \
        : "+f"((d)[0]), "+f"((d)[1]), "+f"((d)[2]), "+f"((d)[3]) \
        : "r"((a)[0]), "r"((a)[1]), "r"((a)[2]), "r"((a)[3]), "r"(b0), "r"(b1))

#define CP_ASYNC16(dst_u32, src_ptr) \
    asm volatile("cp.async.cg.shared.global [%0], [%1], 16;" \
        :: "r"(dst_u32), "l"(src_ptr) : "memory")
#define CP_COMMIT()  asm volatile("cp.async.commit_group;" ::: "memory")
#define CP_WAIT0()   asm volatile("cp.async.wait_group 0;" ::: "memory")
#define CP_WAIT1()   asm volatile("cp.async.wait_group 1;" ::: "memory")

__device__ __forceinline__ uint32_t swaddr(uint32_t base, int row, int chunk) {
    return base + row * 256 + ((chunk ^ (row & 7)) << 4);
}

__device__ __forceinline__ bool gbit(const GMask& gm, int i) {
    return (gm.w[i >> 5] >> (i & 31)) & 1u;
}

// permuted index of original row r: non-globals keep order, globals -> 2016+rank
__device__ __forceinline__ int newidx(const GMask& gm, int r) {
    int cnt = 0;
    const int wr = r >> 5;
    for (int w = 0; w < wr; w++) cnt += __popc(gm.w[w]);
    cnt += __popc(gm.w[wr] & ((1u << (r & 31)) - 1u));
    return gbit(gm, r) ? (NS - 32) + cnt : r - cnt;
}

__device__ __forceinline__ void repack_frag(const float* c0, const float* c1,
                                            uint32_t* pah, uint32_t* pal) {
    uint32_t a0 = __float_as_uint(c0[0]), a1 = __float_as_uint(c0[1]);
    uint32_t a2 = __float_as_uint(c0[2]), a3 = __float_as_uint(c0[3]);
    uint32_t b0 = __float_as_uint(c1[0]), b1 = __float_as_uint(c1[1]);
    uint32_t b2 = __float_as_uint(c1[2]), b3 = __float_as_uint(c1[3]);
    pah[0] = prmt_hi(a0, a1);
    pah[1] = prmt_hi(a2, a3);
    pah[2] = prmt_hi(b0, b1);
    pah[3] = prmt_hi(b2, b3);
    pal[0] = packbf(trunc_lo(c0[0], a0), trunc_lo(c0[1], a1));
    pal[1] = packbf(trunc_lo(c0[2], a2), trunc_lo(c0[3], a3));
    pal[2] = packbf(trunc_lo(c1[0], b0), trunc_lo(c1[1], b1));
    pal[3] = packbf(trunc_lo(c1[2], b2), trunc_lo(c1[3], b3));
}

// ===========================================================================
// Setup kernels
// ===========================================================================
__global__ void setup_inv_kernel(GMask gm)
{
    const int r = blockIdx.x * 256 + threadIdx.x;
    if (r < NS) g_inv[newidx(gm, r)] = r;
}

// Pre-convert W (3 x [128,1024] fp32) into chunk operand tiles (hi/lo, swizzled).
__global__ void conv_w_kernel(const float* __restrict__ Wq,
                              const float* __restrict__ Wk,
                              const float* __restrict__ Wv)
{
    const int kc = blockIdx.x, proj = blockIdx.y, tid = threadIdx.x;
    const float* W = (proj == 0) ? Wq : (proj == 1) ? Wk : Wv;
    unsigned char* dH = (unsigned char*)g_wt[proj][kc][0];
    unsigned char* dL = (unsigned char*)g_wt[proj][kc][1];
    #pragma unroll
    for (int i = 0; i < 8; i++) {
        const int p4  = tid + i * 256;
        const int p   = p4 * 4;
        const int row = p >> 6, col = p & 63;
        const int ch8 = col >> 3, sub = (col >> 2) & 1;
        float4 wv = *(const float4*)(W + (size_t)row * NDIN + kc * 64 + col);
        uint32_t b0 = __float_as_uint(wv.x), b1 = __float_as_uint(wv.y);
        uint32_t b2 = __float_as_uint(wv.z), b3 = __float_as_uint(wv.w);
        uint2 H, L;
        H.x = prmt_hi(b0, b1); H.y = prmt_hi(b2, b3);
        L.x = packbf(trunc_lo(wv.x, b0), trunc_lo(wv.y, b1));
        L.y = packbf(trunc_lo(wv.z, b2), trunc_lo(wv.w, b3));
        const uint32_t off = (uint32_t)(row * 128 + ((ch8 ^ (row & 7)) << 4) + sub * 8);
        *(uint2*)(dH + off) = H;
        *(uint2*)(dL + off) = L;
    }
}

// ===========================================================================
// Projection GEMM: 512 threads, 16 warps (unchanged from R14).
// ===========================================================================
#define PROJ_SMEM 131072

__global__ __launch_bounds__(512)
void proj_mma_kernel(const float* __restrict__ xq, const float* __restrict__ xk, const float* __restrict__ xv,
                     const float* __restrict__ bq, const float* __restrict__ bk, const float* __restrict__ bv,
                     GMask gm)
{
    extern __shared__ char psm[];
    const uint32_t sb  = smem_to_u32(psm);
    const uint32_t sXH = sb;
    const uint32_t sXL = sb + 16384;
    const uint32_t sWb = sb + 32768;     // two 32KB W operand buffers
    const uint32_t sXF = sb + 98304;     // fp32 X stage, 32KB

    const int proj = blockIdx.y;
    const float* X    = (proj == 0) ? xq : (proj == 1) ? xk : xv;
    const float* bias = (proj == 0) ? bq : (proj == 1) ? bk : bv;

    const int tid  = threadIdx.x;
    const int w    = tid >> 5;
    const int wm   = w & 7;
    const int ng   = w >> 3;
    const int lane = tid & 31;
    const int g    = lane >> 2;
    const int tg   = lane & 3;
    const int g4   = lane >> 3;
    const int lr   = lane & 7;
    const int m0   = wm * 16;
    const int co   = ng * 64;
    const int mb   = blockIdx.x * 128;

    auto prefetch = [&](int kc) {
        const int k0 = kc * 64;
        const uint32_t wdst = sWb + (uint32_t)(kc & 1) * 32768u;
        const uint4* wsrc = g_wt[proj][kc][0];
        #pragma unroll
        for (int k = 0; k < 4; k++) {
            const int p4  = tid + k * 512;
            const int p   = p4 * 4;
            const int row = p >> 6, col = p & 63;
            CP_ASYNC16(sXF + (uint32_t)(p4 * 16), X + (size_t)(mb + row) * NDIN + k0 + col);
            CP_ASYNC16(wdst + (uint32_t)(p4 * 16), wsrc + p4);
        }
        CP_COMMIT();
    };

    auto convert = [&]() {
        #pragma unroll
        for (int i = 0; i < 4; i++) {
            const int p4  = tid + i * 512;
            const int p   = p4 * 4;
            const int row = p >> 6, col = p & 63;
            const int ch8 = col >> 3, sub = (col >> 2) & 1;
            const uint32_t soff = (uint32_t)(p4 * 16);
            const uint32_t doff = (uint32_t)(row * 128 + ((ch8 ^ (row & 7)) << 4) + sub * 8);

            float4 xv = *(const float4*)(psm + 98304 + soff);
            uint32_t xb0 = __float_as_uint(xv.x), xb1 = __float_as_uint(xv.y);
            uint32_t xb2 = __float_as_uint(xv.z), xb3 = __float_as_uint(xv.w);
            uint2 H, L;
            H.x = prmt_hi(xb0, xb1); H.y = prmt_hi(xb2, xb3);
            L.x = packbf(trunc_lo(xv.x, xb0), trunc_lo(xv.y, xb1));
            L.y = packbf(trunc_lo(xv.z, xb2), trunc_lo(xv.w, xb3));
            *(uint2*)(psm + (sXH - sb) + doff) = H;
            *(uint2*)(psm + (sXL - sb) + doff) = L;
        }
    };

    float acc[8][4];
    #pragma unroll
    for (int j = 0; j < 8; j++)
        #pragma unroll
        for (int e = 0; e < 4; e++) acc[j][e] = 0.0f;

    prefetch(0);
    CP_WAIT0();
    __syncthreads();
    convert();
    __syncthreads();

    for (int kc = 0; kc < NDIN / 64; kc++) {
        if (kc + 1 < NDIN / 64) prefetch(kc + 1);

        const uint32_t sWH = sWb + (uint32_t)(kc & 1) * 32768u;
        const uint32_t sWL = sWH + 16384;

        #pragma unroll
        for (int ks = 0; ks < 4; ks++) {
            uint32_t ah[4], al[4];
            const int arow = m0 + ((g4 & 1) << 3) + lr;
            const int ach  = 2 * ks + (g4 >> 1);
            LDSM_X4(ah, sXH + (uint32_t)(arow * 128 + ((ach ^ (arow & 7)) << 4)));
            LDSM_X4(al, sXL + (uint32_t)(arow * 128 + ((ach ^ (arow & 7)) << 4)));
            #pragma unroll
            for (int jp = 0; jp < 4; jp++) {
                uint32_t bh[4], bl[4];
                const int brow = co + 8 * (2 * jp + (g4 >> 1)) + lr;
                const int bch  = 2 * ks + (g4 & 1);
                LDSM_X4(bh, sWH + (uint32_t)(brow * 128 + ((bch ^ (brow & 7)) << 4)));
                LDSM_X4(bl, sWL + (uint32_t)(brow * 128 + ((bch ^ (brow & 7)) << 4)));
                MMA16816(acc[2 * jp],     ah, bh[0], bh[1]);
                MMA16816(acc[2 * jp + 1], ah, bh[2], bh[3]);
                MMA16816(acc[2 * jp],     al, bh[0], bh[1]);
                MMA16816(acc[2 * jp + 1], al, bh[2], bh[3]);
                MMA16816(acc[2 * jp],     ah, bl[0], bl[1]);
                MMA16816(acc[2 * jp + 1], ah, bl[2], bl[3]);
            }
        }

        if (kc + 1 < NDIN / 64) {
            CP_WAIT0();
            __syncthreads();
            convert();
            __syncthreads();
        }
    }

    // ---- epilogue: + bias -> bf16 hi/lo swizzled tiles (Q permuted) ----
    const int r0  = mb + m0 + g;
    const int bb_ = mb / NS;
    const int s0  = r0 % NS;
    int p0 = s0, p1 = s0 + 8;
    if (proj == 0) { p0 = newidx(gm, s0); p1 = newidx(gm, s0 + 8); }
    const int t0 = p0 >> 6, rin0 = p0 & 63;
    const int t1 = p1 >> 6, rin1 = p1 & 63;

    unsigned char* pH0 = (unsigned char*)g_bf[2 * proj][bb_][t0];
    unsigned char* pL0 = (unsigned char*)g_bf[2 * proj + 1][bb_][t0];
    unsigned char* pH1 = (unsigned char*)g_bf[2 * proj][bb_][t1];
    unsigned char* pL1 = (unsigned char*)g_bf[2 * proj + 1][bb_][t1];

    #pragma unroll
    for (int j = 0; j < 8; j++) {
        const int c   = co + 8 * j + 2 * tg;
        const int chk = (c >> 3);
        const float b0 = bias[c], b1 = bias[c + 1];
        const float x00 = acc[j][0] + b0, x01 = acc[j][1] + b1;
        const float x10 = acc[j][2] + b0, x11 = acc[j][3] + b1;

        uint32_t u00 = __float_as_uint(x00), u01 = __float_as_uint(x01);
        uint32_t off0 = (uint32_t)(rin0 * 256 + ((chk ^ (rin0 & 7)) << 4) + tg * 4);
        *(uint32_t*)(pH0 + off0) = prmt_hi(u00, u01);
        *(uint32_t*)(pL0 + off0) = packbf(trunc_lo(x00, u00), trunc_lo(x01, u01));

        uint32_t u10 = __float_as_uint(x10), u11 = __float_as_uint(x11);
        uint32_t off1 = (uint32_t)(rin1 * 256 + ((chk ^ (rin1 & 7)) << 4) + tg * 4);
        *(uint32_t*)(pH1 + off1) = prmt_hi(u10, u11);
        *(uint32_t*)(pL1 + off1) = packbf(trunc_lo(x10, u10), trunc_lo(x11, u11));
    }
}

// ===========================================================================
// Flash attention with causal tile skipping on permuted rows.
// Tail K/V rows gathered DIRECTLY via scattered cp.async (no gather kernel);
// tail buffer rows 32-63 left stale — masking zeroes their contribution.
// ===========================================================================
#define ATTN_SMEM 196608

__global__ __launch_bounds__(512)
void attn_mma_kernel(float* __restrict__ out, GMask gm, GIdx gi)
{
    extern __shared__ char smem[];
    const uint32_t sb  = smem_to_u32(smem);
    const uint32_t sQH = sb;
    const uint32_t sQL = sb + 32768;

    const int tid  = threadIdx.x;
    const int w    = tid >> 5;
    const int sub  = w >> 3;
    const int wm   = (w >> 1) & 3;
    const int ng   = w & 1;
    const int lane = tid & 31;
    const int g    = lane >> 2;
    const int tg   = lane & 3;
    const int g4   = lane >> 3;
    const int lr   = lane & 7;
    const int b    = blockIdx.y;
    const int bx   = blockIdx.x;
    const int hj   = 31 - bx;
    const int lj   = bx;
    const int myj  = sub ? lj : hj;
    const int L0   = (hj + 2 < 32) ? hj + 2 : 32;
    const int L1   = lj + 2;
    const int Lcta = L0;
    const int N    = Lcta + 1;
    const int myL  = sub ? L1 : L0;

    const int srow  = sub * 64 + wm * 16;
    const int pbase = myj * 64 + wm * 16;
    const int co    = ng * 32;

    #pragma unroll
    for (int seg = 0; seg < 4; seg++) {
        const uint4* src = g_bf[seg >> 1][b][(seg & 1) ? lj : hj];
        const uint32_t d0 = sb + (uint32_t)seg * 16384 + (uint32_t)tid * 16;
        #pragma unroll
        for (int k = 0; k < 2; k++)
            CP_ASYNC16(d0 + (uint32_t)k * 8192, src + tid + k * 512);
    }
    CP_COMMIT();

    auto kv_prefetch = [&](int i) {
        const uint32_t bufb = sb + 65536u + (uint32_t)(i & 1) * 65536u;
        if (i < Lcta) {
            #pragma unroll
            for (int seg = 0; seg < 4; seg++) {
                const uint4* src = g_bf[2 + seg][b][i];
                const uint32_t d0 = bufb + (uint32_t)seg * 16384 + (uint32_t)tid * 16;
                #pragma unroll
                for (int k = 0; k < 2; k++)
                    CP_ASYNC16(d0 + (uint32_t)k * 8192, src + tid + k * 512);
            }
        } else {
            // tail: scatter-gather the 32 global rows; rows 32-63 stay stale
            const int row = tid >> 4, ch = tid & 15;
            const int tok = gi.idx[row];
            const int tn  = tok >> 6, rr = tok & 63;
            const uint32_t dsw = (uint32_t)(row * 256 + ((ch ^ (row & 7)) << 4));
            const int soff = rr * 16 + (ch ^ (rr & 7));
            #pragma unroll
            for (int seg = 0; seg < 4; seg++)
                CP_ASYNC16(bufb + (uint32_t)seg * 16384 + dsw,
                           g_bf[2 + seg][b][tn] + soff);
        }
        CP_COMMIT();
    };
    kv_prefetch(0);

    const int r0a = g_inv[pbase + g];
    const int r1a = g_inv[pbase + g + 8];
    const bool rg0 = gbit(gm, r0a);
    const bool rg1 = gbit(gm, r1a);
    const float inv_scale = 0.08838834764831844f;   // 1/sqrt(128)

    float l0 = 0.0f, l1 = 0.0f;
    float O[16][4];
    #pragma unroll
    for (int j = 0; j < 16; j++)
        #pragma unroll
        for (int e = 0; e < 4; e++) O[j][e] = 0.0f;

    for (int i = 0; i < N; i++) {
        if (i + 1 < N) {
            kv_prefetch(i + 1);
            CP_WAIT1();
        } else {
            CP_WAIT0();
        }
        __syncthreads();

        const bool is_tail = (i == Lcta);
        const bool active  = (i < myL) || (is_tail && ng == 0);

        if (active) {
            const uint32_t bufb = sb + 65536u + (uint32_t)(i & 1) * 65536u;
            const uint32_t sKH = bufb;
            const uint32_t sKL = bufb + 16384;
            const uint32_t sVH = bufb + 32768;
            const uint32_t sVL = bufb + 49152;

            float S[4][4];
            #pragma unroll
            for (int j = 0; j < 4; j++)
                #pragma unroll
                for (int e = 0; e < 4; e++) S[j][e] = 0.0f;

            #pragma unroll
            for (int ks = 0; ks < 8; ks++) {
                uint32_t ah[4], al[4];
                const int arow = srow + ((g4 & 1) << 3) + lr;
                const int ach  = 2 * ks + (g4 >> 1);
                LDSM_X4(ah, swaddr(sQH, arow, ach));
                LDSM_X4(al, swaddr(sQL, arow, ach));
                #pragma unroll
                for (int jp = 0; jp < 2; jp++) {
                    uint32_t bh[4], bl[4];
                    const int brow = co + 8 * (2 * jp + (g4 >> 1)) + lr;
                    const int bch  = 2 * ks + (g4 & 1);
                    LDSM_X4(bh, swaddr(sKH, brow, bch));
                    LDSM_X4(bl, swaddr(sKL, brow, bch));
                    MMA16816(S[2 * jp],     ah, bh[0], bh[1]);
                    MMA16816(S[2 * jp + 1], ah, bh[2], bh[3]);
                    MMA16816(S[2 * jp],     al, bh[0], bh[1]);
                    MMA16816(S[2 * jp + 1], al, bh[2], bh[3]);
                    MMA16816(S[2 * jp],     ah, bl[0], bl[1]);
                    MMA16816(S[2 * jp + 1], ah, bl[2], bl[3]);
                }
            }

            if (is_tail) {
                const int bound = 64 * myL;
                #pragma unroll
                for (int j = 0; j < 4; j++) {
                    const int c0i = co + 8 * j + 2 * tg;
                    const int o0 = (c0i     < 32) ? gi.idx[c0i]     : -1;
                    const int o1 = (c0i + 1 < 32) ? gi.idx[c0i + 1] : -1;
                    const bool a0 = (o0 >= bound);
                    const bool a1 = (o1 >= bound);
                    S[j][0] = a0 ? __expf(S[j][0] * inv_scale) : 0.0f;
                    S[j][1] = a1 ? __expf(S[j][1] * inv_scale) : 0.0f;
                    S[j][2] = a0 ? __expf(S[j][2] * inv_scale) : 0.0f;
                    S[j][3] = a1 ? __expf(S[j][3] * inv_scale) : 0.0f;
                    l0 += S[j][0] + S[j][1];
                    l1 += S[j][2] + S[j][3];
                }
            } else if (i * 64 + 63 <= pbase) {
                #pragma unroll
                for (int j = 0; j < 4; j++) {
                    S[j][0] = __expf(S[j][0] * inv_scale);
                    S[j][1] = __expf(S[j][1] * inv_scale);
                    S[j][2] = __expf(S[j][2] * inv_scale);
                    S[j][3] = __expf(S[j][3] * inv_scale);
                    l0 += S[j][0] + S[j][1];
                    l1 += S[j][2] + S[j][3];
                }
            } else {
                const int k0 = i * 64;
                #pragma unroll
                for (int j = 0; j < 4; j++) {
                    const int cb = k0 + co + 8 * j + 2 * tg;
                    const bool cg0 = gbit(gm, cb);
                    const bool cg1 = gbit(gm, cb + 1);
                    S[j][0] = (cg0 | rg0 | (cb     <= r0a)) ? __expf(S[j][0] * inv_scale) : 0.0f;
                    S[j][1] = (cg1 | rg0 | (cb + 1 <= r0a)) ? __expf(S[j][1] * inv_scale) : 0.0f;
                    S[j][2] = (cg0 | rg1 | (cb     <= r1a)) ? __expf(S[j][2] * inv_scale) : 0.0f;
                    S[j][3] = (cg1 | rg1 | (cb + 1 <= r1a)) ? __expf(S[j][3] * inv_scale) : 0.0f;
                    l0 += S[j][0] + S[j][1];
                    l1 += S[j][2] + S[j][3];
                }
            }

            #pragma unroll
            for (int ks = 0; ks < 2; ks++) {
                uint32_t pah[4], pal[4];
                repack_frag(S[2 * ks], S[2 * ks + 1], pah, pal);
                #pragma unroll
                for (int jp = 0; jp < 8; jp++) {
                    uint32_t bh[4], bl[4];
                    const int brow = co + 16 * ks + ((g4 & 1) << 3) + lr;
                    const int bch  = 2 * jp + (g4 >> 1);
                    LDSM_X4_T(bh, swaddr(sVH, brow, bch));
                    LDSM_X4_T(bl, swaddr(sVL, brow, bch));
                    MMA16816(O[2 * jp],     pah, bh[0], bh[1]);
                    MMA16816(O[2 * jp + 1], pah, bh[2], bh[3]);
                    MMA16816(O[2 * jp],     pal, bh[0], bh[1]);
                    MMA16816(O[2 * jp + 1], pal, bh[2], bh[3]);
                    MMA16816(O[2 * jp],     pah, bl[0], bl[1]);
                    MMA16816(O[2 * jp + 1], pah, bl[2], bl[3]);
                }
            }
        }
        __syncthreads();
    }

    l0 += __shfl_xor_sync(0xffffffffu, l0, 1);
    l0 += __shfl_xor_sync(0xffffffffu, l0, 2);
    l1 += __shfl_xor_sync(0xffffffffu, l1, 1);
    l1 += __shfl_xor_sync(0xffffffffu, l1, 2);

    float* lsm = (float*)(smem + 131072);
    const int reg = sub * 4 + wm;
    if (ng == 1) {
        float* ob = (float*)(smem + reg * 8192);
        #pragma unroll
        for (int j = 0; j < 16; j++) {
            const int c = 8 * j + 2 * tg;
            *(float2*)(ob + g * 128 + c)       = make_float2(O[j][0], O[j][1]);
            *(float2*)(ob + (g + 8) * 128 + c) = make_float2(O[j][2], O[j][3]);
        }
        lsm[reg * 16 + g]     = l0;
        lsm[reg * 16 + g + 8] = l1;
    }
    __syncthreads();
    if (ng == 0) {
        const float* ob = (const float*)(smem + reg * 8192);
        l0 += lsm[reg * 16 + g];
        l1 += lsm[reg * 16 + g + 8];
        const float inv0 = 1.0f / l0;
        const float inv1 = 1.0f / l1;
        float* o0 = out + ((size_t)b * NS + r0a) * ND;
        float* o1 = out + ((size_t)b * NS + r1a) * ND;
        #pragma unroll
        for (int j = 0; j < 16; j++) {
            const int c = 8 * j + 2 * tg;
            float2 p0 = *(const float2*)(ob + g * 128 + c);
            float2 p1 = *(const float2*)(ob + (g + 8) * 128 + c);
            *(float2*)(o0 + c) = make_float2((O[j][0] + p0.x) * inv0, (O[j][1] + p0.y) * inv0);
            *(float2*)(o1 + c) = make_float2((O[j][2] + p1.x) * inv1, (O[j][3] + p1.y) * inv1);
        }
    }
}

// ---------------------------------------------------------------------------
// Host: exact port of np.random.default_rng(0).choice(2048, 32, replace=False)
// ---------------------------------------------------------------------------
static void compute_global_mask(GMask* gm, GIdx* gidx)
{
    const uint32_t INIT_A = 0x43b0d7e5u, MULT_A = 0x931e8875u;
    const uint32_t INIT_B = 0x8b51f9ddu, MULT_B = 0x58f38dedu;
    const uint32_t MIX_L  = 0xca01f9ddu, MIX_R  = 0x4973f715u;

    uint32_t hc = INIT_A;
    auto hashf = [&](uint32_t v) -> uint32_t {
        v ^= hc; hc *= MULT_A; v *= hc; v ^= v >> 16; return v;
    };
    auto mixf = [&](uint32_t x, uint32_t y) -> uint32_t {
        uint32_t r = MIX_L * x - MIX_R * y;
        r ^= r >> 16; return r;
    };

    uint32_t pool[4];
    for (int i = 0; i < 4; i++) pool[i] = hashf(0u);
    for (int s = 0; s < 4; s++)
        for (int d = 0; d < 4; d++)
            if (s != d)
                pool[d] = mixf(pool[d], hashf(pool[s]));

    uint32_t gw[8]; uint32_t hb = INIT_B;
    for (int i = 0; i < 8; i++) {
        uint32_t dv = pool[i & 3];
        dv ^= hb; hb *= MULT_B; dv *= hb; dv ^= dv >> 16;
        gw[i] = dv;
    }
    uint64_t v64[4];
    for (int k = 0; k < 4; k++)
        v64[k] = (uint64_t)gw[2 * k] | ((uint64_t)gw[2 * k + 1] << 32);

    typedef __uint128_t u128;
    const u128 MULT = ((u128)0x2360ed051fc65da4ULL << 64) | 0x4385df649fccf645ULL;
    u128 inc = ((((u128)v64[2] << 64) | v64[3]) << 1) | 1;
    u128 st  = 0;
    st = st * MULT + inc;
    st += ((u128)v64[0] << 64) | v64[1];
    st = st * MULT + inc;

    int have = 0; uint32_t cache = 0;
    auto n64 = [&]() -> uint64_t {
        st = st * MULT + inc;
        uint64_t hi = (uint64_t)(st >> 64), lo = (uint64_t)st;
        unsigned rot = (unsigned)(hi >> 58);
        uint64_t x = hi ^ lo;
        return rot ? ((x >> rot) | (x << (64 - rot))) : x;
    };
    auto n32 = [&]() -> uint32_t {
        if (have) { have = 0; return cache; }
        uint64_t u = n64();
        have = 1; cache = (uint32_t)(u >> 32);
        return (uint32_t)u;
    };

    bool chosen[NS] = {false};
    for (uint32_t j = NS - 32; j < NS; j++) {
        uint32_t rng_excl = j + 1;
        uint64_t m = (uint64_t)n32() * rng_excl;
        uint32_t leftover = (uint32_t)m;
        if (leftover < rng_excl) {
            uint32_t threshold = (0xFFFFFFFFu - j) % rng_excl;
            while (leftover < threshold) {
                m = (uint64_t)n32() * rng_excl;
                leftover = (uint32_t)m;
            }
        }
        uint32_t val = (uint32_t)(m >> 32);
        if (chosen[val]) val = j;
        chosen[val] = true;
    }

    for (int w = 0; w < NS / 32; w++) gm->w[w] = 0u;
    int n = 0;
    for (int i = 0; i < NS; i++)
        if (chosen[i]) {
            gm->w[i >> 5] |= (1u << (i & 31));
            gidx->idx[n++] = i;
        }
}

extern "C" void kernel_launch(void* const* d_in, const int* in_sizes, int n_in,
                              void* d_out, int out_size)
{
    (void)in_sizes; (void)n_in; (void)out_size;
    GMask gm; GIdx gi;
    compute_global_mask(&gm, &gi);

    setup_inv_kernel<<<NS / 256, 256>>>(gm);
    conv_w_kernel<<<dim3(16, 3), 256>>>(
        (const float*)d_in[3], (const float*)d_in[5], (const float*)d_in[7]);

    cudaFuncSetAttribute(proj_mma_kernel, cudaFuncAttributeMaxDynamicSharedMemorySize, PROJ_SMEM);
    proj_mma_kernel<<<dim3(NB * NS / 128, 3), 512, PROJ_SMEM>>>(
        (const float*)d_in[0], (const float*)d_in[1], (const float*)d_in[2],
        (const float*)d_in[4], (const float*)d_in[6], (const float*)d_in[8], gm);

    cudaFuncSetAttribute(attn_mma_kernel, cudaFuncAttributeMaxDynamicSharedMemorySize, ATTN_SMEM);
    attn_mma_kernel<<<dim3(16, NB), 512, ATTN_SMEM>>>((float*)d_out, gm, gi);
}